// round 10
// baseline (speedup 1.0000x reference)
#include <cuda_runtime.h>
#include <cuda_bf16.h>

// ---------------- problem constants ----------------
#define BB    64
#define LL    256
#define EE    512
#define DD    512
#define MROWS (BB * LL)        // 16384
#define CATW  2048             // [x(512) | ctx(512) | attended(1024)]

// ---------------- scratch (static device globals; no allocations) ----------
__device__ float g_cmp_p[MROWS * CATW];      // prem  [x|ctx|att_hypo]
__device__ float g_cmp_h[MROWS * CATW];      // hypo  [x|ctx|att_prem]
__device__ float g_hid  [MROWS * DD];
__device__ float g_pq   [MROWS * DD];
__device__ float g_hk   [MROWS * DD];
__device__ float g_s1   [BB * LL * LL];      // scores / z / p2h
__device__ float g_s2   [BB * LL * LL];      // h2p
__device__ float g_agg  [BB * 2 * DD];       // [prem_cmp | hypo_cmp]
__device__ int   g_mask_p[MROWS];
__device__ int   g_mask_h[MROWS];

__device__ __forceinline__ float relu_(float x) { return x > 0.f ? x : 0.f; }

// =====================================================================
// SGEMM: C = act(op(A) @ op(B) + bias), 128x128x16 tiles, double buffered
//   A: [M,K] row-major (lda).  B: NN -> [K,N] (ldb); NT -> [N,K] (ldb).
//   grid = (N/128, M/128, batch). Dims must be multiples of 128 / 16.
//   __launch_bounds__(256, 2): 2 CTAs/SM (4 warps/SMSP) to cover LDS/sync
//   stalls — FMA pipe needs 2 back-to-back-issuing warps per SMSP.
// =====================================================================
template<bool NT, bool BIAS, bool RELU>
__global__ void __launch_bounds__(256, 2)
sgemm_k(const float* __restrict__ A, const float* __restrict__ B,
        const float* __restrict__ bias, float* __restrict__ C,
        int K, int lda, int ldb, int ldc,
        long long sA, long long sB, long long sC)
{
    __shared__ float As[2][16][132];
    __shared__ float Bs[2][16][132];

    const int tid = threadIdx.x;
    const int bm = blockIdx.y << 7;
    const int bn = blockIdx.x << 7;
    A += (long long)blockIdx.z * sA;
    B += (long long)blockIdx.z * sB;
    C += (long long)blockIdx.z * sC;

    // A tile loader mapping (also used for NT B): 64 rows x (4-float) cols
    const int lm = tid >> 2;            // 0..63
    const int lk = (tid & 3) << 2;      // 0,4,8,12

    const float* Ap0 = A + (long long)(bm + lm) * lda + lk;
    const float* Ap1 = Ap0 + (long long)64 * lda;

    const float* Bp0;
    const float* Bp1;
    int bkr = 0, bnc = 0;
    long long bstep = 16;               // pointer step per k-tile for B
    if (NT) {
        Bp0 = B + (long long)(bn + lm) * ldb + lk;
        Bp1 = Bp0 + (long long)64 * ldb;
    } else {
        bkr = tid >> 5;                 // 0..7
        bnc = (tid & 31) << 2;          // 0..124
        Bp0 = B + (long long)bkr * ldb + bn + bnc;
        Bp1 = Bp0 + (long long)8 * ldb;
        bstep = (long long)16 * ldb;
    }

    const int cr = (tid >> 4) << 3;     // 0..120
    const int cc = (tid & 15) << 3;     // 0..120

    float acc[8][8];
#pragma unroll
    for (int i = 0; i < 8; i++)
#pragma unroll
        for (int j = 0; j < 8; j++) acc[i][j] = 0.f;

    // ---- stage 0 load ----
    {
        float4 a0 = *(const float4*)Ap0;
        float4 a1 = *(const float4*)Ap1;
        As[0][lk + 0][lm] = a0.x; As[0][lk + 1][lm] = a0.y;
        As[0][lk + 2][lm] = a0.z; As[0][lk + 3][lm] = a0.w;
        As[0][lk + 0][lm + 64] = a1.x; As[0][lk + 1][lm + 64] = a1.y;
        As[0][lk + 2][lm + 64] = a1.z; As[0][lk + 3][lm + 64] = a1.w;
        if (NT) {
            float4 b0 = *(const float4*)Bp0;
            float4 b1 = *(const float4*)Bp1;
            Bs[0][lk + 0][lm] = b0.x; Bs[0][lk + 1][lm] = b0.y;
            Bs[0][lk + 2][lm] = b0.z; Bs[0][lk + 3][lm] = b0.w;
            Bs[0][lk + 0][lm + 64] = b1.x; Bs[0][lk + 1][lm + 64] = b1.y;
            Bs[0][lk + 2][lm + 64] = b1.z; Bs[0][lk + 3][lm + 64] = b1.w;
        } else {
            *(float4*)&Bs[0][bkr][bnc]     = *(const float4*)Bp0;
            *(float4*)&Bs[0][bkr + 8][bnc] = *(const float4*)Bp1;
        }
    }
    __syncthreads();

    const int KT = K >> 4;
    int buf = 0;
    for (int kt = 0; kt < KT; ++kt) {
        // advance source pointers (incremental — keeps address math cheap)
        Ap0 += 16; Ap1 += 16;
        Bp0 += bstep; Bp1 += bstep;

        float4 na0, na1, nb0, nb1;
        const bool has_next = (kt + 1 < KT);
        if (has_next) {
            na0 = *(const float4*)Ap0;
            na1 = *(const float4*)Ap1;
            nb0 = *(const float4*)Bp0;
            nb1 = *(const float4*)Bp1;
        }

#pragma unroll
        for (int kk = 0; kk < 16; ++kk) {
            float av[8], bv[8];
            *(float4*)&av[0] = *(const float4*)&As[buf][kk][cr];
            *(float4*)&av[4] = *(const float4*)&As[buf][kk][cr + 4];
            *(float4*)&bv[0] = *(const float4*)&Bs[buf][kk][cc];
            *(float4*)&bv[4] = *(const float4*)&Bs[buf][kk][cc + 4];
#pragma unroll
            for (int i = 0; i < 8; i++)
#pragma unroll
                for (int j = 0; j < 8; j++)
                    acc[i][j] = fmaf(av[i], bv[j], acc[i][j]);
        }

        if (has_next) {
            const int nb = buf ^ 1;
            As[nb][lk + 0][lm] = na0.x; As[nb][lk + 1][lm] = na0.y;
            As[nb][lk + 2][lm] = na0.z; As[nb][lk + 3][lm] = na0.w;
            As[nb][lk + 0][lm + 64] = na1.x; As[nb][lk + 1][lm + 64] = na1.y;
            As[nb][lk + 2][lm + 64] = na1.z; As[nb][lk + 3][lm + 64] = na1.w;
            if (NT) {
                Bs[nb][lk + 0][lm] = nb0.x; Bs[nb][lk + 1][lm] = nb0.y;
                Bs[nb][lk + 2][lm] = nb0.z; Bs[nb][lk + 3][lm] = nb0.w;
                Bs[nb][lk + 0][lm + 64] = nb1.x; Bs[nb][lk + 1][lm + 64] = nb1.y;
                Bs[nb][lk + 2][lm + 64] = nb1.z; Bs[nb][lk + 3][lm + 64] = nb1.w;
            } else {
                *(float4*)&Bs[nb][bkr][bnc]     = nb0;
                *(float4*)&Bs[nb][bkr + 8][bnc] = nb1;
            }
            __syncthreads();
            buf = nb;
        }
    }

    // ---- epilogue ----
    float bb[8];
    if (BIAS) {
#pragma unroll
        for (int j = 0; j < 8; j++) bb[j] = bias[bn + cc + j];
    }
#pragma unroll
    for (int i = 0; i < 8; i++) {
        float v[8];
#pragma unroll
        for (int j = 0; j < 8; j++) {
            float x = acc[i][j];
            if (BIAS) x += bb[j];
            if (RELU) x = relu_(x);
            v[j] = x;
        }
        float* cp = C + (long long)(bm + cr + i) * ldc + bn + cc;
        *(float4*)cp       = make_float4(v[0], v[1], v[2], v[3]);
        *(float4*)(cp + 4) = make_float4(v[4], v[5], v[6], v[7]);
    }
}

// =====================================================================
// embedding gather into the wide concat buffer (cols 0..511), + mask
// =====================================================================
__global__ void embed_k(const int* __restrict__ tok, const float* __restrict__ W,
                        float* __restrict__ out, int* __restrict__ mask)
{
    const int r = blockIdx.x;
    const int t = tok[r];
    if (threadIdx.x == 0) mask[r] = (t != 0);
    const float4* src = (const float4*)(W + (long long)t * EE);
    float4* dst = (float4*)(out + (long long)r * CATW);
    dst[threadIdx.x] = src[threadIdx.x];   // 128 threads x 16B = 512 floats
}

// ---------------- block reductions (blockDim = 256) ----------------
__device__ __forceinline__ float blockMax256(float v, float* red)
{
#pragma unroll
    for (int o = 16; o; o >>= 1) v = fmaxf(v, __shfl_xor_sync(0xffffffffu, v, o));
    if ((threadIdx.x & 31) == 0) red[threadIdx.x >> 5] = v;
    __syncthreads();
    float m = red[0];
#pragma unroll
    for (int i = 1; i < 8; i++) m = fmaxf(m, red[i]);
    return m;
}
__device__ __forceinline__ float blockSum256(float v, float* red)
{
#pragma unroll
    for (int o = 16; o; o >>= 1) v += __shfl_xor_sync(0xffffffffu, v, o);
    if ((threadIdx.x & 31) == 0) red[threadIdx.x >> 5] = v;
    __syncthreads();
    float s = red[0];
#pragma unroll
    for (int i = 1; i < 8; i++) s += red[i];
    return s;
}

// self-attention softmax (in place): rel bias, diag=-inf, padded key=-1e9
__global__ void softmax_self_k(float* __restrict__ S, const int* __restrict__ mask,
                               const float* __restrict__ distW)
{
    const int q = blockIdx.x, b = blockIdx.y, k = threadIdx.x;
    float* row = S + ((long long)(b * LL + q)) * LL;
    __shared__ float red[8];
    __shared__ float dw[23];
    if (k < 23) dw[k] = distW[k];
    const int valid = mask[b * LL + k];
    const float sc = row[k];
    __syncthreads();

    float v;
    if (!valid)      v = -1e9f;
    else if (k == q) v = __int_as_float(0xff800000);   // -inf
    else {
        int d = k - q; d = d < -11 ? -11 : (d > 11 ? 11 : d);
        v = sc + dw[d + 11];
    }
    const float m = blockMax256(v, red);
    __syncthreads();
    const float e = expf(v - m);
    const float s = blockSum256(e, red);
    row[k] = e / s;
}

// row softmax with key mask (in place)
__global__ void softmax_rows_k(float* __restrict__ Z, const int* __restrict__ mask)
{
    const int q = blockIdx.x, b = blockIdx.y, k = threadIdx.x;
    float* row = Z + ((long long)(b * LL + q)) * LL;
    __shared__ float red[8];
    const float v = mask[b * LL + k] ? row[k] : -1e9f;
    const float m = blockMax256(v, red);
    __syncthreads();
    const float e = expf(v - m);
    const float s = blockSum256(e, red);
    row[k] = e / s;
}

// column softmax: Out[b,h,p] = softmax_p( Z[b,p,h] masked by maskP[p] )
__global__ void softmax_cols_k(const float* __restrict__ Z, const int* __restrict__ maskP,
                               float* __restrict__ Out)
{
    const int h = blockIdx.x, b = blockIdx.y, p = threadIdx.x;
    __shared__ float red[8];
    const float v = maskP[b * LL + p]
                  ? Z[((long long)(b * LL + p)) * LL + h] : -1e9f;
    const float m = blockMax256(v, red);
    __syncthreads();
    const float e = expf(v - m);
    const float s = blockSum256(e, red);
    Out[((long long)(b * LL + h)) * LL + p] = e / s;
}

// masked sum over sequence: out[b*1024 + off + d] = sum_l mask * X[b,l,d]
__global__ void masked_sum_k(const float* __restrict__ X, const int* __restrict__ mask,
                             float* __restrict__ out, int off)
{
    const int b = blockIdx.y;
    const int d = blockIdx.x * 128 + threadIdx.x;
    const float* xb = X + (long long)b * LL * DD;
    const int* mb = mask + b * LL;
    float acc = 0.f;
    for (int l = 0; l < LL; l++)
        if (mb[l]) acc += xb[l * DD + d];
    out[b * (2 * DD) + off + d] = acc;
}

// aggregate MLP + output head (tiny): 64 blocks x 512 threads
__global__ void head_k(const float* __restrict__ aggin,
                       const float* __restrict__ Wg1, const float* __restrict__ bg1,
                       const float* __restrict__ Wg2, const float* __restrict__ bg2,
                       const float* __restrict__ Wo, float* __restrict__ out)
{
    __shared__ float sin[2 * DD];
    __shared__ float h1[DD];
    __shared__ float h2[DD];
    const int b = blockIdx.x, t = threadIdx.x;
    sin[t]       = aggin[b * 2 * DD + t];
    sin[t + DD]  = aggin[b * 2 * DD + DD + t];
    __syncthreads();
    float a = bg1[t];
    for (int k = 0; k < 2 * DD; k++) a = fmaf(sin[k], Wg1[k * DD + t], a);
    h1[t] = relu_(a);
    __syncthreads();
    a = bg2[t];
    for (int k = 0; k < DD; k++) a = fmaf(h1[k], Wg2[k * DD + t], a);
    h2[t] = relu_(a);
    __syncthreads();
    if (t < 3) {
        float s = 0.f;
        for (int k = 0; k < DD; k++) s = fmaf(h2[k], Wo[k * 3 + t], s);
        out[b * 3 + t] = s;
    }
}

// ---------------- host-side GEMM dispatch ----------------
enum GType { G_MLP, G_NN, G_NT };
static void gemm(GType t, const float* A, const float* B, const float* bias, float* C,
                 int M, int N, int K, int lda, int ldb, int ldc,
                 long long sA, long long sB, long long sC, int batch)
{
    dim3 grid(N >> 7, M >> 7, batch), blk(256);
    switch (t) {
    case G_MLP: sgemm_k<false, true,  true ><<<grid, blk>>>(A, B, bias, C, K, lda, ldb, ldc, sA, sB, sC); break;
    case G_NN:  sgemm_k<false, false, false><<<grid, blk>>>(A, B, bias, C, K, lda, ldb, ldc, sA, sB, sC); break;
    case G_NT:  sgemm_k<true,  false, false><<<grid, blk>>>(A, B, bias, C, K, lda, ldb, ldc, sA, sB, sC); break;
    }
}

extern "C" void kernel_launch(void* const* d_in, const int* in_sizes, int n_in,
                              void* d_out, int out_size)
{
    (void)in_sizes; (void)n_in; (void)out_size;
    const int*   prem  = (const int*)  d_in[0];
    const int*   hypo  = (const int*)  d_in[1];
    const float* embW  = (const float*)d_in[2];
    const float* distW = (const float*)d_in[3];
    const float* Ws1 = (const float*)d_in[4];  const float* bs1 = (const float*)d_in[5];
    const float* Ws2 = (const float*)d_in[6];  const float* bs2 = (const float*)d_in[7];
    const float* Wa1 = (const float*)d_in[8];  const float* ba1 = (const float*)d_in[9];
    const float* Wa2 = (const float*)d_in[10]; const float* ba2 = (const float*)d_in[11];
    const float* Wc1 = (const float*)d_in[12]; const float* bc1 = (const float*)d_in[13];
    const float* Wc2 = (const float*)d_in[14]; const float* bc2 = (const float*)d_in[15];
    const float* Wg1 = (const float*)d_in[16]; const float* bg1 = (const float*)d_in[17];
    const float* Wg2 = (const float*)d_in[18]; const float* bg2 = (const float*)d_in[19];
    const float* Wo  = (const float*)d_in[20];
    float* out = (float*)d_out;

    float *cmp_p, *cmp_h, *hid, *pq, *hk, *s1, *s2, *agg;
    int *mp, *mh;
    cudaGetSymbolAddress((void**)&cmp_p, g_cmp_p);
    cudaGetSymbolAddress((void**)&cmp_h, g_cmp_h);
    cudaGetSymbolAddress((void**)&hid,   g_hid);
    cudaGetSymbolAddress((void**)&pq,    g_pq);
    cudaGetSymbolAddress((void**)&hk,    g_hk);
    cudaGetSymbolAddress((void**)&s1,    g_s1);
    cudaGetSymbolAddress((void**)&s2,    g_s2);
    cudaGetSymbolAddress((void**)&agg,   g_agg);
    cudaGetSymbolAddress((void**)&mp,    g_mask_p);
    cudaGetSymbolAddress((void**)&mh,    g_mask_h);

    const long long SQ  = (long long)LL * DD;     // 256*512  per-batch Q stride
    const long long SS  = (long long)LL * LL;     // 256*256  per-batch score stride
    const long long SC  = (long long)LL * CATW;   // 256*2048 per-batch concat stride

    // embeddings -> concat[:, 0:512], masks
    embed_k<<<MROWS, 128>>>(prem, embW, cmp_p, mp);
    embed_k<<<MROWS, 128>>>(hypo, embW, cmp_h, mh);

    // ---- self branch: prem ----
    gemm(G_MLP, cmp_p, Ws1, bs1, hid, MROWS, DD, EE,   CATW, DD, DD, 0, 0, 0, 1);
    gemm(G_MLP, hid,   Ws2, bs2, pq,  MROWS, DD, DD,   DD,   DD, DD, 0, 0, 0, 1);
    gemm(G_NT,  pq, pq, nullptr, s1,  LL, LL, DD, DD, DD, LL, SQ, SQ, SS, BB);
    softmax_self_k<<<dim3(LL, BB), 256>>>(s1, mp, distW);
    gemm(G_NN,  s1, cmp_p, nullptr, cmp_p + EE, LL, EE, LL, LL, CATW, CATW, SS, SC, SC, BB);

    // ---- self branch: hypo ----
    gemm(G_MLP, cmp_h, Ws1, bs1, hid, MROWS, DD, EE,   CATW, DD, DD, 0, 0, 0, 1);
    gemm(G_MLP, hid,   Ws2, bs2, pq,  MROWS, DD, DD,   DD,   DD, DD, 0, 0, 0, 1);
    gemm(G_NT,  pq, pq, nullptr, s1,  LL, LL, DD, DD, DD, LL, SQ, SQ, SS, BB);
    softmax_self_k<<<dim3(LL, BB), 256>>>(s1, mh, distW);
    gemm(G_NN,  s1, cmp_h, nullptr, cmp_h + EE, LL, EE, LL, LL, CATW, CATW, SS, SC, SC, BB);

    // ---- inter attention ----
    gemm(G_MLP, cmp_p, Wa1, ba1, hid, MROWS, DD, 2 * EE, CATW, DD, DD, 0, 0, 0, 1);
    gemm(G_MLP, hid,   Wa2, ba2, pq,  MROWS, DD, DD,     DD,   DD, DD, 0, 0, 0, 1);
    gemm(G_MLP, cmp_h, Wa1, ba1, hid, MROWS, DD, 2 * EE, CATW, DD, DD, 0, 0, 0, 1);
    gemm(G_MLP, hid,   Wa2, ba2, hk,  MROWS, DD, DD,     DD,   DD, DD, 0, 0, 0, 1);
    gemm(G_NT,  pq, hk, nullptr, s1,  LL, LL, DD, DD, DD, LL, SQ, SQ, SS, BB);
    softmax_cols_k<<<dim3(LL, BB), 256>>>(s1, mp, s2);   // hypo2prem (reads cols of z)
    softmax_rows_k<<<dim3(LL, BB), 256>>>(s1, mh);       // prem2hypo (in place)
    // attended_hypo -> cmp_p[:, 1024:2048]
    gemm(G_NN, s1, cmp_h, nullptr, cmp_p + 2 * EE, LL, 2 * EE, LL, LL, CATW, CATW, SS, SC, SC, BB);
    // attended_prem -> cmp_h[:, 1024:2048]
    gemm(G_NN, s2, cmp_p, nullptr, cmp_h + 2 * EE, LL, 2 * EE, LL, LL, CATW, CATW, SS, SC, SC, BB);

    // ---- compare + masked sum ----
    gemm(G_MLP, cmp_p, Wc1, bc1, hid, MROWS, DD, 4 * EE, CATW, DD, DD, 0, 0, 0, 1);
    gemm(G_MLP, hid,   Wc2, bc2, pq,  MROWS, DD, DD,     DD,   DD, DD, 0, 0, 0, 1);
    masked_sum_k<<<dim3(DD / 128, BB), 128>>>(pq, mp, agg, 0);
    gemm(G_MLP, cmp_h, Wc1, bc1, hid, MROWS, DD, 4 * EE, CATW, DD, DD, 0, 0, 0, 1);
    gemm(G_MLP, hid,   Wc2, bc2, pq,  MROWS, DD, DD,     DD,   DD, DD, 0, 0, 0, 1);
    masked_sum_k<<<dim3(DD / 128, BB), 128>>>(pq, mh, agg, DD);

    // ---- aggregate MLP + output ----
    head_k<<<BB, DD>>>(agg, Wg1, bg1, Wg2, bg2, Wo, out);
}

// round 13
// speedup vs baseline: 1.6609x; 1.6609x over previous
#include <cuda_runtime.h>
#include <cuda_bf16.h>
#include <cstdint>

// ---------------- problem constants ----------------
#define BB    64
#define LL    256
#define EE    512
#define DD    512
#define MROWS (BB * LL)        // 16384
#define CATW  2048             // [x(512) | ctx(512) | attended(1024)]

// ---------------- scratch (static device globals; no allocations) ----------
__device__ float g_cmp_p[MROWS * CATW];
__device__ float g_cmp_h[MROWS * CATW];
__device__ float g_pq   [MROWS * DD];
__device__ float g_hk   [MROWS * DD];
__device__ float g_s1   [BB * LL * LL];
__device__ float g_s2   [BB * LL * LL];
__device__ float g_agg  [BB * 2 * DD];
__device__ int   g_mask_p[MROWS];
__device__ int   g_mask_h[MROWS];
// bf16 split buffers
__device__ __align__(256) __nv_bfloat16 g_ahi[MROWS * 2048];
__device__ __align__(256) __nv_bfloat16 g_alo[MROWS * 2048];
__device__ __align__(256) __nv_bfloat16 g_hhi[MROWS * DD];
__device__ __align__(256) __nv_bfloat16 g_hlo[MROWS * DD];
__device__ __align__(256) __nv_bfloat16 g_w1h[2048 * DD];
__device__ __align__(256) __nv_bfloat16 g_w1l[2048 * DD];
__device__ __align__(256) __nv_bfloat16 g_w2h[2048 * DD];
__device__ __align__(256) __nv_bfloat16 g_w2l[2048 * DD];

__device__ __forceinline__ float relu_(float x) { return x > 0.f ? x : 0.f; }

// ===================== portable tensor-core helpers (sm_80+ PTX) ============
__device__ __forceinline__ uint32_t smem_u32(const void* p) {
    uint32_t a;
    asm("{ .reg .u64 t; cvta.to.shared.u64 t, %1; cvt.u32.u64 %0, t; }" : "=r"(a) : "l"(p));
    return a;
}
__device__ __forceinline__ void cp16(uint32_t dst, const void* src) {
    asm volatile("cp.async.cg.shared.global [%0], [%1], 16;\n" :: "r"(dst), "l"(src));
}
__device__ __forceinline__ void cp_commit() {
    asm volatile("cp.async.commit_group;\n" ::);
}
template<int N>
__device__ __forceinline__ void cp_wait() {
    asm volatile("cp.async.wait_group %0;\n" :: "n"(N));
}
__device__ __forceinline__ void ldmx4(uint32_t* r, uint32_t addr) {
    asm volatile("ldmatrix.sync.aligned.m8n8.x4.shared.b16 {%0,%1,%2,%3}, [%4];\n"
                 : "=r"(r[0]), "=r"(r[1]), "=r"(r[2]), "=r"(r[3]) : "r"(addr));
}
__device__ __forceinline__ void mma16816(float* d, const uint32_t* a, const uint32_t* b) {
    asm volatile("mma.sync.aligned.m16n8k16.row.col.f32.bf16.bf16.f32 "
                 "{%0,%1,%2,%3}, {%4,%5,%6,%7}, {%8,%9}, {%0,%1,%2,%3};\n"
                 : "+f"(d[0]), "+f"(d[1]), "+f"(d[2]), "+f"(d[3])
                 : "r"(a[0]), "r"(a[1]), "r"(a[2]), "r"(a[3]), "r"(b[0]), "r"(b[1]));
}

// =====================================================================
// split-bf16 MLP GEMM on mma.sync: C = relu(A @ W + bias)
//   A: bf16 hi/lo [M,K] row-major.  W: bf16 hi/lo [N,K] (pre-transposed).
//   CTA tile 128x128, K-stage 32, cp.async double buffer.
//   8 warps = 4(m) x 2(n); warp tile 32x64; m16n8k16 frags via ldmatrix.
//   OUTMODE 0: fp32 C[ldc].  OUTMODE 1: bf16 hi/lo pair [ldc16].
// =====================================================================
#define ST 40                                   // smem row stride (bf16 elems)
#define TILE_ELEMS (128 * ST)                   // one operand tile
#define TC_SMEM_BYTES (2 * 4 * TILE_ELEMS * 2)  // 81920 B

template<int OUTMODE>
__global__ void __launch_bounds__(256)
tcmlp_k(const __nv_bfloat16* __restrict__ Ah, const __nv_bfloat16* __restrict__ Al,
        const __nv_bfloat16* __restrict__ Bh, const __nv_bfloat16* __restrict__ Bl,
        const float* __restrict__ bias, int K,
        float* __restrict__ Cf, int ldc,
        __nv_bfloat16* __restrict__ Ch, __nv_bfloat16* __restrict__ Cl, int ldc16)
{
    extern __shared__ __nv_bfloat16 sm[];       // [2][4][TILE_ELEMS]
    const int tid = threadIdx.x, lane = tid & 31, wid = tid >> 5;
    const int bm = blockIdx.y << 7, bn = blockIdx.x << 7;
    const int wm = (wid & 3) << 5;              // warp m offset (0..96)
    const int wn = (wid >> 2) << 6;             // warp n offset (0/64)

    const __nv_bfloat16* gsrc[4] = {
        Ah + (long long)bm * K, Al + (long long)bm * K,
        Bh + (long long)bn * K, Bl + (long long)bn * K };

    // loader coords: chunk c = tid + j*256 -> row = c>>2, 16B piece = c&3
    const int lrow0 = tid >> 2;
    const int lh    = (tid & 3) << 3;           // bf16-element offset of 16B piece

    float acc[2][8][4];
#pragma unroll
    for (int mt = 0; mt < 2; mt++)
#pragma unroll
        for (int nt = 0; nt < 8; nt++)
#pragma unroll
            for (int i = 0; i < 4; i++) acc[mt][nt][i] = 0.f;

    const int S = K >> 5;

    auto issue = [&](int s) {
        const int buf = s & 1;
        const int k0 = s << 5;
#pragma unroll
        for (int t = 0; t < 4; t++) {
            const __nv_bfloat16* g = gsrc[t] + k0 + lh;
            const uint32_t dbase = smem_u32(sm + (buf * 4 + t) * TILE_ELEMS) + lh * 2;
#pragma unroll
            for (int j = 0; j < 2; j++) {
                const int row = lrow0 + j * 64;
                cp16(dbase + row * (ST * 2), g + (long long)row * K);
            }
        }
        cp_commit();
    };

    issue(0);
    issue(1);

    for (int s = 0; s < S; s++) {
        if (s + 1 < S) cp_wait<1>(); else cp_wait<0>();
        __syncthreads();

        const uint32_t base = smem_u32(sm + (s & 1) * 4 * TILE_ELEMS);
        const uint32_t sAh = base;
        const uint32_t sAl = base + TILE_ELEMS * 2;
        const uint32_t sBh = base + 2 * TILE_ELEMS * 2;
        const uint32_t sBl = base + 3 * TILE_ELEMS * 2;

#pragma unroll
        for (int kk = 0; kk < 2; kk++) {
            const int ko = kk << 4;
            // A fragments (hi & lo) for both m16 tiles
            uint32_t afh[2][4], afl[2][4];
            const int arow  = lane & 15;
            const int akofs = ko + ((lane >> 4) << 3);
#pragma unroll
            for (int mt = 0; mt < 2; mt++) {
                const uint32_t off = (uint32_t)(((wm + mt * 16 + arow) * ST + akofs) * 2);
                ldmx4(afh[mt], sAh + off);
                ldmx4(afl[mt], sAl + off);
            }
            // B fragments: each ldmatrix.x4 yields two n8k16 col-frags
            const int brow  = ((lane >> 4) << 3) + (lane & 7);
            const int bkofs = ko + (((lane >> 3) & 1) << 3);
#pragma unroll
            for (int np = 0; np < 4; np++) {
                const uint32_t off = (uint32_t)(((wn + np * 16 + brow) * ST + bkofs) * 2);
                uint32_t bfh[4], bfl[4];
                ldmx4(bfh, sBh + off);
                ldmx4(bfl, sBl + off);
#pragma unroll
                for (int mt = 0; mt < 2; mt++) {
                    mma16816(acc[mt][np * 2 + 0], afh[mt], bfh + 0);   // Ah*Wh
                    mma16816(acc[mt][np * 2 + 1], afh[mt], bfh + 2);
                    mma16816(acc[mt][np * 2 + 0], afh[mt], bfl + 0);   // Ah*Wl
                    mma16816(acc[mt][np * 2 + 1], afh[mt], bfl + 2);
                    mma16816(acc[mt][np * 2 + 0], afl[mt], bfh + 0);   // Al*Wh
                    mma16816(acc[mt][np * 2 + 1], afl[mt], bfh + 2);
                }
            }
        }
        __syncthreads();
        if (s + 2 < S) issue(s + 2);
    }

    // ---- epilogue: d frag (row = lane/4 (+8), col = 2*(lane&3) (+1)) ----
    const int er = lane >> 2;
    const int ec = (lane & 3) << 1;
#pragma unroll
    for (int mt = 0; mt < 2; mt++) {
        const int r0 = bm + wm + mt * 16 + er;
#pragma unroll
        for (int nt = 0; nt < 8; nt++) {
            const int col = bn + wn + nt * 8 + ec;
            const float b0 = bias[col], b1 = bias[col + 1];
            const float v00 = relu_(acc[mt][nt][0] + b0);
            const float v01 = relu_(acc[mt][nt][1] + b1);
            const float v10 = relu_(acc[mt][nt][2] + b0);
            const float v11 = relu_(acc[mt][nt][3] + b1);
            if (OUTMODE == 0) {
                *(float2*)(Cf + (long long)r0 * ldc + col)       = make_float2(v00, v01);
                *(float2*)(Cf + (long long)(r0 + 8) * ldc + col) = make_float2(v10, v11);
            } else {
                __nv_bfloat16 h00 = __float2bfloat16(v00), h01 = __float2bfloat16(v01);
                __nv_bfloat16 h10 = __float2bfloat16(v10), h11 = __float2bfloat16(v11);
                *(__nv_bfloat162*)(Ch + (long long)r0 * ldc16 + col) = __nv_bfloat162(h00, h01);
                *(__nv_bfloat162*)(Ch + (long long)(r0 + 8) * ldc16 + col) = __nv_bfloat162(h10, h11);
                *(__nv_bfloat162*)(Cl + (long long)r0 * ldc16 + col) =
                    __nv_bfloat162(__float2bfloat16(v00 - __bfloat162float(h00)),
                                   __float2bfloat16(v01 - __bfloat162float(h01)));
                *(__nv_bfloat162*)(Cl + (long long)(r0 + 8) * ldc16 + col) =
                    __nv_bfloat162(__float2bfloat16(v10 - __bfloat162float(h10)),
                                   __float2bfloat16(v11 - __bfloat162float(h11)));
            }
        }
    }
}

// ---- split fp32 activation [M,K] (row stride lda) -> bf16 hi/lo [M,K] ----
__global__ void split_a_k(const float* __restrict__ X, int lda, int K,
                          __nv_bfloat16* __restrict__ Ah, __nv_bfloat16* __restrict__ Al)
{
    const long long e = ((long long)blockIdx.x * 256 + threadIdx.x) * 4;
    const int r = (int)(e / K), c = (int)(e % K);
    float4 v = *(const float4*)(X + (long long)r * lda + c);
    __nv_bfloat16 h0 = __float2bfloat16(v.x), h1 = __float2bfloat16(v.y);
    __nv_bfloat16 h2 = __float2bfloat16(v.z), h3 = __float2bfloat16(v.w);
    __nv_bfloat162* hp = (__nv_bfloat162*)(Ah + e);
    __nv_bfloat162* lp = (__nv_bfloat162*)(Al + e);
    hp[0] = __nv_bfloat162(h0, h1); hp[1] = __nv_bfloat162(h2, h3);
    lp[0] = __nv_bfloat162(__float2bfloat16(v.x - __bfloat162float(h0)),
                           __float2bfloat16(v.y - __bfloat162float(h1)));
    lp[1] = __nv_bfloat162(__float2bfloat16(v.z - __bfloat162float(h2)),
                           __float2bfloat16(v.w - __bfloat162float(h3)));
}

// ---- transpose + split weight: W[K,N] fp32 -> Bh/Bl [N,K] bf16 ----
__global__ void splitT_k(const float* __restrict__ W,
                         __nv_bfloat16* __restrict__ Bh, __nv_bfloat16* __restrict__ Bl,
                         int K, int N)
{
    __shared__ float t[32][33];
    const int n0 = blockIdx.x * 32, k0 = blockIdx.y * 32;
    const int tx = threadIdx.x, ty = threadIdx.y;
    t[ty][tx] = W[(long long)(k0 + ty) * N + n0 + tx];
    __syncthreads();
    const float v = t[tx][ty];
    const __nv_bfloat16 h = __float2bfloat16(v);
    const long long o = (long long)(n0 + ty) * K + k0 + tx;
    Bh[o] = h;
    Bl[o] = __float2bfloat16(v - __bfloat162float(h));
}

// =====================================================================
// fp32 SGEMM (attention GEMMs): 128x128x16 tiles, double buffered
// =====================================================================
template<bool NT>
__global__ void __launch_bounds__(256, 2)
sgemm_k(const float* __restrict__ A, const float* __restrict__ B,
        float* __restrict__ C,
        int K, int lda, int ldb, int ldc,
        long long sA, long long sB, long long sC)
{
    __shared__ float As[2][16][132];
    __shared__ float Bs[2][16][132];

    const int tid = threadIdx.x;
    const int bm = blockIdx.y << 7;
    const int bn = blockIdx.x << 7;
    A += (long long)blockIdx.z * sA;
    B += (long long)blockIdx.z * sB;
    C += (long long)blockIdx.z * sC;

    const int lm = tid >> 2;
    const int lk = (tid & 3) << 2;

    const float* Ap0 = A + (long long)(bm + lm) * lda + lk;
    const float* Ap1 = Ap0 + (long long)64 * lda;

    const float* Bp0;
    const float* Bp1;
    int bkr = 0, bnc = 0;
    long long bstep = 16;
    if (NT) {
        Bp0 = B + (long long)(bn + lm) * ldb + lk;
        Bp1 = Bp0 + (long long)64 * ldb;
    } else {
        bkr = tid >> 5;
        bnc = (tid & 31) << 2;
        Bp0 = B + (long long)bkr * ldb + bn + bnc;
        Bp1 = Bp0 + (long long)8 * ldb;
        bstep = (long long)16 * ldb;
    }

    const int cr = (tid >> 4) << 3;
    const int cc = (tid & 15) << 3;

    float acc[8][8];
#pragma unroll
    for (int i = 0; i < 8; i++)
#pragma unroll
        for (int j = 0; j < 8; j++) acc[i][j] = 0.f;

    {
        float4 a0 = *(const float4*)Ap0;
        float4 a1 = *(const float4*)Ap1;
        As[0][lk + 0][lm] = a0.x; As[0][lk + 1][lm] = a0.y;
        As[0][lk + 2][lm] = a0.z; As[0][lk + 3][lm] = a0.w;
        As[0][lk + 0][lm + 64] = a1.x; As[0][lk + 1][lm + 64] = a1.y;
        As[0][lk + 2][lm + 64] = a1.z; As[0][lk + 3][lm + 64] = a1.w;
        if (NT) {
            float4 b0 = *(const float4*)Bp0;
            float4 b1 = *(const float4*)Bp1;
            Bs[0][lk + 0][lm] = b0.x; Bs[0][lk + 1][lm] = b0.y;
            Bs[0][lk + 2][lm] = b0.z; Bs[0][lk + 3][lm] = b0.w;
            Bs[0][lk + 0][lm + 64] = b1.x; Bs[0][lk + 1][lm + 64] = b1.y;
            Bs[0][lk + 2][lm + 64] = b1.z; Bs[0][lk + 3][lm + 64] = b1.w;
        } else {
            *(float4*)&Bs[0][bkr][bnc]     = *(const float4*)Bp0;
            *(float4*)&Bs[0][bkr + 8][bnc] = *(const float4*)Bp1;
        }
    }
    __syncthreads();

    const int KT = K >> 4;
    int buf = 0;
    for (int kt = 0; kt < KT; ++kt) {
        Ap0 += 16; Ap1 += 16;
        Bp0 += bstep; Bp1 += bstep;

        float4 na0, na1, nb0, nb1;
        const bool has_next = (kt + 1 < KT);
        if (has_next) {
            na0 = *(const float4*)Ap0;
            na1 = *(const float4*)Ap1;
            nb0 = *(const float4*)Bp0;
            nb1 = *(const float4*)Bp1;
        }

#pragma unroll
        for (int kk = 0; kk < 16; ++kk) {
            float av[8], bv[8];
            *(float4*)&av[0] = *(const float4*)&As[buf][kk][cr];
            *(float4*)&av[4] = *(const float4*)&As[buf][kk][cr + 4];
            *(float4*)&bv[0] = *(const float4*)&Bs[buf][kk][cc];
            *(float4*)&bv[4] = *(const float4*)&Bs[buf][kk][cc + 4];
#pragma unroll
            for (int i = 0; i < 8; i++)
#pragma unroll
                for (int j = 0; j < 8; j++)
                    acc[i][j] = fmaf(av[i], bv[j], acc[i][j]);
        }

        if (has_next) {
            const int nb = buf ^ 1;
            As[nb][lk + 0][lm] = na0.x; As[nb][lk + 1][lm] = na0.y;
            As[nb][lk + 2][lm] = na0.z; As[nb][lk + 3][lm] = na0.w;
            As[nb][lk + 0][lm + 64] = na1.x; As[nb][lk + 1][lm + 64] = na1.y;
            As[nb][lk + 2][lm + 64] = na1.z; As[nb][lk + 3][lm + 64] = na1.w;
            if (NT) {
                Bs[nb][lk + 0][lm] = nb0.x; Bs[nb][lk + 1][lm] = nb0.y;
                Bs[nb][lk + 2][lm] = nb0.z; Bs[nb][lk + 3][lm] = nb0.w;
                Bs[nb][lk + 0][lm + 64] = nb1.x; Bs[nb][lk + 1][lm + 64] = nb1.y;
                Bs[nb][lk + 2][lm + 64] = nb1.z; Bs[nb][lk + 3][lm + 64] = nb1.w;
            } else {
                *(float4*)&Bs[nb][bkr][bnc]     = nb0;
                *(float4*)&Bs[nb][bkr + 8][bnc] = nb1;
            }
            __syncthreads();
            buf = nb;
        }
    }

#pragma unroll
    for (int i = 0; i < 8; i++) {
        float* cp = C + (long long)(bm + cr + i) * ldc + bn + cc;
        *(float4*)cp       = make_float4(acc[i][0], acc[i][1], acc[i][2], acc[i][3]);
        *(float4*)(cp + 4) = make_float4(acc[i][4], acc[i][5], acc[i][6], acc[i][7]);
    }
}

// ---- embedding gather + mask ----
__global__ void embed_k(const int* __restrict__ tok, const float* __restrict__ W,
                        float* __restrict__ out, int* __restrict__ mask)
{
    const int r = blockIdx.x;
    const int t = tok[r];
    if (threadIdx.x == 0) mask[r] = (t != 0);
    const float4* src = (const float4*)(W + (long long)t * EE);
    float4* dst = (float4*)(out + (long long)r * CATW);
    dst[threadIdx.x] = src[threadIdx.x];
}

// ---------------- block reductions (blockDim = 256) ----------------
__device__ __forceinline__ float blockMax256(float v, float* red)
{
#pragma unroll
    for (int o = 16; o; o >>= 1) v = fmaxf(v, __shfl_xor_sync(0xffffffffu, v, o));
    if ((threadIdx.x & 31) == 0) red[threadIdx.x >> 5] = v;
    __syncthreads();
    float m = red[0];
#pragma unroll
    for (int i = 1; i < 8; i++) m = fmaxf(m, red[i]);
    return m;
}
__device__ __forceinline__ float blockSum256(float v, float* red)
{
#pragma unroll
    for (int o = 16; o; o >>= 1) v += __shfl_xor_sync(0xffffffffu, v, o);
    if ((threadIdx.x & 31) == 0) red[threadIdx.x >> 5] = v;
    __syncthreads();
    float s = red[0];
#pragma unroll
    for (int i = 1; i < 8; i++) s += red[i];
    return s;
}

__global__ void softmax_self_k(float* __restrict__ S, const int* __restrict__ mask,
                               const float* __restrict__ distW)
{
    const int q = blockIdx.x, b = blockIdx.y, k = threadIdx.x;
    float* row = S + ((long long)(b * LL + q)) * LL;
    __shared__ float red[8];
    __shared__ float dw[23];
    if (k < 23) dw[k] = distW[k];
    const int valid = mask[b * LL + k];
    const float sc = row[k];
    __syncthreads();

    float v;
    if (!valid)      v = -1e9f;
    else if (k == q) v = __int_as_float(0xff800000);
    else {
        int d = k - q; d = d < -11 ? -11 : (d > 11 ? 11 : d);
        v = sc + dw[d + 11];
    }
    const float m = blockMax256(v, red);
    __syncthreads();
    const float e = expf(v - m);
    const float s = blockSum256(e, red);
    row[k] = e / s;
}

__global__ void softmax_rows_k(float* __restrict__ Z, const int* __restrict__ mask)
{
    const int q = blockIdx.x, b = blockIdx.y, k = threadIdx.x;
    float* row = Z + ((long long)(b * LL + q)) * LL;
    __shared__ float red[8];
    const float v = mask[b * LL + k] ? row[k] : -1e9f;
    const float m = blockMax256(v, red);
    __syncthreads();
    const float e = expf(v - m);
    const float s = blockSum256(e, red);
    row[k] = e / s;
}

__global__ void softmax_cols_k(const float* __restrict__ Z, const int* __restrict__ maskP,
                               float* __restrict__ Out)
{
    const int h = blockIdx.x, b = blockIdx.y, p = threadIdx.x;
    __shared__ float red[8];
    const float v = maskP[b * LL + p]
                  ? Z[((long long)(b * LL + p)) * LL + h] : -1e9f;
    const float m = blockMax256(v, red);
    __syncthreads();
    const float e = expf(v - m);
    const float s = blockSum256(e, red);
    Out[((long long)(b * LL + h)) * LL + p] = e / s;
}

__global__ void masked_sum_k(const float* __restrict__ X, const int* __restrict__ mask,
                             float* __restrict__ out, int off)
{
    const int b = blockIdx.y;
    const int d = blockIdx.x * 128 + threadIdx.x;
    const float* xb = X + (long long)b * LL * DD;
    const int* mb = mask + b * LL;
    float acc = 0.f;
    for (int l = 0; l < LL; l++)
        if (mb[l]) acc += xb[l * DD + d];
    out[b * (2 * DD) + off + d] = acc;
}

__global__ void head_k(const float* __restrict__ aggin,
                       const float* __restrict__ Wg1, const float* __restrict__ bg1,
                       const float* __restrict__ Wg2, const float* __restrict__ bg2,
                       const float* __restrict__ Wo, float* __restrict__ out)
{
    __shared__ float sin[2 * DD];
    __shared__ float h1[DD];
    __shared__ float h2[DD];
    const int b = blockIdx.x, t = threadIdx.x;
    sin[t]       = aggin[b * 2 * DD + t];
    sin[t + DD]  = aggin[b * 2 * DD + DD + t];
    __syncthreads();
    float a = bg1[t];
    for (int k = 0; k < 2 * DD; k++) a = fmaf(sin[k], Wg1[k * DD + t], a);
    h1[t] = relu_(a);
    __syncthreads();
    a = bg2[t];
    for (int k = 0; k < DD; k++) a = fmaf(h1[k], Wg2[k * DD + t], a);
    h2[t] = relu_(a);
    __syncthreads();
    if (t < 3) {
        float s = 0.f;
        for (int k = 0; k < DD; k++) s = fmaf(h2[k], Wo[k * 3 + t], s);
        out[b * 3 + t] = s;
    }
}

// ---------------- host-side dispatch ----------------
static void gemm_nt(const float* A, const float* B, float* C, int M, int N, int K,
                    int lda, int ldb, int ldc, long long sA, long long sB, long long sC, int batch)
{
    dim3 grid(N >> 7, M >> 7, batch), blk(256);
    sgemm_k<true><<<grid, blk>>>(A, B, C, K, lda, ldb, ldc, sA, sB, sC);
}
static void gemm_nn(const float* A, const float* B, float* C, int M, int N, int K,
                    int lda, int ldb, int ldc, long long sA, long long sB, long long sC, int batch)
{
    dim3 grid(N >> 7, M >> 7, batch), blk(256);
    sgemm_k<false><<<grid, blk>>>(A, B, C, K, lda, ldb, ldc, sA, sB, sC);
}

static void tcmlp_f32(const __nv_bfloat16* Ah, const __nv_bfloat16* Al,
                      const __nv_bfloat16* Bh, const __nv_bfloat16* Bl,
                      const float* bias, int K, float* C, int ldc)
{
    dim3 grid(DD >> 7, MROWS >> 7);
    tcmlp_k<0><<<grid, 256, TC_SMEM_BYTES>>>(Ah, Al, Bh, Bl, bias, K, C, ldc,
                                             nullptr, nullptr, 0);
}
static void tcmlp_b16(const __nv_bfloat16* Ah, const __nv_bfloat16* Al,
                      const __nv_bfloat16* Bh, const __nv_bfloat16* Bl,
                      const float* bias, int K, __nv_bfloat16* Ch, __nv_bfloat16* Cl, int ldc16)
{
    dim3 grid(DD >> 7, MROWS >> 7);
    tcmlp_k<1><<<grid, 256, TC_SMEM_BYTES>>>(Ah, Al, Bh, Bl, bias, K, nullptr, 0,
                                             Ch, Cl, ldc16);
}
static void split_a(const float* X, int lda, int K, __nv_bfloat16* Ah, __nv_bfloat16* Al)
{
    long long total = (long long)MROWS * K / 4;
    split_a_k<<<(unsigned)(total / 256), 256>>>(X, lda, K, Ah, Al);
}
static void splitT(const float* W, __nv_bfloat16* Bh, __nv_bfloat16* Bl, int K, int N)
{
    splitT_k<<<dim3(N / 32, K / 32), dim3(32, 32)>>>(W, Bh, Bl, K, N);
}

extern "C" void kernel_launch(void* const* d_in, const int* in_sizes, int n_in,
                              void* d_out, int out_size)
{
    (void)in_sizes; (void)n_in; (void)out_size;
    const int*   prem  = (const int*)  d_in[0];
    const int*   hypo  = (const int*)  d_in[1];
    const float* embW  = (const float*)d_in[2];
    const float* distW = (const float*)d_in[3];
    const float* Ws1 = (const float*)d_in[4];  const float* bs1 = (const float*)d_in[5];
    const float* Ws2 = (const float*)d_in[6];  const float* bs2 = (const float*)d_in[7];
    const float* Wa1 = (const float*)d_in[8];  const float* ba1 = (const float*)d_in[9];
    const float* Wa2 = (const float*)d_in[10]; const float* ba2 = (const float*)d_in[11];
    const float* Wc1 = (const float*)d_in[12]; const float* bc1 = (const float*)d_in[13];
    const float* Wc2 = (const float*)d_in[14]; const float* bc2 = (const float*)d_in[15];
    const float* Wg1 = (const float*)d_in[16]; const float* bg1 = (const float*)d_in[17];
    const float* Wg2 = (const float*)d_in[18]; const float* bg2 = (const float*)d_in[19];
    const float* Wo  = (const float*)d_in[20];
    float* out = (float*)d_out;

    cudaFuncSetAttribute(tcmlp_k<0>, cudaFuncAttributeMaxDynamicSharedMemorySize, TC_SMEM_BYTES);
    cudaFuncSetAttribute(tcmlp_k<1>, cudaFuncAttributeMaxDynamicSharedMemorySize, TC_SMEM_BYTES);

    float *cmp_p, *cmp_h, *pq, *hk, *s1, *s2, *agg;
    int *mp, *mh;
    __nv_bfloat16 *ahi, *alo, *hhi, *hlo, *w1h, *w1l, *w2h, *w2l;
    cudaGetSymbolAddress((void**)&cmp_p, g_cmp_p);
    cudaGetSymbolAddress((void**)&cmp_h, g_cmp_h);
    cudaGetSymbolAddress((void**)&pq,    g_pq);
    cudaGetSymbolAddress((void**)&hk,    g_hk);
    cudaGetSymbolAddress((void**)&s1,    g_s1);
    cudaGetSymbolAddress((void**)&s2,    g_s2);
    cudaGetSymbolAddress((void**)&agg,   g_agg);
    cudaGetSymbolAddress((void**)&mp,    g_mask_p);
    cudaGetSymbolAddress((void**)&mh,    g_mask_h);
    cudaGetSymbolAddress((void**)&ahi,   g_ahi);
    cudaGetSymbolAddress((void**)&alo,   g_alo);
    cudaGetSymbolAddress((void**)&hhi,   g_hhi);
    cudaGetSymbolAddress((void**)&hlo,   g_hlo);
    cudaGetSymbolAddress((void**)&w1h,   g_w1h);
    cudaGetSymbolAddress((void**)&w1l,   g_w1l);
    cudaGetSymbolAddress((void**)&w2h,   g_w2h);
    cudaGetSymbolAddress((void**)&w2l,   g_w2l);

    const long long SQ  = (long long)LL * DD;
    const long long SS  = (long long)LL * LL;
    const long long SC  = (long long)LL * CATW;

    // embeddings -> concat[:, 0:512], masks
    embed_k<<<MROWS, 128>>>(prem, embW, cmp_p, mp);
    embed_k<<<MROWS, 128>>>(hypo, embW, cmp_h, mh);

    // ---- self branch (shared weights) ----
    splitT(Ws1, w1h, w1l, EE, DD);
    splitT(Ws2, w2h, w2l, DD, DD);
    // prem
    split_a(cmp_p, CATW, EE, ahi, alo);
    tcmlp_b16(ahi, alo, w1h, w1l, bs1, EE, hhi, hlo, DD);
    tcmlp_f32(hhi, hlo, w2h, w2l, bs2, DD, pq, DD);
    gemm_nt(pq, pq, s1, LL, LL, DD, DD, DD, LL, SQ, SQ, SS, BB);
    softmax_self_k<<<dim3(LL, BB), 256>>>(s1, mp, distW);
    gemm_nn(s1, cmp_p, cmp_p + EE, LL, EE, LL, LL, CATW, CATW, SS, SC, SC, BB);
    // hypo
    split_a(cmp_h, CATW, EE, ahi, alo);
    tcmlp_b16(ahi, alo, w1h, w1l, bs1, EE, hhi, hlo, DD);
    tcmlp_f32(hhi, hlo, w2h, w2l, bs2, DD, pq, DD);
    gemm_nt(pq, pq, s1, LL, LL, DD, DD, DD, LL, SQ, SQ, SS, BB);
    softmax_self_k<<<dim3(LL, BB), 256>>>(s1, mh, distW);
    gemm_nn(s1, cmp_h, cmp_h + EE, LL, EE, LL, LL, CATW, CATW, SS, SC, SC, BB);

    // ---- inter attention ----
    splitT(Wa1, w1h, w1l, 2 * EE, DD);
    splitT(Wa2, w2h, w2l, DD, DD);
    split_a(cmp_p, CATW, 2 * EE, ahi, alo);
    tcmlp_b16(ahi, alo, w1h, w1l, ba1, 2 * EE, hhi, hlo, DD);
    tcmlp_f32(hhi, hlo, w2h, w2l, ba2, DD, pq, DD);
    split_a(cmp_h, CATW, 2 * EE, ahi, alo);
    tcmlp_b16(ahi, alo, w1h, w1l, ba1, 2 * EE, hhi, hlo, DD);
    tcmlp_f32(hhi, hlo, w2h, w2l, ba2, DD, hk, DD);
    gemm_nt(pq, hk, s1, LL, LL, DD, DD, DD, LL, SQ, SQ, SS, BB);
    softmax_cols_k<<<dim3(LL, BB), 256>>>(s1, mp, s2);
    softmax_rows_k<<<dim3(LL, BB), 256>>>(s1, mh);
    gemm_nn(s1, cmp_h, cmp_p + 2 * EE, LL, 2 * EE, LL, LL, CATW, CATW, SS, SC, SC, BB);
    gemm_nn(s2, cmp_p, cmp_h + 2 * EE, LL, 2 * EE, LL, LL, CATW, CATW, SS, SC, SC, BB);

    // ---- compare + masked sum ----
    splitT(Wc1, w1h, w1l, 4 * EE, DD);
    splitT(Wc2, w2h, w2l, DD, DD);
    split_a(cmp_p, CATW, 4 * EE, ahi, alo);
    tcmlp_b16(ahi, alo, w1h, w1l, bc1, 4 * EE, hhi, hlo, DD);
    tcmlp_f32(hhi, hlo, w2h, w2l, bc2, DD, pq, DD);
    masked_sum_k<<<dim3(DD / 128, BB), 128>>>(pq, mp, agg, 0);
    split_a(cmp_h, CATW, 4 * EE, ahi, alo);
    tcmlp_b16(ahi, alo, w1h, w1l, bc1, 4 * EE, hhi, hlo, DD);
    tcmlp_f32(hhi, hlo, w2h, w2l, bc2, DD, pq, DD);
    masked_sum_k<<<dim3(DD / 128, BB), 128>>>(pq, mh, agg, DD);

    // ---- aggregate MLP + output ----
    head_k<<<BB, DD>>>(agg, Wg1, bg1, Wg2, bg2, Wo, out);
}

// round 14
// speedup vs baseline: 1.9128x; 1.1517x over previous
#include <cuda_runtime.h>
#include <cuda_bf16.h>
#include <cstdint>

// ---------------- problem constants ----------------
#define BB    64
#define LL    256
#define EE    512
#define DD    512
#define MROWS (BB * LL)        // 16384
#define CATW  2048             // [x(512) | ctx(512) | attended(1024)]

// ---------------- scratch (static device globals; no allocations) ----------
__device__ float g_cmp_p[MROWS * CATW];
__device__ float g_cmp_h[MROWS * CATW];
__device__ float g_pq   [MROWS * DD];
__device__ float g_s1   [BB * LL * LL];
__device__ float g_s2   [BB * LL * LL];
__device__ float g_agg  [BB * 2 * DD];
__device__ int   g_mask_p[MROWS];
__device__ int   g_mask_h[MROWS];
// bf16 split buffers
__device__ __align__(256) __nv_bfloat16 g_ahi[MROWS * 2048];
__device__ __align__(256) __nv_bfloat16 g_alo[MROWS * 2048];
__device__ __align__(256) __nv_bfloat16 g_bhi[MROWS * 1024];
__device__ __align__(256) __nv_bfloat16 g_blo[MROWS * 1024];
__device__ __align__(256) __nv_bfloat16 g_hhi[MROWS * DD];
__device__ __align__(256) __nv_bfloat16 g_hlo[MROWS * DD];
__device__ __align__(256) __nv_bfloat16 g_qhi[MROWS * DD];
__device__ __align__(256) __nv_bfloat16 g_qlo[MROWS * DD];
__device__ __align__(256) __nv_bfloat16 g_khi[MROWS * DD];
__device__ __align__(256) __nv_bfloat16 g_klo[MROWS * DD];
__device__ __align__(256) __nv_bfloat16 g_p1h[MROWS * LL];
__device__ __align__(256) __nv_bfloat16 g_p1l[MROWS * LL];
__device__ __align__(256) __nv_bfloat16 g_p2h[MROWS * LL];
__device__ __align__(256) __nv_bfloat16 g_p2l[MROWS * LL];
__device__ __align__(256) __nv_bfloat16 g_w1h[2048 * DD];
__device__ __align__(256) __nv_bfloat16 g_w1l[2048 * DD];
__device__ __align__(256) __nv_bfloat16 g_w2h[2048 * DD];
__device__ __align__(256) __nv_bfloat16 g_w2l[2048 * DD];

__device__ __forceinline__ float relu_(float x) { return x > 0.f ? x : 0.f; }

// ===================== portable tensor-core helpers (sm_80+ PTX) ============
__device__ __forceinline__ uint32_t smem_u32(const void* p) {
    uint32_t a;
    asm("{ .reg .u64 t; cvta.to.shared.u64 t, %1; cvt.u32.u64 %0, t; }" : "=r"(a) : "l"(p));
    return a;
}
__device__ __forceinline__ void cp16(uint32_t dst, const void* src) {
    asm volatile("cp.async.cg.shared.global [%0], [%1], 16;\n" :: "r"(dst), "l"(src));
}
__device__ __forceinline__ void cp_commit() {
    asm volatile("cp.async.commit_group;\n" ::);
}
template<int N>
__device__ __forceinline__ void cp_wait() {
    asm volatile("cp.async.wait_group %0;\n" :: "n"(N));
}
__device__ __forceinline__ void ldmx4(uint32_t* r, uint32_t addr) {
    asm volatile("ldmatrix.sync.aligned.m8n8.x4.shared.b16 {%0,%1,%2,%3}, [%4];\n"
                 : "=r"(r[0]), "=r"(r[1]), "=r"(r[2]), "=r"(r[3]) : "r"(addr));
}
__device__ __forceinline__ void ldmx4t(uint32_t* r, uint32_t addr) {
    asm volatile("ldmatrix.sync.aligned.m8n8.x4.trans.shared.b16 {%0,%1,%2,%3}, [%4];\n"
                 : "=r"(r[0]), "=r"(r[1]), "=r"(r[2]), "=r"(r[3]) : "r"(addr));
}
__device__ __forceinline__ void mma16816(float* d, const uint32_t* a, const uint32_t* b) {
    asm volatile("mma.sync.aligned.m16n8k16.row.col.f32.bf16.bf16.f32 "
                 "{%0,%1,%2,%3}, {%4,%5,%6,%7}, {%8,%9}, {%0,%1,%2,%3};\n"
                 : "+f"(d[0]), "+f"(d[1]), "+f"(d[2]), "+f"(d[3])
                 : "r"(a[0]), "r"(a[1]), "r"(a[2]), "r"(a[3]), "r"(b[0]), "r"(b[1]));
}

// =====================================================================
// split-bf16 MLP GEMM on mma.sync: C = relu(A @ W + bias)
//   A: bf16 hi/lo [M,K] row-major.  W: bf16 hi/lo [N,K] (pre-transposed).
//   CTA tile 128x128, K-stage 32, cp.async double buffer.
//   8 warps = 4(m) x 2(n); warp tile 32x64; m16n8k16 frags via ldmatrix.
//   OUTMODE 0: fp32 C[ldc].  OUTMODE 1: bf16 hi/lo pair [ldc16].
// =====================================================================
#define ST 40                                   // smem row stride (bf16 elems)
#define TILE_ELEMS (128 * ST)                   // one operand tile
#define TC_SMEM_BYTES (2 * 4 * TILE_ELEMS * 2)  // 81920 B

template<int OUTMODE>
__global__ void __launch_bounds__(256)
tcmlp_k(const __nv_bfloat16* __restrict__ Ah, const __nv_bfloat16* __restrict__ Al,
        const __nv_bfloat16* __restrict__ Bh, const __nv_bfloat16* __restrict__ Bl,
        const float* __restrict__ bias, int K,
        float* __restrict__ Cf, int ldc,
        __nv_bfloat16* __restrict__ Ch, __nv_bfloat16* __restrict__ Cl, int ldc16)
{
    extern __shared__ __nv_bfloat16 sm[];       // [2][4][TILE_ELEMS]
    const int tid = threadIdx.x, lane = tid & 31, wid = tid >> 5;
    const int bm = blockIdx.y << 7, bn = blockIdx.x << 7;
    const int wm = (wid & 3) << 5;
    const int wn = (wid >> 2) << 6;

    const __nv_bfloat16* gsrc[4] = {
        Ah + (long long)bm * K, Al + (long long)bm * K,
        Bh + (long long)bn * K, Bl + (long long)bn * K };

    const int lrow0 = tid >> 2;
    const int lh    = (tid & 3) << 3;

    float acc[2][8][4];
#pragma unroll
    for (int mt = 0; mt < 2; mt++)
#pragma unroll
        for (int nt = 0; nt < 8; nt++)
#pragma unroll
            for (int i = 0; i < 4; i++) acc[mt][nt][i] = 0.f;

    const int S = K >> 5;

    auto issue = [&](int s) {
        const int buf = s & 1;
        const int k0 = s << 5;
#pragma unroll
        for (int t = 0; t < 4; t++) {
            const __nv_bfloat16* g = gsrc[t] + k0 + lh;
            const uint32_t dbase = smem_u32(sm + (buf * 4 + t) * TILE_ELEMS) + lh * 2;
#pragma unroll
            for (int j = 0; j < 2; j++) {
                const int row = lrow0 + j * 64;
                cp16(dbase + row * (ST * 2), g + (long long)row * K);
            }
        }
        cp_commit();
    };

    issue(0);
    issue(1);

    for (int s = 0; s < S; s++) {
        if (s + 1 < S) cp_wait<1>(); else cp_wait<0>();
        __syncthreads();

        const uint32_t base = smem_u32(sm + (s & 1) * 4 * TILE_ELEMS);
        const uint32_t sAh = base;
        const uint32_t sAl = base + TILE_ELEMS * 2;
        const uint32_t sBh = base + 2 * TILE_ELEMS * 2;
        const uint32_t sBl = base + 3 * TILE_ELEMS * 2;

#pragma unroll
        for (int kk = 0; kk < 2; kk++) {
            const int ko = kk << 4;
            uint32_t afh[2][4], afl[2][4];
            const int arow  = lane & 15;
            const int akofs = ko + ((lane >> 4) << 3);
#pragma unroll
            for (int mt = 0; mt < 2; mt++) {
                const uint32_t off = (uint32_t)(((wm + mt * 16 + arow) * ST + akofs) * 2);
                ldmx4(afh[mt], sAh + off);
                ldmx4(afl[mt], sAl + off);
            }
            const int brow  = ((lane >> 4) << 3) + (lane & 7);
            const int bkofs = ko + (((lane >> 3) & 1) << 3);
#pragma unroll
            for (int np = 0; np < 4; np++) {
                const uint32_t off = (uint32_t)(((wn + np * 16 + brow) * ST + bkofs) * 2);
                uint32_t bfh[4], bfl[4];
                ldmx4(bfh, sBh + off);
                ldmx4(bfl, sBl + off);
#pragma unroll
                for (int mt = 0; mt < 2; mt++) {
                    mma16816(acc[mt][np * 2 + 0], afh[mt], bfh + 0);
                    mma16816(acc[mt][np * 2 + 1], afh[mt], bfh + 2);
                    mma16816(acc[mt][np * 2 + 0], afh[mt], bfl + 0);
                    mma16816(acc[mt][np * 2 + 1], afh[mt], bfl + 2);
                    mma16816(acc[mt][np * 2 + 0], afl[mt], bfh + 0);
                    mma16816(acc[mt][np * 2 + 1], afl[mt], bfh + 2);
                }
            }
        }
        __syncthreads();
        if (s + 2 < S) issue(s + 2);
    }

    const int er = lane >> 2;
    const int ec = (lane & 3) << 1;
#pragma unroll
    for (int mt = 0; mt < 2; mt++) {
        const int r0 = bm + wm + mt * 16 + er;
#pragma unroll
        for (int nt = 0; nt < 8; nt++) {
            const int col = bn + wn + nt * 8 + ec;
            const float b0 = bias[col], b1 = bias[col + 1];
            const float v00 = relu_(acc[mt][nt][0] + b0);
            const float v01 = relu_(acc[mt][nt][1] + b1);
            const float v10 = relu_(acc[mt][nt][2] + b0);
            const float v11 = relu_(acc[mt][nt][3] + b1);
            if (OUTMODE == 0) {
                *(float2*)(Cf + (long long)r0 * ldc + col)       = make_float2(v00, v01);
                *(float2*)(Cf + (long long)(r0 + 8) * ldc + col) = make_float2(v10, v11);
            } else {
                __nv_bfloat16 h00 = __float2bfloat16(v00), h01 = __float2bfloat16(v01);
                __nv_bfloat16 h10 = __float2bfloat16(v10), h11 = __float2bfloat16(v11);
                *(__nv_bfloat162*)(Ch + (long long)r0 * ldc16 + col) = __nv_bfloat162(h00, h01);
                *(__nv_bfloat162*)(Ch + (long long)(r0 + 8) * ldc16 + col) = __nv_bfloat162(h10, h11);
                *(__nv_bfloat162*)(Cl + (long long)r0 * ldc16 + col) =
                    __nv_bfloat162(__float2bfloat16(v00 - __bfloat162float(h00)),
                                   __float2bfloat16(v01 - __bfloat162float(h01)));
                *(__nv_bfloat162*)(Cl + (long long)(r0 + 8) * ldc16 + col) =
                    __nv_bfloat162(__float2bfloat16(v10 - __bfloat162float(h10)),
                                   __float2bfloat16(v11 - __bfloat162float(h11)));
            }
        }
    }
}

// =====================================================================
// batched NT scores on mma.sync: S[z] = A[z] @ B[z]^T, fp32 out.
//   A,B: bf16 hi/lo [LL, DD] per batch (row stride DD).  C: [LL, LL].
//   grid (2, 2, BB).  K = DD.
// =====================================================================
__global__ void __launch_bounds__(256)
tcnt_k(const __nv_bfloat16* __restrict__ Ah, const __nv_bfloat16* __restrict__ Al,
       const __nv_bfloat16* __restrict__ Bh, const __nv_bfloat16* __restrict__ Bl,
       float* __restrict__ C)
{
    extern __shared__ __nv_bfloat16 sm[];
    const int tid = threadIdx.x, lane = tid & 31, wid = tid >> 5;
    const int bm = blockIdx.y << 7, bn = blockIdx.x << 7;
    const long long zq = (long long)blockIdx.z * LL * DD;
    const int wm = (wid & 3) << 5;
    const int wn = (wid >> 2) << 6;

    const __nv_bfloat16* gsrc[4] = {
        Ah + zq + (long long)bm * DD, Al + zq + (long long)bm * DD,
        Bh + zq + (long long)bn * DD, Bl + zq + (long long)bn * DD };

    const int lrow0 = tid >> 2;
    const int lh    = (tid & 3) << 3;

    float acc[2][8][4];
#pragma unroll
    for (int mt = 0; mt < 2; mt++)
#pragma unroll
        for (int nt = 0; nt < 8; nt++)
#pragma unroll
            for (int i = 0; i < 4; i++) acc[mt][nt][i] = 0.f;

    const int S = DD >> 5;          // 16 stages

    auto issue = [&](int s) {
        const int buf = s & 1;
        const int k0 = s << 5;
#pragma unroll
        for (int t = 0; t < 4; t++) {
            const __nv_bfloat16* g = gsrc[t] + k0 + lh;
            const uint32_t dbase = smem_u32(sm + (buf * 4 + t) * TILE_ELEMS) + lh * 2;
#pragma unroll
            for (int j = 0; j < 2; j++) {
                const int row = lrow0 + j * 64;
                cp16(dbase + row * (ST * 2), g + (long long)row * DD);
            }
        }
        cp_commit();
    };

    issue(0);
    issue(1);

    for (int s = 0; s < S; s++) {
        if (s + 1 < S) cp_wait<1>(); else cp_wait<0>();
        __syncthreads();

        const uint32_t base = smem_u32(sm + (s & 1) * 4 * TILE_ELEMS);
        const uint32_t sAh = base;
        const uint32_t sAl = base + TILE_ELEMS * 2;
        const uint32_t sBh = base + 2 * TILE_ELEMS * 2;
        const uint32_t sBl = base + 3 * TILE_ELEMS * 2;

#pragma unroll
        for (int kk = 0; kk < 2; kk++) {
            const int ko = kk << 4;
            uint32_t afh[2][4], afl[2][4];
            const int arow  = lane & 15;
            const int akofs = ko + ((lane >> 4) << 3);
#pragma unroll
            for (int mt = 0; mt < 2; mt++) {
                const uint32_t off = (uint32_t)(((wm + mt * 16 + arow) * ST + akofs) * 2);
                ldmx4(afh[mt], sAh + off);
                ldmx4(afl[mt], sAl + off);
            }
            const int brow  = ((lane >> 4) << 3) + (lane & 7);
            const int bkofs = ko + (((lane >> 3) & 1) << 3);
#pragma unroll
            for (int np = 0; np < 4; np++) {
                const uint32_t off = (uint32_t)(((wn + np * 16 + brow) * ST + bkofs) * 2);
                uint32_t bfh[4], bfl[4];
                ldmx4(bfh, sBh + off);
                ldmx4(bfl, sBl + off);
#pragma unroll
                for (int mt = 0; mt < 2; mt++) {
                    mma16816(acc[mt][np * 2 + 0], afh[mt], bfh + 0);
                    mma16816(acc[mt][np * 2 + 1], afh[mt], bfh + 2);
                    mma16816(acc[mt][np * 2 + 0], afh[mt], bfl + 0);
                    mma16816(acc[mt][np * 2 + 1], afh[mt], bfl + 2);
                    mma16816(acc[mt][np * 2 + 0], afl[mt], bfh + 0);
                    mma16816(acc[mt][np * 2 + 1], afl[mt], bfh + 2);
                }
            }
        }
        __syncthreads();
        if (s + 2 < S) issue(s + 2);
    }

    float* Cz = C + (long long)blockIdx.z * LL * LL;
    const int er = lane >> 2;
    const int ec = (lane & 3) << 1;
#pragma unroll
    for (int mt = 0; mt < 2; mt++) {
        const int r0 = bm + wm + mt * 16 + er;
#pragma unroll
        for (int nt = 0; nt < 8; nt++) {
            const int col = bn + wn + nt * 8 + ec;
            *(float2*)(Cz + (long long)r0 * LL + col)       = make_float2(acc[mt][nt][0], acc[mt][nt][1]);
            *(float2*)(Cz + (long long)(r0 + 8) * LL + col) = make_float2(acc[mt][nt][2], acc[mt][nt][3]);
        }
    }
}

// =====================================================================
// batched NN attention-apply on mma.sync: C[z] = P[z] @ X[z], fp32 out.
//   P: probs bf16 hi/lo [LL, LL] per batch.  X: bf16 hi/lo [LL, N] per
//   batch (row stride N).  C: fp32 rows stride CATW (pointer pre-offset
//   to the target column block), batch stride LL*CATW.  K = LL.
//   B tiles loaded [32K x 128N] (stride 136), frags via ldmatrix.trans.
// =====================================================================
#define STN 136
#define BT_ELEMS (32 * STN)                     // 4352
#define NN_STAGE (2 * TILE_ELEMS + 2 * BT_ELEMS) // 18944 elems
#define NN_SMEM_BYTES (2 * NN_STAGE * 2)         // 75776 B

__global__ void __launch_bounds__(256)
tcnn_k(const __nv_bfloat16* __restrict__ Ph, const __nv_bfloat16* __restrict__ Pl,
       const __nv_bfloat16* __restrict__ Xh, const __nv_bfloat16* __restrict__ Xl,
       float* __restrict__ C, int N)
{
    extern __shared__ __nv_bfloat16 sm[];
    const int tid = threadIdx.x, lane = tid & 31, wid = tid >> 5;
    const int bm = blockIdx.y << 7, bn = blockIdx.x << 7;
    const int wm = (wid & 3) << 5;
    const int wn = (wid >> 2) << 6;

    const long long zp = (long long)blockIdx.z * LL * LL;
    const long long zx = (long long)blockIdx.z * LL * N;
    const __nv_bfloat16* gA[2] = { Ph + zp + (long long)bm * LL,
                                   Pl + zp + (long long)bm * LL };
    const __nv_bfloat16* gX[2] = { Xh + zx + bn, Xl + zx + bn };

    // A loader: 128 rows x 4 chunks (16B).  B loader: 32 rows x 16 chunks.
    const int arow0 = tid >> 2, ap = (tid & 3) << 3;
    const int brow0 = tid >> 4, bp = (tid & 15) << 3;

    float acc[2][8][4];
#pragma unroll
    for (int mt = 0; mt < 2; mt++)
#pragma unroll
        for (int nt = 0; nt < 8; nt++)
#pragma unroll
            for (int i = 0; i < 4; i++) acc[mt][nt][i] = 0.f;

    const int S = LL >> 5;          // 8 stages

    auto issue = [&](int s) {
        const int buf = s & 1;
        const int k0 = s << 5;
        const uint32_t sb = smem_u32(sm + buf * NN_STAGE);
#pragma unroll
        for (int t = 0; t < 2; t++) {
            const __nv_bfloat16* g = gA[t] + k0 + ap;
            const uint32_t dbase = sb + t * (TILE_ELEMS * 2) + ap * 2;
#pragma unroll
            for (int j = 0; j < 2; j++) {
                const int row = arow0 + j * 64;
                cp16(dbase + row * (ST * 2), g + (long long)row * LL);
            }
        }
#pragma unroll
        for (int t = 0; t < 2; t++) {
            const __nv_bfloat16* g = gX[t] + bp;
            const uint32_t dbase = sb + (2 * TILE_ELEMS + t * BT_ELEMS) * 2 + bp * 2;
#pragma unroll
            for (int j = 0; j < 2; j++) {
                const int row = brow0 + j * 16;
                cp16(dbase + row * (STN * 2), g + (long long)(k0 + row) * N);
            }
        }
        cp_commit();
    };

    issue(0);
    issue(1);

    for (int s = 0; s < S; s++) {
        if (s + 1 < S) cp_wait<1>(); else cp_wait<0>();
        __syncthreads();

        const uint32_t base = smem_u32(sm + (s & 1) * NN_STAGE);
        const uint32_t sAh = base;
        const uint32_t sAl = base + TILE_ELEMS * 2;
        const uint32_t sBh = base + 2 * TILE_ELEMS * 2;
        const uint32_t sBl = sBh + BT_ELEMS * 2;

#pragma unroll
        for (int kk = 0; kk < 2; kk++) {
            const int ko = kk << 4;
            uint32_t afh[2][4], afl[2][4];
            const int arow  = lane & 15;
            const int akofs = ko + ((lane >> 4) << 3);
#pragma unroll
            for (int mt = 0; mt < 2; mt++) {
                const uint32_t off = (uint32_t)(((wm + mt * 16 + arow) * ST + akofs) * 2);
                ldmx4(afh[mt], sAh + off);
                ldmx4(afl[mt], sAl + off);
            }
            // trans B frags from [K,N] tile
            const int krow = ko + (((lane >> 3) & 1) << 3) + (lane & 7);
            const int ncol = (lane >> 4) << 3;
#pragma unroll
            for (int np = 0; np < 4; np++) {
                const uint32_t off = (uint32_t)((krow * STN + wn + np * 16 + ncol) * 2);
                uint32_t bfh[4], bfl[4];
                ldmx4t(bfh, sBh + off);
                ldmx4t(bfl, sBl + off);
#pragma unroll
                for (int mt = 0; mt < 2; mt++) {
                    mma16816(acc[mt][np * 2 + 0], afh[mt], bfh + 0);
                    mma16816(acc[mt][np * 2 + 1], afh[mt], bfh + 2);
                    mma16816(acc[mt][np * 2 + 0], afh[mt], bfl + 0);
                    mma16816(acc[mt][np * 2 + 1], afh[mt], bfl + 2);
                    mma16816(acc[mt][np * 2 + 0], afl[mt], bfh + 0);
                    mma16816(acc[mt][np * 2 + 1], afl[mt], bfh + 2);
                }
            }
        }
        __syncthreads();
        if (s + 2 < S) issue(s + 2);
    }

    float* Cz = C + (long long)blockIdx.z * LL * CATW;
    const int er = lane >> 2;
    const int ec = (lane & 3) << 1;
#pragma unroll
    for (int mt = 0; mt < 2; mt++) {
        const int r0 = bm + wm + mt * 16 + er;
#pragma unroll
        for (int nt = 0; nt < 8; nt++) {
            const int col = bn + wn + nt * 8 + ec;
            *(float2*)(Cz + (long long)r0 * CATW + col)       = make_float2(acc[mt][nt][0], acc[mt][nt][1]);
            *(float2*)(Cz + (long long)(r0 + 8) * CATW + col) = make_float2(acc[mt][nt][2], acc[mt][nt][3]);
        }
    }
}

// ---- split fp32 [MROWS,K] (row stride lda) -> bf16 hi/lo [MROWS,K] ----
__global__ void split_a_k(const float* __restrict__ X, int lda, int K,
                          __nv_bfloat16* __restrict__ Ah, __nv_bfloat16* __restrict__ Al)
{
    const long long e = ((long long)blockIdx.x * 256 + threadIdx.x) * 4;
    const int r = (int)(e / K), c = (int)(e % K);
    float4 v = *(const float4*)(X + (long long)r * lda + c);
    __nv_bfloat16 h0 = __float2bfloat16(v.x), h1 = __float2bfloat16(v.y);
    __nv_bfloat16 h2 = __float2bfloat16(v.z), h3 = __float2bfloat16(v.w);
    __nv_bfloat162* hp = (__nv_bfloat162*)(Ah + e);
    __nv_bfloat162* lp = (__nv_bfloat162*)(Al + e);
    hp[0] = __nv_bfloat162(h0, h1); hp[1] = __nv_bfloat162(h2, h3);
    lp[0] = __nv_bfloat162(__float2bfloat16(v.x - __bfloat162float(h0)),
                           __float2bfloat16(v.y - __bfloat162float(h1)));
    lp[1] = __nv_bfloat162(__float2bfloat16(v.z - __bfloat162float(h2)),
                           __float2bfloat16(v.w - __bfloat162float(h3)));
}

// ---- transpose + split weight: W[K,N] fp32 -> Bh/Bl [N,K] bf16 ----
__global__ void splitT_k(const float* __restrict__ W,
                         __nv_bfloat16* __restrict__ Bh, __nv_bfloat16* __restrict__ Bl,
                         int K, int N)
{
    __shared__ float t[32][33];
    const int n0 = blockIdx.x * 32, k0 = blockIdx.y * 32;
    const int tx = threadIdx.x, ty = threadIdx.y;
    t[ty][tx] = W[(long long)(k0 + ty) * N + n0 + tx];
    __syncthreads();
    const float v = t[tx][ty];
    const __nv_bfloat16 h = __float2bfloat16(v);
    const long long o = (long long)(n0 + ty) * K + k0 + tx;
    Bh[o] = h;
    Bl[o] = __float2bfloat16(v - __bfloat162float(h));
}

// ---- embedding gather + mask ----
__global__ void embed_k(const int* __restrict__ tok, const float* __restrict__ W,
                        float* __restrict__ out, int* __restrict__ mask)
{
    const int r = blockIdx.x;
    const int t = tok[r];
    if (threadIdx.x == 0) mask[r] = (t != 0);
    const float4* src = (const float4*)(W + (long long)t * EE);
    float4* dst = (float4*)(out + (long long)r * CATW);
    dst[threadIdx.x] = src[threadIdx.x];
}

// ---------------- block reductions (blockDim = 256) ----------------
__device__ __forceinline__ float blockMax256(float v, float* red)
{
#pragma unroll
    for (int o = 16; o; o >>= 1) v = fmaxf(v, __shfl_xor_sync(0xffffffffu, v, o));
    if ((threadIdx.x & 31) == 0) red[threadIdx.x >> 5] = v;
    __syncthreads();
    float m = red[0];
#pragma unroll
    for (int i = 1; i < 8; i++) m = fmaxf(m, red[i]);
    return m;
}
__device__ __forceinline__ float blockSum256(float v, float* red)
{
#pragma unroll
    for (int o = 16; o; o >>= 1) v += __shfl_xor_sync(0xffffffffu, v, o);
    if ((threadIdx.x & 31) == 0) red[threadIdx.x >> 5] = v;
    __syncthreads();
    float s = red[0];
#pragma unroll
    for (int i = 1; i < 8; i++) s += red[i];
    return s;
}

__global__ void softmax_self_k(float* __restrict__ S, const int* __restrict__ mask,
                               const float* __restrict__ distW)
{
    const int q = blockIdx.x, b = blockIdx.y, k = threadIdx.x;
    float* row = S + ((long long)(b * LL + q)) * LL;
    __shared__ float red[8];
    __shared__ float dw[23];
    if (k < 23) dw[k] = distW[k];
    const int valid = mask[b * LL + k];
    const float sc = row[k];
    __syncthreads();

    float v;
    if (!valid)      v = -1e9f;
    else if (k == q) v = __int_as_float(0xff800000);
    else {
        int d = k - q; d = d < -11 ? -11 : (d > 11 ? 11 : d);
        v = sc + dw[d + 11];
    }
    const float m = blockMax256(v, red);
    __syncthreads();
    const float e = expf(v - m);
    const float s = blockSum256(e, red);
    row[k] = e / s;
}

__global__ void softmax_rows_k(float* __restrict__ Z, const int* __restrict__ mask)
{
    const int q = blockIdx.x, b = blockIdx.y, k = threadIdx.x;
    float* row = Z + ((long long)(b * LL + q)) * LL;
    __shared__ float red[8];
    const float v = mask[b * LL + k] ? row[k] : -1e9f;
    const float m = blockMax256(v, red);
    __syncthreads();
    const float e = expf(v - m);
    const float s = blockSum256(e, red);
    row[k] = e / s;
}

__global__ void softmax_cols_k(const float* __restrict__ Z, const int* __restrict__ maskP,
                               float* __restrict__ Out)
{
    const int h = blockIdx.x, b = blockIdx.y, p = threadIdx.x;
    __shared__ float red[8];
    const float v = maskP[b * LL + p]
                  ? Z[((long long)(b * LL + p)) * LL + h] : -1e9f;
    const float m = blockMax256(v, red);
    __syncthreads();
    const float e = expf(v - m);
    const float s = blockSum256(e, red);
    Out[((long long)(b * LL + h)) * LL + p] = e / s;
}

__global__ void masked_sum_k(const float* __restrict__ X, const int* __restrict__ mask,
                             float* __restrict__ out, int off)
{
    const int b = blockIdx.y;
    const int d = blockIdx.x * 128 + threadIdx.x;
    const float* xb = X + (long long)b * LL * DD;
    const int* mb = mask + b * LL;
    float acc = 0.f;
    for (int l = 0; l < LL; l++)
        if (mb[l]) acc += xb[l * DD + d];
    out[b * (2 * DD) + off + d] = acc;
}

__global__ void head_k(const float* __restrict__ aggin,
                       const float* __restrict__ Wg1, const float* __restrict__ bg1,
                       const float* __restrict__ Wg2, const float* __restrict__ bg2,
                       const float* __restrict__ Wo, float* __restrict__ out)
{
    __shared__ float sin[2 * DD];
    __shared__ float h1[DD];
    __shared__ float h2[DD];
    const int b = blockIdx.x, t = threadIdx.x;
    sin[t]       = aggin[b * 2 * DD + t];
    sin[t + DD]  = aggin[b * 2 * DD + DD + t];
    __syncthreads();
    float a = bg1[t];
    for (int k = 0; k < 2 * DD; k++) a = fmaf(sin[k], Wg1[k * DD + t], a);
    h1[t] = relu_(a);
    __syncthreads();
    a = bg2[t];
    for (int k = 0; k < DD; k++) a = fmaf(h1[k], Wg2[k * DD + t], a);
    h2[t] = relu_(a);
    __syncthreads();
    if (t < 3) {
        float s = 0.f;
        for (int k = 0; k < DD; k++) s = fmaf(h2[k], Wo[k * 3 + t], s);
        out[b * 3 + t] = s;
    }
}

// ---------------- host-side dispatch ----------------
static void tcmlp_f32(const __nv_bfloat16* Ah, const __nv_bfloat16* Al,
                      const __nv_bfloat16* Bh, const __nv_bfloat16* Bl,
                      const float* bias, int K, float* C, int ldc)
{
    dim3 grid(DD >> 7, MROWS >> 7);
    tcmlp_k<0><<<grid, 256, TC_SMEM_BYTES>>>(Ah, Al, Bh, Bl, bias, K, C, ldc,
                                             nullptr, nullptr, 0);
}
static void tcmlp_b16(const __nv_bfloat16* Ah, const __nv_bfloat16* Al,
                      const __nv_bfloat16* Bh, const __nv_bfloat16* Bl,
                      const float* bias, int K, __nv_bfloat16* Ch, __nv_bfloat16* Cl, int ldc16)
{
    dim3 grid(DD >> 7, MROWS >> 7);
    tcmlp_k<1><<<grid, 256, TC_SMEM_BYTES>>>(Ah, Al, Bh, Bl, bias, K, nullptr, 0,
                                             Ch, Cl, ldc16);
}
static void tcnt(const __nv_bfloat16* Ah, const __nv_bfloat16* Al,
                 const __nv_bfloat16* Bh, const __nv_bfloat16* Bl, float* C)
{
    tcnt_k<<<dim3(2, 2, BB), 256, TC_SMEM_BYTES>>>(Ah, Al, Bh, Bl, C);
}
static void tcnn(const __nv_bfloat16* Ph, const __nv_bfloat16* Pl,
                 const __nv_bfloat16* Xh, const __nv_bfloat16* Xl, float* C, int N)
{
    tcnn_k<<<dim3(N >> 7, 2, BB), 256, NN_SMEM_BYTES>>>(Ph, Pl, Xh, Xl, C, N);
}
static void split_a(const float* X, int lda, int K, __nv_bfloat16* Ah, __nv_bfloat16* Al)
{
    long long total = (long long)MROWS * K / 4;
    split_a_k<<<(unsigned)(total / 256), 256>>>(X, lda, K, Ah, Al);
}
static void splitT(const float* W, __nv_bfloat16* Bh, __nv_bfloat16* Bl, int K, int N)
{
    splitT_k<<<dim3(N / 32, K / 32), dim3(32, 32)>>>(W, Bh, Bl, K, N);
}

extern "C" void kernel_launch(void* const* d_in, const int* in_sizes, int n_in,
                              void* d_out, int out_size)
{
    (void)in_sizes; (void)n_in; (void)out_size;
    const int*   prem  = (const int*)  d_in[0];
    const int*   hypo  = (const int*)  d_in[1];
    const float* embW  = (const float*)d_in[2];
    const float* distW = (const float*)d_in[3];
    const float* Ws1 = (const float*)d_in[4];  const float* bs1 = (const float*)d_in[5];
    const float* Ws2 = (const float*)d_in[6];  const float* bs2 = (const float*)d_in[7];
    const float* Wa1 = (const float*)d_in[8];  const float* ba1 = (const float*)d_in[9];
    const float* Wa2 = (const float*)d_in[10]; const float* ba2 = (const float*)d_in[11];
    const float* Wc1 = (const float*)d_in[12]; const float* bc1 = (const float*)d_in[13];
    const float* Wc2 = (const float*)d_in[14]; const float* bc2 = (const float*)d_in[15];
    const float* Wg1 = (const float*)d_in[16]; const float* bg1 = (const float*)d_in[17];
    const float* Wg2 = (const float*)d_in[18]; const float* bg2 = (const float*)d_in[19];
    const float* Wo  = (const float*)d_in[20];
    float* out = (float*)d_out;

    cudaFuncSetAttribute(tcmlp_k<0>, cudaFuncAttributeMaxDynamicSharedMemorySize, TC_SMEM_BYTES);
    cudaFuncSetAttribute(tcmlp_k<1>, cudaFuncAttributeMaxDynamicSharedMemorySize, TC_SMEM_BYTES);
    cudaFuncSetAttribute(tcnt_k, cudaFuncAttributeMaxDynamicSharedMemorySize, TC_SMEM_BYTES);
    cudaFuncSetAttribute(tcnn_k, cudaFuncAttributeMaxDynamicSharedMemorySize, NN_SMEM_BYTES);

    float *cmp_p, *cmp_h, *pq, *s1, *s2, *agg;
    int *mp, *mh;
    __nv_bfloat16 *ahi, *alo, *bhi, *blo, *hhi, *hlo, *qhi, *qlo, *khi, *klo;
    __nv_bfloat16 *p1h, *p1l, *p2h, *p2l, *w1h, *w1l, *w2h, *w2l;
    cudaGetSymbolAddress((void**)&cmp_p, g_cmp_p);
    cudaGetSymbolAddress((void**)&cmp_h, g_cmp_h);
    cudaGetSymbolAddress((void**)&pq,    g_pq);
    cudaGetSymbolAddress((void**)&s1,    g_s1);
    cudaGetSymbolAddress((void**)&s2,    g_s2);
    cudaGetSymbolAddress((void**)&agg,   g_agg);
    cudaGetSymbolAddress((void**)&mp,    g_mask_p);
    cudaGetSymbolAddress((void**)&mh,    g_mask_h);
    cudaGetSymbolAddress((void**)&ahi,   g_ahi);
    cudaGetSymbolAddress((void**)&alo,   g_alo);
    cudaGetSymbolAddress((void**)&bhi,   g_bhi);
    cudaGetSymbolAddress((void**)&blo,   g_blo);
    cudaGetSymbolAddress((void**)&hhi,   g_hhi);
    cudaGetSymbolAddress((void**)&hlo,   g_hlo);
    cudaGetSymbolAddress((void**)&qhi,   g_qhi);
    cudaGetSymbolAddress((void**)&qlo,   g_qlo);
    cudaGetSymbolAddress((void**)&khi,   g_khi);
    cudaGetSymbolAddress((void**)&klo,   g_klo);
    cudaGetSymbolAddress((void**)&p1h,   g_p1h);
    cudaGetSymbolAddress((void**)&p1l,   g_p1l);
    cudaGetSymbolAddress((void**)&p2h,   g_p2h);
    cudaGetSymbolAddress((void**)&p2l,   g_p2l);
    cudaGetSymbolAddress((void**)&w1h,   g_w1h);
    cudaGetSymbolAddress((void**)&w1l,   g_w1l);
    cudaGetSymbolAddress((void**)&w2h,   g_w2h);
    cudaGetSymbolAddress((void**)&w2l,   g_w2l);

    // embeddings -> concat[:, 0:512], masks
    embed_k<<<MROWS, 128>>>(prem, embW, cmp_p, mp);
    embed_k<<<MROWS, 128>>>(hypo, embW, cmp_h, mh);

    // ---- self branch (shared weights) ----
    splitT(Ws1, w1h, w1l, EE, DD);
    splitT(Ws2, w2h, w2l, DD, DD);
    // prem
    split_a(cmp_p, CATW, EE, ahi, alo);
    tcmlp_b16(ahi, alo, w1h, w1l, bs1, EE, hhi, hlo, DD);
    tcmlp_b16(hhi, hlo, w2h, w2l, bs2, DD, qhi, qlo, DD);
    tcnt(qhi, qlo, qhi, qlo, s1);
    softmax_self_k<<<dim3(LL, BB), 256>>>(s1, mp, distW);
    split_a(s1, LL, LL, p1h, p1l);
    tcnn(p1h, p1l, ahi, alo, cmp_p + EE, EE);          // ctx_prem
    // hypo
    split_a(cmp_h, CATW, EE, ahi, alo);
    tcmlp_b16(ahi, alo, w1h, w1l, bs1, EE, hhi, hlo, DD);
    tcmlp_b16(hhi, hlo, w2h, w2l, bs2, DD, qhi, qlo, DD);
    tcnt(qhi, qlo, qhi, qlo, s1);
    softmax_self_k<<<dim3(LL, BB), 256>>>(s1, mh, distW);
    split_a(s1, LL, LL, p1h, p1l);
    tcnn(p1h, p1l, ahi, alo, cmp_h + EE, EE);          // ctx_hypo

    // ---- inter attention ----
    splitT(Wa1, w1h, w1l, 2 * EE, DD);
    splitT(Wa2, w2h, w2l, DD, DD);
    split_a(cmp_p, CATW, 2 * EE, ahi, alo);            // prem [x|ctx] split (kept)
    tcmlp_b16(ahi, alo, w1h, w1l, ba1, 2 * EE, hhi, hlo, DD);
    tcmlp_b16(hhi, hlo, w2h, w2l, ba2, DD, qhi, qlo, DD);
    split_a(cmp_h, CATW, 2 * EE, bhi, blo);            // hypo [x|ctx] split (kept)
    tcmlp_b16(bhi, blo, w1h, w1l, ba1, 2 * EE, hhi, hlo, DD);
    tcmlp_b16(hhi, hlo, w2h, w2l, ba2, DD, khi, klo, DD);
    tcnt(qhi, qlo, khi, klo, s1);                      // z
    softmax_cols_k<<<dim3(LL, BB), 256>>>(s1, mp, s2); // hypo2prem
    softmax_rows_k<<<dim3(LL, BB), 256>>>(s1, mh);     // prem2hypo (in place)
    split_a(s1, LL, LL, p1h, p1l);
    split_a(s2, LL, LL, p2h, p2l);
    tcnn(p1h, p1l, bhi, blo, cmp_p + 2 * EE, 2 * EE);  // attended_hypo
    tcnn(p2h, p2l, ahi, alo, cmp_h + 2 * EE, 2 * EE);  // attended_prem

    // ---- compare + masked sum ----
    splitT(Wc1, w1h, w1l, 4 * EE, DD);
    splitT(Wc2, w2h, w2l, DD, DD);
    split_a(cmp_p, CATW, 4 * EE, ahi, alo);
    tcmlp_b16(ahi, alo, w1h, w1l, bc1, 4 * EE, hhi, hlo, DD);
    tcmlp_f32(hhi, hlo, w2h, w2l, bc2, DD, pq, DD);
    masked_sum_k<<<dim3(DD / 128, BB), 128>>>(pq, mp, agg, 0);
    split_a(cmp_h, CATW, 4 * EE, ahi, alo);
    tcmlp_b16(ahi, alo, w1h, w1l, bc1, 4 * EE, hhi, hlo, DD);
    tcmlp_f32(hhi, hlo, w2h, w2l, bc2, DD, pq, DD);
    masked_sum_k<<<dim3(DD / 128, BB), 128>>>(pq, mh, agg, DD);

    // ---- aggregate MLP + output ----
    head_k<<<BB, DD>>>(agg, Wg1, bg1, Wg2, bg2, Wo, out);
}

// round 15
// speedup vs baseline: 1.9533x; 1.0212x over previous
#include <cuda_runtime.h>
#include <cuda_bf16.h>
#include <cstdint>

// ---------------- problem constants ----------------
#define BB    64
#define LL    256
#define EE    512
#define DD    512
#define MROWS (BB * LL)        // 16384
#define CATW  2048             // [x(512) | ctx(512) | attended(1024)]

// ---------------- scratch (static device globals; no allocations) ----------
__device__ float g_pq [MROWS * DD];
__device__ float g_s1 [BB * LL * LL];
__device__ float g_agg[BB * 2 * DD];
__device__ int   g_mask_p[MROWS];
__device__ int   g_mask_h[MROWS];
// bf16 hi/lo concat buffers (row stride CATW)
__device__ __align__(256) __nv_bfloat16 g_chp[MROWS * CATW];
__device__ __align__(256) __nv_bfloat16 g_clp[MROWS * CATW];
__device__ __align__(256) __nv_bfloat16 g_chh[MROWS * CATW];
__device__ __align__(256) __nv_bfloat16 g_clh[MROWS * CATW];
// packed bf16 hi/lo intermediates
__device__ __align__(256) __nv_bfloat16 g_hhi[MROWS * DD];
__device__ __align__(256) __nv_bfloat16 g_hlo[MROWS * DD];
__device__ __align__(256) __nv_bfloat16 g_qhi[MROWS * DD];
__device__ __align__(256) __nv_bfloat16 g_qlo[MROWS * DD];
__device__ __align__(256) __nv_bfloat16 g_khi[MROWS * DD];
__device__ __align__(256) __nv_bfloat16 g_klo[MROWS * DD];
__device__ __align__(256) __nv_bfloat16 g_p1h[MROWS * LL];
__device__ __align__(256) __nv_bfloat16 g_p1l[MROWS * LL];
__device__ __align__(256) __nv_bfloat16 g_p2h[MROWS * LL];
__device__ __align__(256) __nv_bfloat16 g_p2l[MROWS * LL];
// weight splits [N,K]
__device__ __align__(256) __nv_bfloat16 g_w1h[2048 * DD];
__device__ __align__(256) __nv_bfloat16 g_w1l[2048 * DD];
__device__ __align__(256) __nv_bfloat16 g_w2h[2048 * DD];
__device__ __align__(256) __nv_bfloat16 g_w2l[2048 * DD];

__device__ __forceinline__ float relu_(float x) { return x > 0.f ? x : 0.f; }

// ===================== portable tensor-core helpers (sm_80+ PTX) ============
__device__ __forceinline__ uint32_t smem_u32(const void* p) {
    uint32_t a;
    asm("{ .reg .u64 t; cvta.to.shared.u64 t, %1; cvt.u32.u64 %0, t; }" : "=r"(a) : "l"(p));
    return a;
}
__device__ __forceinline__ void cp16(uint32_t dst, const void* src) {
    asm volatile("cp.async.cg.shared.global [%0], [%1], 16;\n" :: "r"(dst), "l"(src));
}
__device__ __forceinline__ void cp_commit() {
    asm volatile("cp.async.commit_group;\n" ::);
}
template<int N>
__device__ __forceinline__ void cp_wait() {
    asm volatile("cp.async.wait_group %0;\n" :: "n"(N));
}
__device__ __forceinline__ void ldmx4(uint32_t* r, uint32_t addr) {
    asm volatile("ldmatrix.sync.aligned.m8n8.x4.shared.b16 {%0,%1,%2,%3}, [%4];\n"
                 : "=r"(r[0]), "=r"(r[1]), "=r"(r[2]), "=r"(r[3]) : "r"(addr));
}
__device__ __forceinline__ void ldmx4t(uint32_t* r, uint32_t addr) {
    asm volatile("ldmatrix.sync.aligned.m8n8.x4.trans.shared.b16 {%0,%1,%2,%3}, [%4];\n"
                 : "=r"(r[0]), "=r"(r[1]), "=r"(r[2]), "=r"(r[3]) : "r"(addr));
}
__device__ __forceinline__ void mma16816(float* d, const uint32_t* a, const uint32_t* b) {
    asm volatile("mma.sync.aligned.m16n8k16.row.col.f32.bf16.bf16.f32 "
                 "{%0,%1,%2,%3}, {%4,%5,%6,%7}, {%8,%9}, {%0,%1,%2,%3};\n"
                 : "+f"(d[0]), "+f"(d[1]), "+f"(d[2]), "+f"(d[3])
                 : "r"(a[0]), "r"(a[1]), "r"(a[2]), "r"(a[3]), "r"(b[0]), "r"(b[1]));
}

// product-major mma sweep: consecutive mma hit 16 distinct accumulators
// before any reuse -> HMMA latency fully covered by ILP.
#define MMA_SWEEP(AF, BF)                                              \
    _Pragma("unroll")                                                  \
    for (int np = 0; np < 4; np++) {                                   \
        _Pragma("unroll")                                              \
        for (int mt = 0; mt < 2; mt++) {                               \
            mma16816(acc[mt][np * 2 + 0], AF[mt], BF[np] + 0);         \
            mma16816(acc[mt][np * 2 + 1], AF[mt], BF[np] + 2);         \
        }                                                              \
    }

// bf16 hi/lo pair store helper
__device__ __forceinline__ void store_hl(__nv_bfloat16* Hp, __nv_bfloat16* Lp,
                                         float v0, float v1) {
    __nv_bfloat16 h0 = __float2bfloat16(v0), h1 = __float2bfloat16(v1);
    *(__nv_bfloat162*)Hp = __nv_bfloat162(h0, h1);
    *(__nv_bfloat162*)Lp = __nv_bfloat162(__float2bfloat16(v0 - __bfloat162float(h0)),
                                          __float2bfloat16(v1 - __bfloat162float(h1)));
}

// =====================================================================
// split-bf16 MLP GEMM on mma.sync: C = relu(A @ W + bias)
//   A: bf16 hi/lo [M,K] rows stride lda.  W: bf16 hi/lo [N,K] packed.
//   CTA tile 128x128, K-stage 32, cp.async double buffer.
//   OUTMODE 0: fp32 C[ldc].  OUTMODE 1: bf16 hi/lo pair [ldc].
// =====================================================================
#define ST 40                                   // smem row stride (bf16 elems)
#define TILE_ELEMS (128 * ST)
#define TC_SMEM_BYTES (2 * 4 * TILE_ELEMS * 2)  // 81920 B

template<int OUTMODE>
__global__ void __launch_bounds__(256)
tcmlp_k(const __nv_bfloat16* __restrict__ Ah, const __nv_bfloat16* __restrict__ Al,
        int lda,
        const __nv_bfloat16* __restrict__ Bh, const __nv_bfloat16* __restrict__ Bl,
        const float* __restrict__ bias, int K,
        float* __restrict__ Cf,
        __nv_bfloat16* __restrict__ Ch, __nv_bfloat16* __restrict__ Cl, int ldc)
{
    extern __shared__ __nv_bfloat16 sm[];       // [2][4][TILE_ELEMS]
    const int tid = threadIdx.x, lane = tid & 31, wid = tid >> 5;
    const int bm = blockIdx.y << 7, bn = blockIdx.x << 7;
    const int wm = (wid & 3) << 5;
    const int wn = (wid >> 2) << 6;

    const __nv_bfloat16* gA[2] = { Ah + (long long)bm * lda, Al + (long long)bm * lda };
    const __nv_bfloat16* gB[2] = { Bh + (long long)bn * K,   Bl + (long long)bn * K };

    const int lrow0 = tid >> 2;
    const int lh    = (tid & 3) << 3;

    float acc[2][8][4];
#pragma unroll
    for (int mt = 0; mt < 2; mt++)
#pragma unroll
        for (int nt = 0; nt < 8; nt++)
#pragma unroll
            for (int i = 0; i < 4; i++) acc[mt][nt][i] = 0.f;

    const int S = K >> 5;

    auto issue = [&](int s) {
        const int buf = s & 1;
        const int k0 = s << 5;
#pragma unroll
        for (int t = 0; t < 2; t++) {
            const __nv_bfloat16* g = gA[t] + k0 + lh;
            const uint32_t dbase = smem_u32(sm + (buf * 4 + t) * TILE_ELEMS) + lh * 2;
#pragma unroll
            for (int j = 0; j < 2; j++) {
                const int row = lrow0 + j * 64;
                cp16(dbase + row * (ST * 2), g + (long long)row * lda);
            }
        }
#pragma unroll
        for (int t = 0; t < 2; t++) {
            const __nv_bfloat16* g = gB[t] + k0 + lh;
            const uint32_t dbase = smem_u32(sm + (buf * 4 + 2 + t) * TILE_ELEMS) + lh * 2;
#pragma unroll
            for (int j = 0; j < 2; j++) {
                const int row = lrow0 + j * 64;
                cp16(dbase + row * (ST * 2), g + (long long)row * K);
            }
        }
        cp_commit();
    };

    issue(0);
    issue(1);

    for (int s = 0; s < S; s++) {
        if (s + 1 < S) cp_wait<1>(); else cp_wait<0>();
        __syncthreads();

        const uint32_t base = smem_u32(sm + (s & 1) * 4 * TILE_ELEMS);
        const uint32_t sAh = base;
        const uint32_t sAl = base + TILE_ELEMS * 2;
        const uint32_t sBh = base + 2 * TILE_ELEMS * 2;
        const uint32_t sBl = base + 3 * TILE_ELEMS * 2;

#pragma unroll
        for (int kk = 0; kk < 2; kk++) {
            const int ko = kk << 4;
            uint32_t afh[2][4], afl[2][4];
            const int arow  = lane & 15;
            const int akofs = ko + ((lane >> 4) << 3);
#pragma unroll
            for (int mt = 0; mt < 2; mt++) {
                const uint32_t off = (uint32_t)(((wm + mt * 16 + arow) * ST + akofs) * 2);
                ldmx4(afh[mt], sAh + off);
                ldmx4(afl[mt], sAl + off);
            }
            uint32_t bfh[4][4], bfl[4][4];
            const int brow  = ((lane >> 4) << 3) + (lane & 7);
            const int bkofs = ko + (((lane >> 3) & 1) << 3);
#pragma unroll
            for (int np = 0; np < 4; np++) {
                const uint32_t off = (uint32_t)(((wn + np * 16 + brow) * ST + bkofs) * 2);
                ldmx4(bfh[np], sBh + off);
                ldmx4(bfl[np], sBl + off);
            }
            MMA_SWEEP(afh, bfh);
            MMA_SWEEP(afh, bfl);
            MMA_SWEEP(afl, bfh);
        }
        __syncthreads();
        if (s + 2 < S) issue(s + 2);
    }

    const int er = lane >> 2;
    const int ec = (lane & 3) << 1;
#pragma unroll
    for (int mt = 0; mt < 2; mt++) {
        const int r0 = bm + wm + mt * 16 + er;
#pragma unroll
        for (int nt = 0; nt < 8; nt++) {
            const int col = bn + wn + nt * 8 + ec;
            const float b0 = bias[col], b1 = bias[col + 1];
            const float v00 = relu_(acc[mt][nt][0] + b0);
            const float v01 = relu_(acc[mt][nt][1] + b1);
            const float v10 = relu_(acc[mt][nt][2] + b0);
            const float v11 = relu_(acc[mt][nt][3] + b1);
            if (OUTMODE == 0) {
                *(float2*)(Cf + (long long)r0 * ldc + col)       = make_float2(v00, v01);
                *(float2*)(Cf + (long long)(r0 + 8) * ldc + col) = make_float2(v10, v11);
            } else {
                store_hl(Ch + (long long)r0 * ldc + col,       Cl + (long long)r0 * ldc + col,       v00, v01);
                store_hl(Ch + (long long)(r0 + 8) * ldc + col, Cl + (long long)(r0 + 8) * ldc + col, v10, v11);
            }
        }
    }
}

// =====================================================================
// batched NT scores: S[z] = A[z] @ B[z]^T, fp32 out.  A,B packed [LL,DD].
// =====================================================================
__global__ void __launch_bounds__(256)
tcnt_k(const __nv_bfloat16* __restrict__ Ah, const __nv_bfloat16* __restrict__ Al,
       const __nv_bfloat16* __restrict__ Bh, const __nv_bfloat16* __restrict__ Bl,
       float* __restrict__ C)
{
    extern __shared__ __nv_bfloat16 sm[];
    const int tid = threadIdx.x, lane = tid & 31, wid = tid >> 5;
    const int bm = blockIdx.y << 7, bn = blockIdx.x << 7;
    const long long zq = (long long)blockIdx.z * LL * DD;
    const int wm = (wid & 3) << 5;
    const int wn = (wid >> 2) << 6;

    const __nv_bfloat16* gsrc[4] = {
        Ah + zq + (long long)bm * DD, Al + zq + (long long)bm * DD,
        Bh + zq + (long long)bn * DD, Bl + zq + (long long)bn * DD };

    const int lrow0 = tid >> 2;
    const int lh    = (tid & 3) << 3;

    float acc[2][8][4];
#pragma unroll
    for (int mt = 0; mt < 2; mt++)
#pragma unroll
        for (int nt = 0; nt < 8; nt++)
#pragma unroll
            for (int i = 0; i < 4; i++) acc[mt][nt][i] = 0.f;

    const int S = DD >> 5;

    auto issue = [&](int s) {
        const int buf = s & 1;
        const int k0 = s << 5;
#pragma unroll
        for (int t = 0; t < 4; t++) {
            const __nv_bfloat16* g = gsrc[t] + k0 + lh;
            const uint32_t dbase = smem_u32(sm + (buf * 4 + t) * TILE_ELEMS) + lh * 2;
#pragma unroll
            for (int j = 0; j < 2; j++) {
                const int row = lrow0 + j * 64;
                cp16(dbase + row * (ST * 2), g + (long long)row * DD);
            }
        }
        cp_commit();
    };

    issue(0);
    issue(1);

    for (int s = 0; s < S; s++) {
        if (s + 1 < S) cp_wait<1>(); else cp_wait<0>();
        __syncthreads();

        const uint32_t base = smem_u32(sm + (s & 1) * 4 * TILE_ELEMS);
        const uint32_t sAh = base;
        const uint32_t sAl = base + TILE_ELEMS * 2;
        const uint32_t sBh = base + 2 * TILE_ELEMS * 2;
        const uint32_t sBl = base + 3 * TILE_ELEMS * 2;

#pragma unroll
        for (int kk = 0; kk < 2; kk++) {
            const int ko = kk << 4;
            uint32_t afh[2][4], afl[2][4];
            const int arow  = lane & 15;
            const int akofs = ko + ((lane >> 4) << 3);
#pragma unroll
            for (int mt = 0; mt < 2; mt++) {
                const uint32_t off = (uint32_t)(((wm + mt * 16 + arow) * ST + akofs) * 2);
                ldmx4(afh[mt], sAh + off);
                ldmx4(afl[mt], sAl + off);
            }
            uint32_t bfh[4][4], bfl[4][4];
            const int brow  = ((lane >> 4) << 3) + (lane & 7);
            const int bkofs = ko + (((lane >> 3) & 1) << 3);
#pragma unroll
            for (int np = 0; np < 4; np++) {
                const uint32_t off = (uint32_t)(((wn + np * 16 + brow) * ST + bkofs) * 2);
                ldmx4(bfh[np], sBh + off);
                ldmx4(bfl[np], sBl + off);
            }
            MMA_SWEEP(afh, bfh);
            MMA_SWEEP(afh, bfl);
            MMA_SWEEP(afl, bfh);
        }
        __syncthreads();
        if (s + 2 < S) issue(s + 2);
    }

    float* Cz = C + (long long)blockIdx.z * LL * LL;
    const int er = lane >> 2;
    const int ec = (lane & 3) << 1;
#pragma unroll
    for (int mt = 0; mt < 2; mt++) {
        const int r0 = bm + wm + mt * 16 + er;
#pragma unroll
        for (int nt = 0; nt < 8; nt++) {
            const int col = bn + wn + nt * 8 + ec;
            *(float2*)(Cz + (long long)r0 * LL + col)       = make_float2(acc[mt][nt][0], acc[mt][nt][1]);
            *(float2*)(Cz + (long long)(r0 + 8) * LL + col) = make_float2(acc[mt][nt][2], acc[mt][nt][3]);
        }
    }
}

// =====================================================================
// batched NN attention-apply: C[z] = P[z] @ X[z], bf16 hi/lo out (stride CATW).
//   P: bf16 hi/lo [LL,LL] packed.  X: bf16 hi/lo [LL, N] rows stride ldx,
//   batch stride LL*ldx.  C: hi/lo, rows stride CATW, batch stride LL*CATW
//   (pointers pre-offset to the target column block).
// =====================================================================
#define STN 136
#define BT_ELEMS (32 * STN)
#define NN_STAGE (2 * TILE_ELEMS + 2 * BT_ELEMS)
#define NN_SMEM_BYTES (2 * NN_STAGE * 2)

__global__ void __launch_bounds__(256)
tcnn_k(const __nv_bfloat16* __restrict__ Ph, const __nv_bfloat16* __restrict__ Pl,
       const __nv_bfloat16* __restrict__ Xh, const __nv_bfloat16* __restrict__ Xl,
       int ldx,
       __nv_bfloat16* __restrict__ Ch, __nv_bfloat16* __restrict__ Cl)
{
    extern __shared__ __nv_bfloat16 sm[];
    const int tid = threadIdx.x, lane = tid & 31, wid = tid >> 5;
    const int bm = blockIdx.y << 7, bn = blockIdx.x << 7;
    const int wm = (wid & 3) << 5;
    const int wn = (wid >> 2) << 6;

    const long long zp = (long long)blockIdx.z * LL * LL;
    const long long zx = (long long)blockIdx.z * LL * ldx;
    const __nv_bfloat16* gA[2] = { Ph + zp + (long long)bm * LL,
                                   Pl + zp + (long long)bm * LL };
    const __nv_bfloat16* gX[2] = { Xh + zx + bn, Xl + zx + bn };

    const int arow0 = tid >> 2, ap = (tid & 3) << 3;
    const int brow0 = tid >> 4, bp = (tid & 15) << 3;

    float acc[2][8][4];
#pragma unroll
    for (int mt = 0; mt < 2; mt++)
#pragma unroll
        for (int nt = 0; nt < 8; nt++)
#pragma unroll
            for (int i = 0; i < 4; i++) acc[mt][nt][i] = 0.f;

    const int S = LL >> 5;

    auto issue = [&](int s) {
        const int buf = s & 1;
        const int k0 = s << 5;
        const uint32_t sb = smem_u32(sm + buf * NN_STAGE);
#pragma unroll
        for (int t = 0; t < 2; t++) {
            const __nv_bfloat16* g = gA[t] + k0 + ap;
            const uint32_t dbase = sb + t * (TILE_ELEMS * 2) + ap * 2;
#pragma unroll
            for (int j = 0; j < 2; j++) {
                const int row = arow0 + j * 64;
                cp16(dbase + row * (ST * 2), g + (long long)row * LL);
            }
        }
#pragma unroll
        for (int t = 0; t < 2; t++) {
            const __nv_bfloat16* g = gX[t] + bp;
            const uint32_t dbase = sb + (2 * TILE_ELEMS + t * BT_ELEMS) * 2 + bp * 2;
#pragma unroll
            for (int j = 0; j < 2; j++) {
                const int row = brow0 + j * 16;
                cp16(dbase + row * (STN * 2), g + (long long)(k0 + row) * ldx);
            }
        }
        cp_commit();
    };

    issue(0);
    issue(1);

    for (int s = 0; s < S; s++) {
        if (s + 1 < S) cp_wait<1>(); else cp_wait<0>();
        __syncthreads();

        const uint32_t base = smem_u32(sm + (s & 1) * NN_STAGE);
        const uint32_t sAh = base;
        const uint32_t sAl = base + TILE_ELEMS * 2;
        const uint32_t sBh = base + 2 * TILE_ELEMS * 2;
        const uint32_t sBl = sBh + BT_ELEMS * 2;

#pragma unroll
        for (int kk = 0; kk < 2; kk++) {
            const int ko = kk << 4;
            uint32_t afh[2][4], afl[2][4];
            const int arow  = lane & 15;
            const int akofs = ko + ((lane >> 4) << 3);
#pragma unroll
            for (int mt = 0; mt < 2; mt++) {
                const uint32_t off = (uint32_t)(((wm + mt * 16 + arow) * ST + akofs) * 2);
                ldmx4(afh[mt], sAh + off);
                ldmx4(afl[mt], sAl + off);
            }
            uint32_t bfh[4][4], bfl[4][4];
            const int krow = ko + (((lane >> 3) & 1) << 3) + (lane & 7);
            const int ncol = (lane >> 4) << 3;
#pragma unroll
            for (int np = 0; np < 4; np++) {
                const uint32_t off = (uint32_t)((krow * STN + wn + np * 16 + ncol) * 2);
                ldmx4t(bfh[np], sBh + off);
                ldmx4t(bfl[np], sBl + off);
            }
            MMA_SWEEP(afh, bfh);
            MMA_SWEEP(afh, bfl);
            MMA_SWEEP(afl, bfh);
        }
        __syncthreads();
        if (s + 2 < S) issue(s + 2);
    }

    __nv_bfloat16* Chz = Ch + (long long)blockIdx.z * LL * CATW;
    __nv_bfloat16* Clz = Cl + (long long)blockIdx.z * LL * CATW;
    const int er = lane >> 2;
    const int ec = (lane & 3) << 1;
#pragma unroll
    for (int mt = 0; mt < 2; mt++) {
        const int r0 = bm + wm + mt * 16 + er;
#pragma unroll
        for (int nt = 0; nt < 8; nt++) {
            const int col = bn + wn + nt * 8 + ec;
            store_hl(Chz + (long long)r0 * CATW + col,       Clz + (long long)r0 * CATW + col,
                     acc[mt][nt][0], acc[mt][nt][1]);
            store_hl(Chz + (long long)(r0 + 8) * CATW + col, Clz + (long long)(r0 + 8) * CATW + col,
                     acc[mt][nt][2], acc[mt][nt][3]);
        }
    }
}

// ---- transpose + split weight: W[K,N] fp32 -> Bh/Bl [N,K] bf16 ----
__global__ void splitT_k(const float* __restrict__ W,
                         __nv_bfloat16* __restrict__ Bh, __nv_bfloat16* __restrict__ Bl,
                         int K, int N)
{
    __shared__ float t[32][33];
    const int n0 = blockIdx.x * 32, k0 = blockIdx.y * 32;
    const int tx = threadIdx.x, ty = threadIdx.y;
    t[ty][tx] = W[(long long)(k0 + ty) * N + n0 + tx];
    __syncthreads();
    const float v = t[tx][ty];
    const __nv_bfloat16 h = __float2bfloat16(v);
    const long long o = (long long)(n0 + ty) * K + k0 + tx;
    Bh[o] = h;
    Bl[o] = __float2bfloat16(v - __bfloat162float(h));
}

// ---- embedding gather -> bf16 hi/lo concat cols 0..511, + mask ----
__global__ void embed_k(const int* __restrict__ tok, const float* __restrict__ W,
                        __nv_bfloat16* __restrict__ Oh, __nv_bfloat16* __restrict__ Ol,
                        int* __restrict__ mask)
{
    const int r = blockIdx.x;
    const int t = tok[r];
    if (threadIdx.x == 0) mask[r] = (t != 0);
    const float4 v = ((const float4*)(W + (long long)t * EE))[threadIdx.x];
    const long long o = (long long)r * CATW + threadIdx.x * 4;
    store_hl(Oh + o,     Ol + o,     v.x, v.y);
    store_hl(Oh + o + 2, Ol + o + 2, v.z, v.w);
}

// ---------------- block reductions (blockDim = 256) ----------------
__device__ __forceinline__ float blockMax256(float v, float* red)
{
#pragma unroll
    for (int o = 16; o; o >>= 1) v = fmaxf(v, __shfl_xor_sync(0xffffffffu, v, o));
    if ((threadIdx.x & 31) == 0) red[threadIdx.x >> 5] = v;
    __syncthreads();
    float m = red[0];
#pragma unroll
    for (int i = 1; i < 8; i++) m = fmaxf(m, red[i]);
    return m;
}
__device__ __forceinline__ float blockSum256(float v, float* red)
{
#pragma unroll
    for (int o = 16; o; o >>= 1) v += __shfl_xor_sync(0xffffffffu, v, o);
    if ((threadIdx.x & 31) == 0) red[threadIdx.x >> 5] = v;
    __syncthreads();
    float s = red[0];
#pragma unroll
    for (int i = 1; i < 8; i++) s += red[i];
    return s;
}

__device__ __forceinline__ void store_prob(__nv_bfloat16* Hp, __nv_bfloat16* Lp, float p)
{
    const __nv_bfloat16 h = __float2bfloat16(p);
    *Hp = h;
    *Lp = __float2bfloat16(p - __bfloat162float(h));
}

// self-attention softmax: rel bias, diag=-inf, padded key=-1e9 -> bf16 hi/lo
__global__ void softmax_self_k(const float* __restrict__ S, const int* __restrict__ mask,
                               const float* __restrict__ distW,
                               __nv_bfloat16* __restrict__ Ph, __nv_bfloat16* __restrict__ Pl)
{
    const int q = blockIdx.x, b = blockIdx.y, k = threadIdx.x;
    const long long idx = ((long long)(b * LL + q)) * LL + k;
    __shared__ float red[8];
    __shared__ float dw[23];
    if (k < 23) dw[k] = distW[k];
    const int valid = mask[b * LL + k];
    const float sc = S[idx];
    __syncthreads();

    float v;
    if (!valid)      v = -1e9f;
    else if (k == q) v = __int_as_float(0xff800000);
    else {
        int d = k - q; d = d < -11 ? -11 : (d > 11 ? 11 : d);
        v = sc + dw[d + 11];
    }
    const float m = blockMax256(v, red);
    __syncthreads();
    const float e = expf(v - m);
    const float s = blockSum256(e, red);
    store_prob(Ph + idx, Pl + idx, e / s);
}

// row softmax with key mask -> bf16 hi/lo
__global__ void softmax_rows_k(const float* __restrict__ Z, const int* __restrict__ mask,
                               __nv_bfloat16* __restrict__ Ph, __nv_bfloat16* __restrict__ Pl)
{
    const int q = blockIdx.x, b = blockIdx.y, k = threadIdx.x;
    const long long idx = ((long long)(b * LL + q)) * LL + k;
    __shared__ float red[8];
    const float v = mask[b * LL + k] ? Z[idx] : -1e9f;
    const float m = blockMax256(v, red);
    __syncthreads();
    const float e = expf(v - m);
    const float s = blockSum256(e, red);
    store_prob(Ph + idx, Pl + idx, e / s);
}

// column softmax -> transposed bf16 hi/lo: Out[b,h,p] = softmax_p(Z[b,p,h])
__global__ void softmax_cols_k(const float* __restrict__ Z, const int* __restrict__ maskP,
                               __nv_bfloat16* __restrict__ Ph, __nv_bfloat16* __restrict__ Pl)
{
    const int h = blockIdx.x, b = blockIdx.y, p = threadIdx.x;
    __shared__ float red[8];
    const float v = maskP[b * LL + p]
                  ? Z[((long long)(b * LL + p)) * LL + h] : -1e9f;
    const float m = blockMax256(v, red);
    __syncthreads();
    const float e = expf(v - m);
    const float s = blockSum256(e, red);
    const long long o = ((long long)(b * LL + h)) * LL + p;
    store_prob(Ph + o, Pl + o, e / s);
}

__global__ void masked_sum_k(const float* __restrict__ X, const int* __restrict__ mask,
                             float* __restrict__ out, int off)
{
    const int b = blockIdx.y;
    const int d = blockIdx.x * 128 + threadIdx.x;
    const float* xb = X + (long long)b * LL * DD;
    const int* mb = mask + b * LL;
    float acc = 0.f;
    for (int l = 0; l < LL; l++)
        if (mb[l]) acc += xb[l * DD + d];
    out[b * (2 * DD) + off + d] = acc;
}

__global__ void head_k(const float* __restrict__ aggin,
                       const float* __restrict__ Wg1, const float* __restrict__ bg1,
                       const float* __restrict__ Wg2, const float* __restrict__ bg2,
                       const float* __restrict__ Wo, float* __restrict__ out)
{
    __shared__ float sin[2 * DD];
    __shared__ float h1[DD];
    __shared__ float h2[DD];
    const int b = blockIdx.x, t = threadIdx.x;
    sin[t]       = aggin[b * 2 * DD + t];
    sin[t + DD]  = aggin[b * 2 * DD + DD + t];
    __syncthreads();
    float a = bg1[t];
    for (int k = 0; k < 2 * DD; k++) a = fmaf(sin[k], Wg1[k * DD + t], a);
    h1[t] = relu_(a);
    __syncthreads();
    a = bg2[t];
    for (int k = 0; k < DD; k++) a = fmaf(h1[k], Wg2[k * DD + t], a);
    h2[t] = relu_(a);
    __syncthreads();
    if (t < 3) {
        float s = 0.f;
        for (int k = 0; k < DD; k++) s = fmaf(h2[k], Wo[k * 3 + t], s);
        out[b * 3 + t] = s;
    }
}

// ---------------- host-side dispatch ----------------
static void tcmlp_f32(const __nv_bfloat16* Ah, const __nv_bfloat16* Al, int lda,
                      const __nv_bfloat16* Bh, const __nv_bfloat16* Bl,
                      const float* bias, int K, float* C)
{
    dim3 grid(DD >> 7, MROWS >> 7);
    tcmlp_k<0><<<grid, 256, TC_SMEM_BYTES>>>(Ah, Al, lda, Bh, Bl, bias, K, C,
                                             nullptr, nullptr, DD);
}
static void tcmlp_b16(const __nv_bfloat16* Ah, const __nv_bfloat16* Al, int lda,
                      const __nv_bfloat16* Bh, const __nv_bfloat16* Bl,
                      const float* bias, int K, __nv_bfloat16* Ch, __nv_bfloat16* Cl)
{
    dim3 grid(DD >> 7, MROWS >> 7);
    tcmlp_k<1><<<grid, 256, TC_SMEM_BYTES>>>(Ah, Al, lda, Bh, Bl, bias, K, nullptr,
                                             Ch, Cl, DD);
}
static void tcnt(const __nv_bfloat16* Ah, const __nv_bfloat16* Al,
                 const __nv_bfloat16* Bh, const __nv_bfloat16* Bl, float* C)
{
    tcnt_k<<<dim3(2, 2, BB), 256, TC_SMEM_BYTES>>>(Ah, Al, Bh, Bl, C);
}
static void tcnn(const __nv_bfloat16* Ph, const __nv_bfloat16* Pl,
                 const __nv_bfloat16* Xh, const __nv_bfloat16* Xl, int N,
                 __nv_bfloat16* Ch, __nv_bfloat16* Cl)
{
    tcnn_k<<<dim3(N >> 7, 2, BB), 256, NN_SMEM_BYTES>>>(Ph, Pl, Xh, Xl, CATW, Ch, Cl);
}
static void splitT(const float* W, __nv_bfloat16* Bh, __nv_bfloat16* Bl, int K, int N)
{
    splitT_k<<<dim3(N / 32, K / 32), dim3(32, 32)>>>(W, Bh, Bl, K, N);
}

extern "C" void kernel_launch(void* const* d_in, const int* in_sizes, int n_in,
                              void* d_out, int out_size)
{
    (void)in_sizes; (void)n_in; (void)out_size;
    const int*   prem  = (const int*)  d_in[0];
    const int*   hypo  = (const int*)  d_in[1];
    const float* embW  = (const float*)d_in[2];
    const float* distW = (const float*)d_in[3];
    const float* Ws1 = (const float*)d_in[4];  const float* bs1 = (const float*)d_in[5];
    const float* Ws2 = (const float*)d_in[6];  const float* bs2 = (const float*)d_in[7];
    const float* Wa1 = (const float*)d_in[8];  const float* ba1 = (const float*)d_in[9];
    const float* Wa2 = (const float*)d_in[10]; const float* ba2 = (const float*)d_in[11];
    const float* Wc1 = (const float*)d_in[12]; const float* bc1 = (const float*)d_in[13];
    const float* Wc2 = (const float*)d_in[14]; const float* bc2 = (const float*)d_in[15];
    const float* Wg1 = (const float*)d_in[16]; const float* bg1 = (const float*)d_in[17];
    const float* Wg2 = (const float*)d_in[18]; const float* bg2 = (const float*)d_in[19];
    const float* Wo  = (const float*)d_in[20];
    float* out = (float*)d_out;

    cudaFuncSetAttribute(tcmlp_k<0>, cudaFuncAttributeMaxDynamicSharedMemorySize, TC_SMEM_BYTES);
    cudaFuncSetAttribute(tcmlp_k<1>, cudaFuncAttributeMaxDynamicSharedMemorySize, TC_SMEM_BYTES);
    cudaFuncSetAttribute(tcnt_k, cudaFuncAttributeMaxDynamicSharedMemorySize, TC_SMEM_BYTES);
    cudaFuncSetAttribute(tcnn_k, cudaFuncAttributeMaxDynamicSharedMemorySize, NN_SMEM_BYTES);

    float *pq, *s1, *agg;
    int *mp, *mh;
    __nv_bfloat16 *chp, *clp, *chh, *clh, *hhi, *hlo, *qhi, *qlo, *khi, *klo;
    __nv_bfloat16 *p1h, *p1l, *p2h, *p2l, *w1h, *w1l, *w2h, *w2l;
    cudaGetSymbolAddress((void**)&pq,    g_pq);
    cudaGetSymbolAddress((void**)&s1,    g_s1);
    cudaGetSymbolAddress((void**)&agg,   g_agg);
    cudaGetSymbolAddress((void**)&mp,    g_mask_p);
    cudaGetSymbolAddress((void**)&mh,    g_mask_h);
    cudaGetSymbolAddress((void**)&chp,   g_chp);
    cudaGetSymbolAddress((void**)&clp,   g_clp);
    cudaGetSymbolAddress((void**)&chh,   g_chh);
    cudaGetSymbolAddress((void**)&clh,   g_clh);
    cudaGetSymbolAddress((void**)&hhi,   g_hhi);
    cudaGetSymbolAddress((void**)&hlo,   g_hlo);
    cudaGetSymbolAddress((void**)&qhi,   g_qhi);
    cudaGetSymbolAddress((void**)&qlo,   g_qlo);
    cudaGetSymbolAddress((void**)&khi,   g_khi);
    cudaGetSymbolAddress((void**)&klo,   g_klo);
    cudaGetSymbolAddress((void**)&p1h,   g_p1h);
    cudaGetSymbolAddress((void**)&p1l,   g_p1l);
    cudaGetSymbolAddress((void**)&p2h,   g_p2h);
    cudaGetSymbolAddress((void**)&p2l,   g_p2l);
    cudaGetSymbolAddress((void**)&w1h,   g_w1h);
    cudaGetSymbolAddress((void**)&w1l,   g_w1l);
    cudaGetSymbolAddress((void**)&w2h,   g_w2h);
    cudaGetSymbolAddress((void**)&w2l,   g_w2l);

    // embeddings -> concat cols 0..511 (bf16 hi/lo), masks
    embed_k<<<MROWS, 128>>>(prem, embW, chp, clp, mp);
    embed_k<<<MROWS, 128>>>(hypo, embW, chh, clh, mh);

    // ---- self branch (shared weights) ----
    splitT(Ws1, w1h, w1l, EE, DD);
    splitT(Ws2, w2h, w2l, DD, DD);
    // prem
    tcmlp_b16(chp, clp, CATW, w1h, w1l, bs1, EE, hhi, hlo);
    tcmlp_b16(hhi, hlo, DD,   w2h, w2l, bs2, DD, qhi, qlo);
    tcnt(qhi, qlo, qhi, qlo, s1);
    softmax_self_k<<<dim3(LL, BB), 256>>>(s1, mp, distW, p1h, p1l);
    tcnn(p1h, p1l, chp, clp, EE, chp + EE, clp + EE);          // ctx_prem
    // hypo
    tcmlp_b16(chh, clh, CATW, w1h, w1l, bs1, EE, hhi, hlo);
    tcmlp_b16(hhi, hlo, DD,   w2h, w2l, bs2, DD, qhi, qlo);
    tcnt(qhi, qlo, qhi, qlo, s1);
    softmax_self_k<<<dim3(LL, BB), 256>>>(s1, mh, distW, p1h, p1l);
    tcnn(p1h, p1l, chh, clh, EE, chh + EE, clh + EE);          // ctx_hypo

    // ---- inter attention ----
    splitT(Wa1, w1h, w1l, 2 * EE, DD);
    splitT(Wa2, w2h, w2l, DD, DD);
    tcmlp_b16(chp, clp, CATW, w1h, w1l, ba1, 2 * EE, hhi, hlo);
    tcmlp_b16(hhi, hlo, DD,   w2h, w2l, ba2, DD, qhi, qlo);
    tcmlp_b16(chh, clh, CATW, w1h, w1l, ba1, 2 * EE, hhi, hlo);
    tcmlp_b16(hhi, hlo, DD,   w2h, w2l, ba2, DD, khi, klo);
    tcnt(qhi, qlo, khi, klo, s1);                              // z
    softmax_cols_k<<<dim3(LL, BB), 256>>>(s1, mp, p2h, p2l);   // hypo2prem
    softmax_rows_k<<<dim3(LL, BB), 256>>>(s1, mh, p1h, p1l);   // prem2hypo
    tcnn(p1h, p1l, chh, clh, 2 * EE, chp + 2 * EE, clp + 2 * EE);  // attended_hypo
    tcnn(p2h, p2l, chp, clp, 2 * EE, chh + 2 * EE, clh + 2 * EE);  // attended_prem

    // ---- compare + masked sum ----
    splitT(Wc1, w1h, w1l, 4 * EE, DD);
    splitT(Wc2, w2h, w2l, DD, DD);
    tcmlp_b16(chp, clp, CATW, w1h, w1l, bc1, 4 * EE, hhi, hlo);
    tcmlp_f32(hhi, hlo, DD,   w2h, w2l, bc2, DD, pq);
    masked_sum_k<<<dim3(DD / 128, BB), 128>>>(pq, mp, agg, 0);
    tcmlp_b16(chh, clh, CATW, w1h, w1l, bc1, 4 * EE, hhi, hlo);
    tcmlp_f32(hhi, hlo, DD,   w2h, w2l, bc2, DD, pq);
    masked_sum_k<<<dim3(DD / 128, BB), 128>>>(pq, mh, agg, DD);

    // ---- aggregate MLP + output ----
    head_k<<<BB, DD>>>(agg, Wg1, bg1, Wg2, bg2, Wo, out);
}

// round 16
// speedup vs baseline: 2.2790x; 1.1667x over previous
#include <cuda_runtime.h>
#include <cuda_bf16.h>
#include <cstdint>

// ---------------- problem constants ----------------
#define BB    64
#define LL    256
#define EE    512
#define DD    512
#define MROWS (BB * LL)        // 16384
#define CATW  2048             // [x(512) | ctx(512) | attended(1024)]

// ---------------- scratch (static device globals; no allocations) ----------
__device__ float g_pq [MROWS * DD];
__device__ float g_s1 [BB * LL * LL];
__device__ float g_agg[BB * 2 * DD];
__device__ int   g_mask_p[MROWS];
__device__ int   g_mask_h[MROWS];
// bf16 hi/lo concat buffers (row stride CATW)
__device__ __align__(256) __nv_bfloat16 g_chp[MROWS * CATW];
__device__ __align__(256) __nv_bfloat16 g_clp[MROWS * CATW];
__device__ __align__(256) __nv_bfloat16 g_chh[MROWS * CATW];
__device__ __align__(256) __nv_bfloat16 g_clh[MROWS * CATW];
// packed bf16 hi/lo intermediates
__device__ __align__(256) __nv_bfloat16 g_hhi[MROWS * DD];
__device__ __align__(256) __nv_bfloat16 g_hlo[MROWS * DD];
__device__ __align__(256) __nv_bfloat16 g_qhi[MROWS * DD];
__device__ __align__(256) __nv_bfloat16 g_qlo[MROWS * DD];
__device__ __align__(256) __nv_bfloat16 g_khi[MROWS * DD];
__device__ __align__(256) __nv_bfloat16 g_klo[MROWS * DD];
__device__ __align__(256) __nv_bfloat16 g_p1h[MROWS * LL];
__device__ __align__(256) __nv_bfloat16 g_p1l[MROWS * LL];
__device__ __align__(256) __nv_bfloat16 g_p2h[MROWS * LL];
__device__ __align__(256) __nv_bfloat16 g_p2l[MROWS * LL];
// weight splits [N,K]
__device__ __align__(256) __nv_bfloat16 g_w1h[2048 * DD];
__device__ __align__(256) __nv_bfloat16 g_w1l[2048 * DD];
__device__ __align__(256) __nv_bfloat16 g_w2h[2048 * DD];
__device__ __align__(256) __nv_bfloat16 g_w2l[2048 * DD];

__device__ __forceinline__ float relu_(float x) { return x > 0.f ? x : 0.f; }

// ===================== portable tensor-core helpers (sm_80+ PTX) ============
__device__ __forceinline__ uint32_t smem_u32(const void* p) {
    uint32_t a;
    asm("{ .reg .u64 t; cvta.to.shared.u64 t, %1; cvt.u32.u64 %0, t; }" : "=r"(a) : "l"(p));
    return a;
}
__device__ __forceinline__ void cp16(uint32_t dst, const void* src) {
    asm volatile("cp.async.cg.shared.global [%0], [%1], 16;\n" :: "r"(dst), "l"(src));
}
__device__ __forceinline__ void cp_commit() {
    asm volatile("cp.async.commit_group;\n" ::);
}
template<int N>
__device__ __forceinline__ void cp_wait() {
    asm volatile("cp.async.wait_group %0;\n" :: "n"(N));
}
__device__ __forceinline__ void ldmx4(uint32_t* r, uint32_t addr) {
    asm volatile("ldmatrix.sync.aligned.m8n8.x4.shared.b16 {%0,%1,%2,%3}, [%4];\n"
                 : "=r"(r[0]), "=r"(r[1]), "=r"(r[2]), "=r"(r[3]) : "r"(addr));
}
__device__ __forceinline__ void ldmx4t(uint32_t* r, uint32_t addr) {
    asm volatile("ldmatrix.sync.aligned.m8n8.x4.trans.shared.b16 {%0,%1,%2,%3}, [%4];\n"
                 : "=r"(r[0]), "=r"(r[1]), "=r"(r[2]), "=r"(r[3]) : "r"(addr));
}
__device__ __forceinline__ void mma16816(float* d, const uint32_t* a, const uint32_t* b) {
    asm volatile("mma.sync.aligned.m16n8k16.row.col.f32.bf16.bf16.f32 "
                 "{%0,%1,%2,%3}, {%4,%5,%6,%7}, {%8,%9}, {%0,%1,%2,%3};\n"
                 : "+f"(d[0]), "+f"(d[1]), "+f"(d[2]), "+f"(d[3])
                 : "r"(a[0]), "r"(a[1]), "r"(a[2]), "r"(a[3]), "r"(b[0]), "r"(b[1]));
}

// product-major mma sweep: 16 distinct accumulators before reuse.
#define MMA_SWEEP(AF, BF)                                              \
    _Pragma("unroll")                                                  \
    for (int np = 0; np < 4; np++) {                                   \
        _Pragma("unroll")                                              \
        for (int mt = 0; mt < 2; mt++) {                               \
            mma16816(acc[mt][np * 2 + 0], AF[mt], BF[np] + 0);         \
            mma16816(acc[mt][np * 2 + 1], AF[mt], BF[np] + 2);         \
        }                                                              \
    }

// bf16 hi/lo pair store helper
__device__ __forceinline__ void store_hl(__nv_bfloat16* Hp, __nv_bfloat16* Lp,
                                         float v0, float v1) {
    __nv_bfloat16 h0 = __float2bfloat16(v0), h1 = __float2bfloat16(v1);
    *(__nv_bfloat162*)Hp = __nv_bfloat162(h0, h1);
    *(__nv_bfloat162*)Lp = __nv_bfloat162(__float2bfloat16(v0 - __bfloat162float(h0)),
                                          __float2bfloat16(v1 - __bfloat162float(h1)));
}

// =====================================================================
// split-bf16 MLP GEMM on mma.sync: C = relu(A @ W + bias)
//   A: bf16 hi/lo [M,K] rows stride lda.  W: bf16 hi/lo [N,K] packed.
//   CTA tile 128x128, K-stage 32, cp.async double buffer.
//   __launch_bounds__(256,2): B-frags re-staged per product so live regs
//   fit 128/thread -> 2 CTAs/SM hide syncs + epilogues.
// =====================================================================
#define ST 40                                   // smem row stride (bf16 elems)
#define TILE_ELEMS (128 * ST)
#define TC_SMEM_BYTES (2 * 4 * TILE_ELEMS * 2)  // 81920 B

template<int OUTMODE>
__global__ void __launch_bounds__(256, 2)
tcmlp_k(const __nv_bfloat16* __restrict__ Ah, const __nv_bfloat16* __restrict__ Al,
        int lda,
        const __nv_bfloat16* __restrict__ Bh, const __nv_bfloat16* __restrict__ Bl,
        const float* __restrict__ bias, int K,
        float* __restrict__ Cf,
        __nv_bfloat16* __restrict__ Ch, __nv_bfloat16* __restrict__ Cl, int ldc)
{
    extern __shared__ __nv_bfloat16 sm[];       // [2][4][TILE_ELEMS]
    const int tid = threadIdx.x, lane = tid & 31, wid = tid >> 5;
    const int bm = blockIdx.y << 7, bn = blockIdx.x << 7;
    const int wm = (wid & 3) << 5;
    const int wn = (wid >> 2) << 6;

    const __nv_bfloat16* gA[2] = { Ah + (long long)bm * lda, Al + (long long)bm * lda };
    const __nv_bfloat16* gB[2] = { Bh + (long long)bn * K,   Bl + (long long)bn * K };

    const int lrow0 = tid >> 2;
    const int lh    = (tid & 3) << 3;

    float acc[2][8][4];
#pragma unroll
    for (int mt = 0; mt < 2; mt++)
#pragma unroll
        for (int nt = 0; nt < 8; nt++)
#pragma unroll
            for (int i = 0; i < 4; i++) acc[mt][nt][i] = 0.f;

    const int S = K >> 5;

    auto issue = [&](int s) {
        const int buf = s & 1;
        const int k0 = s << 5;
#pragma unroll
        for (int t = 0; t < 2; t++) {
            const __nv_bfloat16* g = gA[t] + k0 + lh;
            const uint32_t dbase = smem_u32(sm + (buf * 4 + t) * TILE_ELEMS) + lh * 2;
#pragma unroll
            for (int j = 0; j < 2; j++) {
                const int row = lrow0 + j * 64;
                cp16(dbase + row * (ST * 2), g + (long long)row * lda);
            }
        }
#pragma unroll
        for (int t = 0; t < 2; t++) {
            const __nv_bfloat16* g = gB[t] + k0 + lh;
            const uint32_t dbase = smem_u32(sm + (buf * 4 + 2 + t) * TILE_ELEMS) + lh * 2;
#pragma unroll
            for (int j = 0; j < 2; j++) {
                const int row = lrow0 + j * 64;
                cp16(dbase + row * (ST * 2), g + (long long)row * K);
            }
        }
        cp_commit();
    };

    issue(0);
    issue(1);

    for (int s = 0; s < S; s++) {
        if (s + 1 < S) cp_wait<1>(); else cp_wait<0>();
        __syncthreads();

        const uint32_t base = smem_u32(sm + (s & 1) * 4 * TILE_ELEMS);
        const uint32_t sAh = base;
        const uint32_t sAl = base + TILE_ELEMS * 2;
        const uint32_t sBh = base + 2 * TILE_ELEMS * 2;
        const uint32_t sBl = base + 3 * TILE_ELEMS * 2;

#pragma unroll
        for (int kk = 0; kk < 2; kk++) {
            const int ko = kk << 4;
            uint32_t afh[2][4], afl[2][4];
            const int arow  = lane & 15;
            const int akofs = ko + ((lane >> 4) << 3);
#pragma unroll
            for (int mt = 0; mt < 2; mt++) {
                const uint32_t off = (uint32_t)(((wm + mt * 16 + arow) * ST + akofs) * 2);
                ldmx4(afh[mt], sAh + off);
                ldmx4(afl[mt], sAl + off);
            }
            // B frags re-staged per product: only 16 live B regs
            uint32_t bf[4][4];
            const int brow  = ((lane >> 4) << 3) + (lane & 7);
            const int bkofs = ko + (((lane >> 3) & 1) << 3);
#pragma unroll
            for (int np = 0; np < 4; np++)
                ldmx4(bf[np], sBh + (uint32_t)(((wn + np * 16 + brow) * ST + bkofs) * 2));
            MMA_SWEEP(afh, bf);
            MMA_SWEEP(afl, bf);
#pragma unroll
            for (int np = 0; np < 4; np++)
                ldmx4(bf[np], sBl + (uint32_t)(((wn + np * 16 + brow) * ST + bkofs) * 2));
            MMA_SWEEP(afh, bf);
        }
        __syncthreads();
        if (s + 2 < S) issue(s + 2);
    }

    const int er = lane >> 2;
    const int ec = (lane & 3) << 1;
#pragma unroll
    for (int mt = 0; mt < 2; mt++) {
        const int r0 = bm + wm + mt * 16 + er;
#pragma unroll
        for (int nt = 0; nt < 8; nt++) {
            const int col = bn + wn + nt * 8 + ec;
            const float b0 = bias[col], b1 = bias[col + 1];
            const float v00 = relu_(acc[mt][nt][0] + b0);
            const float v01 = relu_(acc[mt][nt][1] + b1);
            const float v10 = relu_(acc[mt][nt][2] + b0);
            const float v11 = relu_(acc[mt][nt][3] + b1);
            if (OUTMODE == 0) {
                *(float2*)(Cf + (long long)r0 * ldc + col)       = make_float2(v00, v01);
                *(float2*)(Cf + (long long)(r0 + 8) * ldc + col) = make_float2(v10, v11);
            } else {
                store_hl(Ch + (long long)r0 * ldc + col,       Cl + (long long)r0 * ldc + col,       v00, v01);
                store_hl(Ch + (long long)(r0 + 8) * ldc + col, Cl + (long long)(r0 + 8) * ldc + col, v10, v11);
            }
        }
    }
}

// =====================================================================
// batched NT scores: S[z] = A[z] @ B[z]^T, fp32 out.  A,B packed [LL,DD].
// =====================================================================
__global__ void __launch_bounds__(256, 2)
tcnt_k(const __nv_bfloat16* __restrict__ Ah, const __nv_bfloat16* __restrict__ Al,
       const __nv_bfloat16* __restrict__ Bh, const __nv_bfloat16* __restrict__ Bl,
       float* __restrict__ C)
{
    extern __shared__ __nv_bfloat16 sm[];
    const int tid = threadIdx.x, lane = tid & 31, wid = tid >> 5;
    const int bm = blockIdx.y << 7, bn = blockIdx.x << 7;
    const long long zq = (long long)blockIdx.z * LL * DD;
    const int wm = (wid & 3) << 5;
    const int wn = (wid >> 2) << 6;

    const __nv_bfloat16* gsrc[4] = {
        Ah + zq + (long long)bm * DD, Al + zq + (long long)bm * DD,
        Bh + zq + (long long)bn * DD, Bl + zq + (long long)bn * DD };

    const int lrow0 = tid >> 2;
    const int lh    = (tid & 3) << 3;

    float acc[2][8][4];
#pragma unroll
    for (int mt = 0; mt < 2; mt++)
#pragma unroll
        for (int nt = 0; nt < 8; nt++)
#pragma unroll
            for (int i = 0; i < 4; i++) acc[mt][nt][i] = 0.f;

    const int S = DD >> 5;

    auto issue = [&](int s) {
        const int buf = s & 1;
        const int k0 = s << 5;
#pragma unroll
        for (int t = 0; t < 4; t++) {
            const __nv_bfloat16* g = gsrc[t] + k0 + lh;
            const uint32_t dbase = smem_u32(sm + (buf * 4 + t) * TILE_ELEMS) + lh * 2;
#pragma unroll
            for (int j = 0; j < 2; j++) {
                const int row = lrow0 + j * 64;
                cp16(dbase + row * (ST * 2), g + (long long)row * DD);
            }
        }
        cp_commit();
    };

    issue(0);
    issue(1);

    for (int s = 0; s < S; s++) {
        if (s + 1 < S) cp_wait<1>(); else cp_wait<0>();
        __syncthreads();

        const uint32_t base = smem_u32(sm + (s & 1) * 4 * TILE_ELEMS);
        const uint32_t sAh = base;
        const uint32_t sAl = base + TILE_ELEMS * 2;
        const uint32_t sBh = base + 2 * TILE_ELEMS * 2;
        const uint32_t sBl = base + 3 * TILE_ELEMS * 2;

#pragma unroll
        for (int kk = 0; kk < 2; kk++) {
            const int ko = kk << 4;
            uint32_t afh[2][4], afl[2][4];
            const int arow  = lane & 15;
            const int akofs = ko + ((lane >> 4) << 3);
#pragma unroll
            for (int mt = 0; mt < 2; mt++) {
                const uint32_t off = (uint32_t)(((wm + mt * 16 + arow) * ST + akofs) * 2);
                ldmx4(afh[mt], sAh + off);
                ldmx4(afl[mt], sAl + off);
            }
            uint32_t bf[4][4];
            const int brow  = ((lane >> 4) << 3) + (lane & 7);
            const int bkofs = ko + (((lane >> 3) & 1) << 3);
#pragma unroll
            for (int np = 0; np < 4; np++)
                ldmx4(bf[np], sBh + (uint32_t)(((wn + np * 16 + brow) * ST + bkofs) * 2));
            MMA_SWEEP(afh, bf);
            MMA_SWEEP(afl, bf);
#pragma unroll
            for (int np = 0; np < 4; np++)
                ldmx4(bf[np], sBl + (uint32_t)(((wn + np * 16 + brow) * ST + bkofs) * 2));
            MMA_SWEEP(afh, bf);
        }
        __syncthreads();
        if (s + 2 < S) issue(s + 2);
    }

    float* Cz = C + (long long)blockIdx.z * LL * LL;
    const int er = lane >> 2;
    const int ec = (lane & 3) << 1;
#pragma unroll
    for (int mt = 0; mt < 2; mt++) {
        const int r0 = bm + wm + mt * 16 + er;
#pragma unroll
        for (int nt = 0; nt < 8; nt++) {
            const int col = bn + wn + nt * 8 + ec;
            *(float2*)(Cz + (long long)r0 * LL + col)       = make_float2(acc[mt][nt][0], acc[mt][nt][1]);
            *(float2*)(Cz + (long long)(r0 + 8) * LL + col) = make_float2(acc[mt][nt][2], acc[mt][nt][3]);
        }
    }
}

// =====================================================================
// batched NN attention-apply: C[z] = P[z] @ X[z], bf16 hi/lo out (stride CATW).
// =====================================================================
#define STN 136
#define BT_ELEMS (32 * STN)
#define NN_STAGE (2 * TILE_ELEMS + 2 * BT_ELEMS)
#define NN_SMEM_BYTES (2 * NN_STAGE * 2)

__global__ void __launch_bounds__(256, 2)
tcnn_k(const __nv_bfloat16* __restrict__ Ph, const __nv_bfloat16* __restrict__ Pl,
       const __nv_bfloat16* __restrict__ Xh, const __nv_bfloat16* __restrict__ Xl,
       int ldx,
       __nv_bfloat16* __restrict__ Ch, __nv_bfloat16* __restrict__ Cl)
{
    extern __shared__ __nv_bfloat16 sm[];
    const int tid = threadIdx.x, lane = tid & 31, wid = tid >> 5;
    const int bm = blockIdx.y << 7, bn = blockIdx.x << 7;
    const int wm = (wid & 3) << 5;
    const int wn = (wid >> 2) << 6;

    const long long zp = (long long)blockIdx.z * LL * LL;
    const long long zx = (long long)blockIdx.z * LL * ldx;
    const __nv_bfloat16* gA[2] = { Ph + zp + (long long)bm * LL,
                                   Pl + zp + (long long)bm * LL };
    const __nv_bfloat16* gX[2] = { Xh + zx + bn, Xl + zx + bn };

    const int arow0 = tid >> 2, ap = (tid & 3) << 3;
    const int brow0 = tid >> 4, bp = (tid & 15) << 3;

    float acc[2][8][4];
#pragma unroll
    for (int mt = 0; mt < 2; mt++)
#pragma unroll
        for (int nt = 0; nt < 8; nt++)
#pragma unroll
            for (int i = 0; i < 4; i++) acc[mt][nt][i] = 0.f;

    const int S = LL >> 5;

    auto issue = [&](int s) {
        const int buf = s & 1;
        const int k0 = s << 5;
        const uint32_t sb = smem_u32(sm + buf * NN_STAGE);
#pragma unroll
        for (int t = 0; t < 2; t++) {
            const __nv_bfloat16* g = gA[t] + k0 + ap;
            const uint32_t dbase = sb + t * (TILE_ELEMS * 2) + ap * 2;
#pragma unroll
            for (int j = 0; j < 2; j++) {
                const int row = arow0 + j * 64;
                cp16(dbase + row * (ST * 2), g + (long long)row * LL);
            }
        }
#pragma unroll
        for (int t = 0; t < 2; t++) {
            const __nv_bfloat16* g = gX[t] + bp;
            const uint32_t dbase = sb + (2 * TILE_ELEMS + t * BT_ELEMS) * 2 + bp * 2;
#pragma unroll
            for (int j = 0; j < 2; j++) {
                const int row = brow0 + j * 16;
                cp16(dbase + row * (STN * 2), g + (long long)(k0 + row) * ldx);
            }
        }
        cp_commit();
    };

    issue(0);
    issue(1);

    for (int s = 0; s < S; s++) {
        if (s + 1 < S) cp_wait<1>(); else cp_wait<0>();
        __syncthreads();

        const uint32_t base = smem_u32(sm + (s & 1) * NN_STAGE);
        const uint32_t sAh = base;
        const uint32_t sAl = base + TILE_ELEMS * 2;
        const uint32_t sBh = base + 2 * TILE_ELEMS * 2;
        const uint32_t sBl = sBh + BT_ELEMS * 2;

#pragma unroll
        for (int kk = 0; kk < 2; kk++) {
            const int ko = kk << 4;
            uint32_t afh[2][4], afl[2][4];
            const int arow  = lane & 15;
            const int akofs = ko + ((lane >> 4) << 3);
#pragma unroll
            for (int mt = 0; mt < 2; mt++) {
                const uint32_t off = (uint32_t)(((wm + mt * 16 + arow) * ST + akofs) * 2);
                ldmx4(afh[mt], sAh + off);
                ldmx4(afl[mt], sAl + off);
            }
            uint32_t bf[4][4];
            const int krow = ko + (((lane >> 3) & 1) << 3) + (lane & 7);
            const int ncol = (lane >> 4) << 3;
#pragma unroll
            for (int np = 0; np < 4; np++)
                ldmx4t(bf[np], sBh + (uint32_t)((krow * STN + wn + np * 16 + ncol) * 2));
            MMA_SWEEP(afh, bf);
            MMA_SWEEP(afl, bf);
#pragma unroll
            for (int np = 0; np < 4; np++)
                ldmx4t(bf[np], sBl + (uint32_t)((krow * STN + wn + np * 16 + ncol) * 2));
            MMA_SWEEP(afh, bf);
        }
        __syncthreads();
        if (s + 2 < S) issue(s + 2);
    }

    __nv_bfloat16* Chz = Ch + (long long)blockIdx.z * LL * CATW;
    __nv_bfloat16* Clz = Cl + (long long)blockIdx.z * LL * CATW;
    const int er = lane >> 2;
    const int ec = (lane & 3) << 1;
#pragma unroll
    for (int mt = 0; mt < 2; mt++) {
        const int r0 = bm + wm + mt * 16 + er;
#pragma unroll
        for (int nt = 0; nt < 8; nt++) {
            const int col = bn + wn + nt * 8 + ec;
            store_hl(Chz + (long long)r0 * CATW + col,       Clz + (long long)r0 * CATW + col,
                     acc[mt][nt][0], acc[mt][nt][1]);
            store_hl(Chz + (long long)(r0 + 8) * CATW + col, Clz + (long long)(r0 + 8) * CATW + col,
                     acc[mt][nt][2], acc[mt][nt][3]);
        }
    }
}

// ---- transpose + split weight: W[K,N] fp32 -> Bh/Bl [N,K] bf16 ----
__global__ void splitT_k(const float* __restrict__ W,
                         __nv_bfloat16* __restrict__ Bh, __nv_bfloat16* __restrict__ Bl,
                         int K, int N)
{
    __shared__ float t[32][33];
    const int n0 = blockIdx.x * 32, k0 = blockIdx.y * 32;
    const int tx = threadIdx.x, ty = threadIdx.y;
    t[ty][tx] = W[(long long)(k0 + ty) * N + n0 + tx];
    __syncthreads();
    const float v = t[tx][ty];
    const __nv_bfloat16 h = __float2bfloat16(v);
    const long long o = (long long)(n0 + ty) * K + k0 + tx;
    Bh[o] = h;
    Bl[o] = __float2bfloat16(v - __bfloat162float(h));
}

// ---- embedding gather -> bf16 hi/lo concat cols 0..511, + mask ----
__global__ void embed_k(const int* __restrict__ tok, const float* __restrict__ W,
                        __nv_bfloat16* __restrict__ Oh, __nv_bfloat16* __restrict__ Ol,
                        int* __restrict__ mask)
{
    const int r = blockIdx.x;
    const int t = tok[r];
    if (threadIdx.x == 0) mask[r] = (t != 0);
    const float4 v = ((const float4*)(W + (long long)t * EE))[threadIdx.x];
    const long long o = (long long)r * CATW + threadIdx.x * 4;
    store_hl(Oh + o,     Ol + o,     v.x, v.y);
    store_hl(Oh + o + 2, Ol + o + 2, v.z, v.w);
}

// ---------------- block reductions (blockDim = 256) ----------------
__device__ __forceinline__ float blockMax256(float v, float* red)
{
#pragma unroll
    for (int o = 16; o; o >>= 1) v = fmaxf(v, __shfl_xor_sync(0xffffffffu, v, o));
    if ((threadIdx.x & 31) == 0) red[threadIdx.x >> 5] = v;
    __syncthreads();
    float m = red[0];
#pragma unroll
    for (int i = 1; i < 8; i++) m = fmaxf(m, red[i]);
    return m;
}
__device__ __forceinline__ float blockSum256(float v, float* red)
{
#pragma unroll
    for (int o = 16; o; o >>= 1) v += __shfl_xor_sync(0xffffffffu, v, o);
    if ((threadIdx.x & 31) == 0) red[threadIdx.x >> 5] = v;
    __syncthreads();
    float s = red[0];
#pragma unroll
    for (int i = 1; i < 8; i++) s += red[i];
    return s;
}

__device__ __forceinline__ void store_prob(__nv_bfloat16* Hp, __nv_bfloat16* Lp, float p)
{
    const __nv_bfloat16 h = __float2bfloat16(p);
    *Hp = h;
    *Lp = __float2bfloat16(p - __bfloat162float(h));
}

// self-attention softmax: rel bias, diag=-inf, padded key=-1e9 -> bf16 hi/lo
__global__ void softmax_self_k(const float* __restrict__ S, const int* __restrict__ mask,
                               const float* __restrict__ distW,
                               __nv_bfloat16* __restrict__ Ph, __nv_bfloat16* __restrict__ Pl)
{
    const int q = blockIdx.x, b = blockIdx.y, k = threadIdx.x;
    const long long idx = ((long long)(b * LL + q)) * LL + k;
    __shared__ float red[8];
    __shared__ float dw[23];
    if (k < 23) dw[k] = distW[k];
    const int valid = mask[b * LL + k];
    const float sc = S[idx];
    __syncthreads();

    float v;
    if (!valid)      v = -1e9f;
    else if (k == q) v = __int_as_float(0xff800000);
    else {
        int d = k - q; d = d < -11 ? -11 : (d > 11 ? 11 : d);
        v = sc + dw[d + 11];
    }
    const float m = blockMax256(v, red);
    __syncthreads();
    const float e = expf(v - m);
    const float s = blockSum256(e, red);
    store_prob(Ph + idx, Pl + idx, e / s);
}

// row softmax with key mask -> bf16 hi/lo
__global__ void softmax_rows_k(const float* __restrict__ Z, const int* __restrict__ mask,
                               __nv_bfloat16* __restrict__ Ph, __nv_bfloat16* __restrict__ Pl)
{
    const int q = blockIdx.x, b = blockIdx.y, k = threadIdx.x;
    const long long idx = ((long long)(b * LL + q)) * LL + k;
    __shared__ float red[8];
    const float v = mask[b * LL + k] ? Z[idx] : -1e9f;
    const float m = blockMax256(v, red);
    __syncthreads();
    const float e = expf(v - m);
    const float s = blockSum256(e, red);
    store_prob(Ph + idx, Pl + idx, e / s);
}

// column softmax -> transposed bf16 hi/lo: Out[b,h,p] = softmax_p(Z[b,p,h])
__global__ void softmax_cols_k(const float* __restrict__ Z, const int* __restrict__ maskP,
                               __nv_bfloat16* __restrict__ Ph, __nv_bfloat16* __restrict__ Pl)
{
    const int h = blockIdx.x, b = blockIdx.y, p = threadIdx.x;
    __shared__ float red[8];
    const float v = maskP[b * LL + p]
                  ? Z[((long long)(b * LL + p)) * LL + h] : -1e9f;
    const float m = blockMax256(v, red);
    __syncthreads();
    const float e = expf(v - m);
    const float s = blockSum256(e, red);
    const long long o = ((long long)(b * LL + h)) * LL + p;
    store_prob(Ph + o, Pl + o, e / s);
}

__global__ void masked_sum_k(const float* __restrict__ X, const int* __restrict__ mask,
                             float* __restrict__ out, int off)
{
    const int b = blockIdx.y;
    const int d = blockIdx.x * 128 + threadIdx.x;
    const float* xb = X + (long long)b * LL * DD;
    const int* mb = mask + b * LL;
    float acc = 0.f;
    for (int l = 0; l < LL; l++)
        if (mb[l]) acc += xb[l * DD + d];
    out[b * (2 * DD) + off + d] = acc;
}

__global__ void head_k(const float* __restrict__ aggin,
                       const float* __restrict__ Wg1, const float* __restrict__ bg1,
                       const float* __restrict__ Wg2, const float* __restrict__ bg2,
                       const float* __restrict__ Wo, float* __restrict__ out)
{
    __shared__ float sin[2 * DD];
    __shared__ float h1[DD];
    __shared__ float h2[DD];
    const int b = blockIdx.x, t = threadIdx.x;
    sin[t]       = aggin[b * 2 * DD + t];
    sin[t + DD]  = aggin[b * 2 * DD + DD + t];
    __syncthreads();
    float a = bg1[t];
    for (int k = 0; k < 2 * DD; k++) a = fmaf(sin[k], Wg1[k * DD + t], a);
    h1[t] = relu_(a);
    __syncthreads();
    a = bg2[t];
    for (int k = 0; k < DD; k++) a = fmaf(h1[k], Wg2[k * DD + t], a);
    h2[t] = relu_(a);
    __syncthreads();
    if (t < 3) {
        float s = 0.f;
        for (int k = 0; k < DD; k++) s = fmaf(h2[k], Wo[k * 3 + t], s);
        out[b * 3 + t] = s;
    }
}

// ---------------- host-side dispatch ----------------
static void tcmlp_f32(const __nv_bfloat16* Ah, const __nv_bfloat16* Al, int lda,
                      const __nv_bfloat16* Bh, const __nv_bfloat16* Bl,
                      const float* bias, int K, float* C)
{
    dim3 grid(DD >> 7, MROWS >> 7);
    tcmlp_k<0><<<grid, 256, TC_SMEM_BYTES>>>(Ah, Al, lda, Bh, Bl, bias, K, C,
                                             nullptr, nullptr, DD);
}
static void tcmlp_b16(const __nv_bfloat16* Ah, const __nv_bfloat16* Al, int lda,
                      const __nv_bfloat16* Bh, const __nv_bfloat16* Bl,
                      const float* bias, int K, __nv_bfloat16* Ch, __nv_bfloat16* Cl)
{
    dim3 grid(DD >> 7, MROWS >> 7);
    tcmlp_k<1><<<grid, 256, TC_SMEM_BYTES>>>(Ah, Al, lda, Bh, Bl, bias, K, nullptr,
                                             Ch, Cl, DD);
}
static void tcnt(const __nv_bfloat16* Ah, const __nv_bfloat16* Al,
                 const __nv_bfloat16* Bh, const __nv_bfloat16* Bl, float* C)
{
    tcnt_k<<<dim3(2, 2, BB), 256, TC_SMEM_BYTES>>>(Ah, Al, Bh, Bl, C);
}
static void tcnn(const __nv_bfloat16* Ph, const __nv_bfloat16* Pl,
                 const __nv_bfloat16* Xh, const __nv_bfloat16* Xl, int N,
                 __nv_bfloat16* Ch, __nv_bfloat16* Cl)
{
    tcnn_k<<<dim3(N >> 7, 2, BB), 256, NN_SMEM_BYTES>>>(Ph, Pl, Xh, Xl, CATW, Ch, Cl);
}
static void splitT(const float* W, __nv_bfloat16* Bh, __nv_bfloat16* Bl, int K, int N)
{
    splitT_k<<<dim3(N / 32, K / 32), dim3(32, 32)>>>(W, Bh, Bl, K, N);
}

extern "C" void kernel_launch(void* const* d_in, const int* in_sizes, int n_in,
                              void* d_out, int out_size)
{
    (void)in_sizes; (void)n_in; (void)out_size;
    const int*   prem  = (const int*)  d_in[0];
    const int*   hypo  = (const int*)  d_in[1];
    const float* embW  = (const float*)d_in[2];
    const float* distW = (const float*)d_in[3];
    const float* Ws1 = (const float*)d_in[4];  const float* bs1 = (const float*)d_in[5];
    const float* Ws2 = (const float*)d_in[6];  const float* bs2 = (const float*)d_in[7];
    const float* Wa1 = (const float*)d_in[8];  const float* ba1 = (const float*)d_in[9];
    const float* Wa2 = (const float*)d_in[10]; const float* ba2 = (const float*)d_in[11];
    const float* Wc1 = (const float*)d_in[12]; const float* bc1 = (const float*)d_in[13];
    const float* Wc2 = (const float*)d_in[14]; const float* bc2 = (const float*)d_in[15];
    const float* Wg1 = (const float*)d_in[16]; const float* bg1 = (const float*)d_in[17];
    const float* Wg2 = (const float*)d_in[18]; const float* bg2 = (const float*)d_in[19];
    const float* Wo  = (const float*)d_in[20];
    float* out = (float*)d_out;

    cudaFuncSetAttribute(tcmlp_k<0>, cudaFuncAttributeMaxDynamicSharedMemorySize, TC_SMEM_BYTES);
    cudaFuncSetAttribute(tcmlp_k<1>, cudaFuncAttributeMaxDynamicSharedMemorySize, TC_SMEM_BYTES);
    cudaFuncSetAttribute(tcnt_k, cudaFuncAttributeMaxDynamicSharedMemorySize, TC_SMEM_BYTES);
    cudaFuncSetAttribute(tcnn_k, cudaFuncAttributeMaxDynamicSharedMemorySize, NN_SMEM_BYTES);

    float *pq, *s1, *agg;
    int *mp, *mh;
    __nv_bfloat16 *chp, *clp, *chh, *clh, *hhi, *hlo, *qhi, *qlo, *khi, *klo;
    __nv_bfloat16 *p1h, *p1l, *p2h, *p2l, *w1h, *w1l, *w2h, *w2l;
    cudaGetSymbolAddress((void**)&pq,    g_pq);
    cudaGetSymbolAddress((void**)&s1,    g_s1);
    cudaGetSymbolAddress((void**)&agg,   g_agg);
    cudaGetSymbolAddress((void**)&mp,    g_mask_p);
    cudaGetSymbolAddress((void**)&mh,    g_mask_h);
    cudaGetSymbolAddress((void**)&chp,   g_chp);
    cudaGetSymbolAddress((void**)&clp,   g_clp);
    cudaGetSymbolAddress((void**)&chh,   g_chh);
    cudaGetSymbolAddress((void**)&clh,   g_clh);
    cudaGetSymbolAddress((void**)&hhi,   g_hhi);
    cudaGetSymbolAddress((void**)&hlo,   g_hlo);
    cudaGetSymbolAddress((void**)&qhi,   g_qhi);
    cudaGetSymbolAddress((void**)&qlo,   g_qlo);
    cudaGetSymbolAddress((void**)&khi,   g_khi);
    cudaGetSymbolAddress((void**)&klo,   g_klo);
    cudaGetSymbolAddress((void**)&p1h,   g_p1h);
    cudaGetSymbolAddress((void**)&p1l,   g_p1l);
    cudaGetSymbolAddress((void**)&p2h,   g_p2h);
    cudaGetSymbolAddress((void**)&p2l,   g_p2l);
    cudaGetSymbolAddress((void**)&w1h,   g_w1h);
    cudaGetSymbolAddress((void**)&w1l,   g_w1l);
    cudaGetSymbolAddress((void**)&w2h,   g_w2h);
    cudaGetSymbolAddress((void**)&w2l,   g_w2l);

    // embeddings -> concat cols 0..511 (bf16 hi/lo), masks
    embed_k<<<MROWS, 128>>>(prem, embW, chp, clp, mp);
    embed_k<<<MROWS, 128>>>(hypo, embW, chh, clh, mh);

    // ---- self branch (shared weights) ----
    splitT(Ws1, w1h, w1l, EE, DD);
    splitT(Ws2, w2h, w2l, DD, DD);
    // prem
    tcmlp_b16(chp, clp, CATW, w1h, w1l, bs1, EE, hhi, hlo);
    tcmlp_b16(hhi, hlo, DD,   w2h, w2l, bs2, DD, qhi, qlo);
    tcnt(qhi, qlo, qhi, qlo, s1);
    softmax_self_k<<<dim3(LL, BB), 256>>>(s1, mp, distW, p1h, p1l);
    tcnn(p1h, p1l, chp, clp, EE, chp + EE, clp + EE);          // ctx_prem
    // hypo
    tcmlp_b16(chh, clh, CATW, w1h, w1l, bs1, EE, hhi, hlo);
    tcmlp_b16(hhi, hlo, DD,   w2h, w2l, bs2, DD, qhi, qlo);
    tcnt(qhi, qlo, qhi, qlo, s1);
    softmax_self_k<<<dim3(LL, BB), 256>>>(s1, mh, distW, p1h, p1l);
    tcnn(p1h, p1l, chh, clh, EE, chh + EE, clh + EE);          // ctx_hypo

    // ---- inter attention ----
    splitT(Wa1, w1h, w1l, 2 * EE, DD);
    splitT(Wa2, w2h, w2l, DD, DD);
    tcmlp_b16(chp, clp, CATW, w1h, w1l, ba1, 2 * EE, hhi, hlo);
    tcmlp_b16(hhi, hlo, DD,   w2h, w2l, ba2, DD, qhi, qlo);
    tcmlp_b16(chh, clh, CATW, w1h, w1l, ba1, 2 * EE, hhi, hlo);
    tcmlp_b16(hhi, hlo, DD,   w2h, w2l, ba2, DD, khi, klo);
    tcnt(qhi, qlo, khi, klo, s1);                              // z
    softmax_cols_k<<<dim3(LL, BB), 256>>>(s1, mp, p2h, p2l);   // hypo2prem
    softmax_rows_k<<<dim3(LL, BB), 256>>>(s1, mh, p1h, p1l);   // prem2hypo
    tcnn(p1h, p1l, chh, clh, 2 * EE, chp + 2 * EE, clp + 2 * EE);  // attended_hypo
    tcnn(p2h, p2l, chp, clp, 2 * EE, chh + 2 * EE, clh + 2 * EE);  // attended_prem

    // ---- compare + masked sum ----
    splitT(Wc1, w1h, w1l, 4 * EE, DD);
    splitT(Wc2, w2h, w2l, DD, DD);
    tcmlp_b16(chp, clp, CATW, w1h, w1l, bc1, 4 * EE, hhi, hlo);
    tcmlp_f32(hhi, hlo, DD,   w2h, w2l, bc2, DD, pq);
    masked_sum_k<<<dim3(DD / 128, BB), 128>>>(pq, mp, agg, 0);
    tcmlp_b16(chh, clh, CATW, w1h, w1l, bc1, 4 * EE, hhi, hlo);
    tcmlp_f32(hhi, hlo, DD,   w2h, w2l, bc2, DD, pq);
    masked_sum_k<<<dim3(DD / 128, BB), 128>>>(pq, mh, agg, DD);

    // ---- aggregate MLP + output ----
    head_k<<<BB, DD>>>(agg, Wg1, bg1, Wg2, bg2, Wo, out);
}

// round 17
// speedup vs baseline: 2.2845x; 1.0024x over previous
#include <cuda_runtime.h>
#include <cuda_bf16.h>
#include <cstdint>

// ---------------- problem constants ----------------
#define BB    64
#define LL    256
#define EE    512
#define DD    512
#define MROWS (BB * LL)        // 16384
#define CATW  2048             // [x(512) | ctx(512) | attended(1024)]

// ---------------- scratch (static device globals; no allocations) ----------
__device__ float g_pq [MROWS * DD];
__device__ float g_s1 [BB * LL * LL];
__device__ float g_agg[BB * 2 * DD];
__device__ int   g_mask_p[MROWS];
__device__ int   g_mask_h[MROWS];
// bf16 hi/lo concat buffers (row stride CATW)
__device__ __align__(256) __nv_bfloat16 g_chp[MROWS * CATW];
__device__ __align__(256) __nv_bfloat16 g_clp[MROWS * CATW];
__device__ __align__(256) __nv_bfloat16 g_chh[MROWS * CATW];
__device__ __align__(256) __nv_bfloat16 g_clh[MROWS * CATW];
// packed bf16 hi/lo intermediates
__device__ __align__(256) __nv_bfloat16 g_hhi[MROWS * DD];
__device__ __align__(256) __nv_bfloat16 g_hlo[MROWS * DD];
__device__ __align__(256) __nv_bfloat16 g_qhi[MROWS * DD];
__device__ __align__(256) __nv_bfloat16 g_qlo[MROWS * DD];
__device__ __align__(256) __nv_bfloat16 g_khi[MROWS * DD];
__device__ __align__(256) __nv_bfloat16 g_klo[MROWS * DD];
__device__ __align__(256) __nv_bfloat16 g_p1h[MROWS * LL];
__device__ __align__(256) __nv_bfloat16 g_p1l[MROWS * LL];
__device__ __align__(256) __nv_bfloat16 g_p2h[MROWS * LL];
__device__ __align__(256) __nv_bfloat16 g_p2l[MROWS * LL];
// weight splits [N,K]
__device__ __align__(256) __nv_bfloat16 g_w1h[2048 * DD];
__device__ __align__(256) __nv_bfloat16 g_w1l[2048 * DD];
__device__ __align__(256) __nv_bfloat16 g_w2h[2048 * DD];
__device__ __align__(256) __nv_bfloat16 g_w2l[2048 * DD];

__device__ __forceinline__ float relu_(float x) { return x > 0.f ? x : 0.f; }

// ===================== portable tensor-core helpers (sm_80+ PTX) ============
__device__ __forceinline__ uint32_t smem_u32(const void* p) {
    uint32_t a;
    asm("{ .reg .u64 t; cvta.to.shared.u64 t, %1; cvt.u32.u64 %0, t; }" : "=r"(a) : "l"(p));
    return a;
}
__device__ __forceinline__ void cp16(uint32_t dst, const void* src) {
    asm volatile("cp.async.cg.shared.global [%0], [%1], 16;\n" :: "r"(dst), "l"(src));
}
__device__ __forceinline__ void cp_commit() {
    asm volatile("cp.async.commit_group;\n" ::);
}
template<int N>
__device__ __forceinline__ void cp_wait() {
    asm volatile("cp.async.wait_group %0;\n" :: "n"(N));
}
__device__ __forceinline__ void ldmx4(uint32_t* r, uint32_t addr) {
    asm volatile("ldmatrix.sync.aligned.m8n8.x4.shared.b16 {%0,%1,%2,%3}, [%4];\n"
                 : "=r"(r[0]), "=r"(r[1]), "=r"(r[2]), "=r"(r[3]) : "r"(addr));
}
__device__ __forceinline__ void ldmx4t(uint32_t* r, uint32_t addr) {
    asm volatile("ldmatrix.sync.aligned.m8n8.x4.trans.shared.b16 {%0,%1,%2,%3}, [%4];\n"
                 : "=r"(r[0]), "=r"(r[1]), "=r"(r[2]), "=r"(r[3]) : "r"(addr));
}
__device__ __forceinline__ void mma16816(float* d, const uint32_t* a, const uint32_t* b) {
    asm volatile("mma.sync.aligned.m16n8k16.row.col.f32.bf16.bf16.f32 "
                 "{%0,%1,%2,%3}, {%4,%5,%6,%7}, {%8,%9}, {%0,%1,%2,%3};\n"
                 : "+f"(d[0]), "+f"(d[1]), "+f"(d[2]), "+f"(d[3])
                 : "r"(a[0]), "r"(a[1]), "r"(a[2]), "r"(a[3]), "r"(b[0]), "r"(b[1]));
}

// product-major mma sweep: 16 distinct accumulators before reuse.
#define MMA_SWEEP(AF, BF)                                              \
    _Pragma("unroll")                                                  \
    for (int np = 0; np < 4; np++) {                                   \
        _Pragma("unroll")                                              \
        for (int mt = 0; mt < 2; mt++) {                               \
            mma16816(acc[mt][np * 2 + 0], AF[mt], BF[np] + 0);         \
            mma16816(acc[mt][np * 2 + 1], AF[mt], BF[np] + 2);         \
        }                                                              \
    }

// bf16 hi/lo pair store helper
__device__ __forceinline__ void store_hl(__nv_bfloat16* Hp, __nv_bfloat16* Lp,
                                         float v0, float v1) {
    __nv_bfloat16 h0 = __float2bfloat16(v0), h1 = __float2bfloat16(v1);
    *(__nv_bfloat162*)Hp = __nv_bfloat162(h0, h1);
    *(__nv_bfloat162*)Lp = __nv_bfloat162(__float2bfloat16(v0 - __bfloat162float(h0)),
                                          __float2bfloat16(v1 - __bfloat162float(h1)));
}

// =====================================================================
// split-bf16 MLP GEMM on mma.sync: C = relu(A @ W + bias)
//   A: bf16 hi/lo [M,K] rows stride lda.  W: bf16 hi/lo [N,K] packed.
//   CTA tile 128x128, K-stage 32, cp.async double buffer.
//   __launch_bounds__(256,2): B-frags re-staged per product so live regs
//   fit 128/thread -> 2 CTAs/SM hide syncs + epilogues.
// =====================================================================
#define ST 40                                   // smem row stride (bf16 elems)
#define TILE_ELEMS (128 * ST)
#define TC_SMEM_BYTES (2 * 4 * TILE_ELEMS * 2)  // 81920 B

template<int OUTMODE>
__global__ void __launch_bounds__(256, 2)
tcmlp_k(const __nv_bfloat16* __restrict__ Ah, const __nv_bfloat16* __restrict__ Al,
        int lda,
        const __nv_bfloat16* __restrict__ Bh, const __nv_bfloat16* __restrict__ Bl,
        const float* __restrict__ bias, int K,
        float* __restrict__ Cf,
        __nv_bfloat16* __restrict__ Ch, __nv_bfloat16* __restrict__ Cl, int ldc)
{
    extern __shared__ __nv_bfloat16 sm[];       // [2][4][TILE_ELEMS]
    const int tid = threadIdx.x, lane = tid & 31, wid = tid >> 5;
    const int bm = blockIdx.y << 7, bn = blockIdx.x << 7;
    const int wm = (wid & 3) << 5;
    const int wn = (wid >> 2) << 6;

    const __nv_bfloat16* gA[2] = { Ah + (long long)bm * lda, Al + (long long)bm * lda };
    const __nv_bfloat16* gB[2] = { Bh + (long long)bn * K,   Bl + (long long)bn * K };

    const int lrow0 = tid >> 2;
    const int lh    = (tid & 3) << 3;

    float acc[2][8][4];
#pragma unroll
    for (int mt = 0; mt < 2; mt++)
#pragma unroll
        for (int nt = 0; nt < 8; nt++)
#pragma unroll
            for (int i = 0; i < 4; i++) acc[mt][nt][i] = 0.f;

    const int S = K >> 5;

    auto issue = [&](int s) {
        const int buf = s & 1;
        const int k0 = s << 5;
#pragma unroll
        for (int t = 0; t < 2; t++) {
            const __nv_bfloat16* g = gA[t] + k0 + lh;
            const uint32_t dbase = smem_u32(sm + (buf * 4 + t) * TILE_ELEMS) + lh * 2;
#pragma unroll
            for (int j = 0; j < 2; j++) {
                const int row = lrow0 + j * 64;
                cp16(dbase + row * (ST * 2), g + (long long)row * lda);
            }
        }
#pragma unroll
        for (int t = 0; t < 2; t++) {
            const __nv_bfloat16* g = gB[t] + k0 + lh;
            const uint32_t dbase = smem_u32(sm + (buf * 4 + 2 + t) * TILE_ELEMS) + lh * 2;
#pragma unroll
            for (int j = 0; j < 2; j++) {
                const int row = lrow0 + j * 64;
                cp16(dbase + row * (ST * 2), g + (long long)row * K);
            }
        }
        cp_commit();
    };

    issue(0);
    issue(1);

    for (int s = 0; s < S; s++) {
        if (s + 1 < S) cp_wait<1>(); else cp_wait<0>();
        __syncthreads();

        const uint32_t base = smem_u32(sm + (s & 1) * 4 * TILE_ELEMS);
        const uint32_t sAh = base;
        const uint32_t sAl = base + TILE_ELEMS * 2;
        const uint32_t sBh = base + 2 * TILE_ELEMS * 2;
        const uint32_t sBl = base + 3 * TILE_ELEMS * 2;

#pragma unroll
        for (int kk = 0; kk < 2; kk++) {
            const int ko = kk << 4;
            uint32_t afh[2][4], afl[2][4];
            const int arow  = lane & 15;
            const int akofs = ko + ((lane >> 4) << 3);
#pragma unroll
            for (int mt = 0; mt < 2; mt++) {
                const uint32_t off = (uint32_t)(((wm + mt * 16 + arow) * ST + akofs) * 2);
                ldmx4(afh[mt], sAh + off);
                ldmx4(afl[mt], sAl + off);
            }
            // B frags re-staged per product: only 16 live B regs
            uint32_t bf[4][4];
            const int brow  = ((lane >> 4) << 3) + (lane & 7);
            const int bkofs = ko + (((lane >> 3) & 1) << 3);
#pragma unroll
            for (int np = 0; np < 4; np++)
                ldmx4(bf[np], sBh + (uint32_t)(((wn + np * 16 + brow) * ST + bkofs) * 2));
            MMA_SWEEP(afh, bf);
            MMA_SWEEP(afl, bf);
#pragma unroll
            for (int np = 0; np < 4; np++)
                ldmx4(bf[np], sBl + (uint32_t)(((wn + np * 16 + brow) * ST + bkofs) * 2));
            MMA_SWEEP(afh, bf);
        }
        __syncthreads();
        if (s + 2 < S) issue(s + 2);
    }

    const int er = lane >> 2;
    const int ec = (lane & 3) << 1;
#pragma unroll
    for (int mt = 0; mt < 2; mt++) {
        const int r0 = bm + wm + mt * 16 + er;
#pragma unroll
        for (int nt = 0; nt < 8; nt++) {
            const int col = bn + wn + nt * 8 + ec;
            const float b0 = bias[col], b1 = bias[col + 1];
            const float v00 = relu_(acc[mt][nt][0] + b0);
            const float v01 = relu_(acc[mt][nt][1] + b1);
            const float v10 = relu_(acc[mt][nt][2] + b0);
            const float v11 = relu_(acc[mt][nt][3] + b1);
            if (OUTMODE == 0) {
                *(float2*)(Cf + (long long)r0 * ldc + col)       = make_float2(v00, v01);
                *(float2*)(Cf + (long long)(r0 + 8) * ldc + col) = make_float2(v10, v11);
            } else {
                store_hl(Ch + (long long)r0 * ldc + col,       Cl + (long long)r0 * ldc + col,       v00, v01);
                store_hl(Ch + (long long)(r0 + 8) * ldc + col, Cl + (long long)(r0 + 8) * ldc + col, v10, v11);
            }
        }
    }
}

// =====================================================================
// batched NT scores: S[z] = A[z] @ B[z]^T, fp32 out.  A,B packed [LL,DD].
// =====================================================================
__global__ void __launch_bounds__(256, 2)
tcnt_k(const __nv_bfloat16* __restrict__ Ah, const __nv_bfloat16* __restrict__ Al,
       const __nv_bfloat16* __restrict__ Bh, const __nv_bfloat16* __restrict__ Bl,
       float* __restrict__ C)
{
    extern __shared__ __nv_bfloat16 sm[];
    const int tid = threadIdx.x, lane = tid & 31, wid = tid >> 5;
    const int bm = blockIdx.y << 7, bn = blockIdx.x << 7;
    const long long zq = (long long)blockIdx.z * LL * DD;
    const int wm = (wid & 3) << 5;
    const int wn = (wid >> 2) << 6;

    const __nv_bfloat16* gsrc[4] = {
        Ah + zq + (long long)bm * DD, Al + zq + (long long)bm * DD,
        Bh + zq + (long long)bn * DD, Bl + zq + (long long)bn * DD };

    const int lrow0 = tid >> 2;
    const int lh    = (tid & 3) << 3;

    float acc[2][8][4];
#pragma unroll
    for (int mt = 0; mt < 2; mt++)
#pragma unroll
        for (int nt = 0; nt < 8; nt++)
#pragma unroll
            for (int i = 0; i < 4; i++) acc[mt][nt][i] = 0.f;

    const int S = DD >> 5;

    auto issue = [&](int s) {
        const int buf = s & 1;
        const int k0 = s << 5;
#pragma unroll
        for (int t = 0; t < 4; t++) {
            const __nv_bfloat16* g = gsrc[t] + k0 + lh;
            const uint32_t dbase = smem_u32(sm + (buf * 4 + t) * TILE_ELEMS) + lh * 2;
#pragma unroll
            for (int j = 0; j < 2; j++) {
                const int row = lrow0 + j * 64;
                cp16(dbase + row * (ST * 2), g + (long long)row * DD);
            }
        }
        cp_commit();
    };

    issue(0);
    issue(1);

    for (int s = 0; s < S; s++) {
        if (s + 1 < S) cp_wait<1>(); else cp_wait<0>();
        __syncthreads();

        const uint32_t base = smem_u32(sm + (s & 1) * 4 * TILE_ELEMS);
        const uint32_t sAh = base;
        const uint32_t sAl = base + TILE_ELEMS * 2;
        const uint32_t sBh = base + 2 * TILE_ELEMS * 2;
        const uint32_t sBl = base + 3 * TILE_ELEMS * 2;

#pragma unroll
        for (int kk = 0; kk < 2; kk++) {
            const int ko = kk << 4;
            uint32_t afh[2][4], afl[2][4];
            const int arow  = lane & 15;
            const int akofs = ko + ((lane >> 4) << 3);
#pragma unroll
            for (int mt = 0; mt < 2; mt++) {
                const uint32_t off = (uint32_t)(((wm + mt * 16 + arow) * ST + akofs) * 2);
                ldmx4(afh[mt], sAh + off);
                ldmx4(afl[mt], sAl + off);
            }
            uint32_t bf[4][4];
            const int brow  = ((lane >> 4) << 3) + (lane & 7);
            const int bkofs = ko + (((lane >> 3) & 1) << 3);
#pragma unroll
            for (int np = 0; np < 4; np++)
                ldmx4(bf[np], sBh + (uint32_t)(((wn + np * 16 + brow) * ST + bkofs) * 2));
            MMA_SWEEP(afh, bf);
            MMA_SWEEP(afl, bf);
#pragma unroll
            for (int np = 0; np < 4; np++)
                ldmx4(bf[np], sBl + (uint32_t)(((wn + np * 16 + brow) * ST + bkofs) * 2));
            MMA_SWEEP(afh, bf);
        }
        __syncthreads();
        if (s + 2 < S) issue(s + 2);
    }

    float* Cz = C + (long long)blockIdx.z * LL * LL;
    const int er = lane >> 2;
    const int ec = (lane & 3) << 1;
#pragma unroll
    for (int mt = 0; mt < 2; mt++) {
        const int r0 = bm + wm + mt * 16 + er;
#pragma unroll
        for (int nt = 0; nt < 8; nt++) {
            const int col = bn + wn + nt * 8 + ec;
            *(float2*)(Cz + (long long)r0 * LL + col)       = make_float2(acc[mt][nt][0], acc[mt][nt][1]);
            *(float2*)(Cz + (long long)(r0 + 8) * LL + col) = make_float2(acc[mt][nt][2], acc[mt][nt][3]);
        }
    }
}

// =====================================================================
// batched NN attention-apply: C[z] = P[z] @ X[z], bf16 hi/lo out (stride CATW).
// =====================================================================
#define STN 136
#define BT_ELEMS (32 * STN)
#define NN_STAGE (2 * TILE_ELEMS + 2 * BT_ELEMS)
#define NN_SMEM_BYTES (2 * NN_STAGE * 2)

__global__ void __launch_bounds__(256, 2)
tcnn_k(const __nv_bfloat16* __restrict__ Ph, const __nv_bfloat16* __restrict__ Pl,
       const __nv_bfloat16* __restrict__ Xh, const __nv_bfloat16* __restrict__ Xl,
       int ldx,
       __nv_bfloat16* __restrict__ Ch, __nv_bfloat16* __restrict__ Cl)
{
    extern __shared__ __nv_bfloat16 sm[];
    const int tid = threadIdx.x, lane = tid & 31, wid = tid >> 5;
    const int bm = blockIdx.y << 7, bn = blockIdx.x << 7;
    const int wm = (wid & 3) << 5;
    const int wn = (wid >> 2) << 6;

    const long long zp = (long long)blockIdx.z * LL * LL;
    const long long zx = (long long)blockIdx.z * LL * ldx;
    const __nv_bfloat16* gA[2] = { Ph + zp + (long long)bm * LL,
                                   Pl + zp + (long long)bm * LL };
    const __nv_bfloat16* gX[2] = { Xh + zx + bn, Xl + zx + bn };

    const int arow0 = tid >> 2, ap = (tid & 3) << 3;
    const int brow0 = tid >> 4, bp = (tid & 15) << 3;

    float acc[2][8][4];
#pragma unroll
    for (int mt = 0; mt < 2; mt++)
#pragma unroll
        for (int nt = 0; nt < 8; nt++)
#pragma unroll
            for (int i = 0; i < 4; i++) acc[mt][nt][i] = 0.f;

    const int S = LL >> 5;

    auto issue = [&](int s) {
        const int buf = s & 1;
        const int k0 = s << 5;
        const uint32_t sb = smem_u32(sm + buf * NN_STAGE);
#pragma unroll
        for (int t = 0; t < 2; t++) {
            const __nv_bfloat16* g = gA[t] + k0 + ap;
            const uint32_t dbase = sb + t * (TILE_ELEMS * 2) + ap * 2;
#pragma unroll
            for (int j = 0; j < 2; j++) {
                const int row = arow0 + j * 64;
                cp16(dbase + row * (ST * 2), g + (long long)row * LL);
            }
        }
#pragma unroll
        for (int t = 0; t < 2; t++) {
            const __nv_bfloat16* g = gX[t] + bp;
            const uint32_t dbase = sb + (2 * TILE_ELEMS + t * BT_ELEMS) * 2 + bp * 2;
#pragma unroll
            for (int j = 0; j < 2; j++) {
                const int row = brow0 + j * 16;
                cp16(dbase + row * (STN * 2), g + (long long)(k0 + row) * ldx);
            }
        }
        cp_commit();
    };

    issue(0);
    issue(1);

    for (int s = 0; s < S; s++) {
        if (s + 1 < S) cp_wait<1>(); else cp_wait<0>();
        __syncthreads();

        const uint32_t base = smem_u32(sm + (s & 1) * NN_STAGE);
        const uint32_t sAh = base;
        const uint32_t sAl = base + TILE_ELEMS * 2;
        const uint32_t sBh = base + 2 * TILE_ELEMS * 2;
        const uint32_t sBl = sBh + BT_ELEMS * 2;

#pragma unroll
        for (int kk = 0; kk < 2; kk++) {
            const int ko = kk << 4;
            uint32_t afh[2][4], afl[2][4];
            const int arow  = lane & 15;
            const int akofs = ko + ((lane >> 4) << 3);
#pragma unroll
            for (int mt = 0; mt < 2; mt++) {
                const uint32_t off = (uint32_t)(((wm + mt * 16 + arow) * ST + akofs) * 2);
                ldmx4(afh[mt], sAh + off);
                ldmx4(afl[mt], sAl + off);
            }
            uint32_t bf[4][4];
            const int krow = ko + (((lane >> 3) & 1) << 3) + (lane & 7);
            const int ncol = (lane >> 4) << 3;
#pragma unroll
            for (int np = 0; np < 4; np++)
                ldmx4t(bf[np], sBh + (uint32_t)((krow * STN + wn + np * 16 + ncol) * 2));
            MMA_SWEEP(afh, bf);
            MMA_SWEEP(afl, bf);
#pragma unroll
            for (int np = 0; np < 4; np++)
                ldmx4t(bf[np], sBl + (uint32_t)((krow * STN + wn + np * 16 + ncol) * 2));
            MMA_SWEEP(afh, bf);
        }
        __syncthreads();
        if (s + 2 < S) issue(s + 2);
    }

    __nv_bfloat16* Chz = Ch + (long long)blockIdx.z * LL * CATW;
    __nv_bfloat16* Clz = Cl + (long long)blockIdx.z * LL * CATW;
    const int er = lane >> 2;
    const int ec = (lane & 3) << 1;
#pragma unroll
    for (int mt = 0; mt < 2; mt++) {
        const int r0 = bm + wm + mt * 16 + er;
#pragma unroll
        for (int nt = 0; nt < 8; nt++) {
            const int col = bn + wn + nt * 8 + ec;
            store_hl(Chz + (long long)r0 * CATW + col,       Clz + (long long)r0 * CATW + col,
                     acc[mt][nt][0], acc[mt][nt][1]);
            store_hl(Chz + (long long)(r0 + 8) * CATW + col, Clz + (long long)(r0 + 8) * CATW + col,
                     acc[mt][nt][2], acc[mt][nt][3]);
        }
    }
}

// ---- transpose + split weight: W[K,N] fp32 -> Bh/Bl [N,K] bf16 ----
__global__ void splitT_k(const float* __restrict__ W,
                         __nv_bfloat16* __restrict__ Bh, __nv_bfloat16* __restrict__ Bl,
                         int K, int N)
{
    __shared__ float t[32][33];
    const int n0 = blockIdx.x * 32, k0 = blockIdx.y * 32;
    const int tx = threadIdx.x, ty = threadIdx.y;
    t[ty][tx] = W[(long long)(k0 + ty) * N + n0 + tx];
    __syncthreads();
    const float v = t[tx][ty];
    const __nv_bfloat16 h = __float2bfloat16(v);
    const long long o = (long long)(n0 + ty) * K + k0 + tx;
    Bh[o] = h;
    Bl[o] = __float2bfloat16(v - __bfloat162float(h));
}

// ---- embedding gather -> bf16 hi/lo concat cols 0..511, + mask ----
__global__ void embed_k(const int* __restrict__ tok, const float* __restrict__ W,
                        __nv_bfloat16* __restrict__ Oh, __nv_bfloat16* __restrict__ Ol,
                        int* __restrict__ mask)
{
    const int r = blockIdx.x;
    const int t = tok[r];
    if (threadIdx.x == 0) mask[r] = (t != 0);
    const float4 v = ((const float4*)(W + (long long)t * EE))[threadIdx.x];
    const long long o = (long long)r * CATW + threadIdx.x * 4;
    store_hl(Oh + o,     Ol + o,     v.x, v.y);
    store_hl(Oh + o + 2, Ol + o + 2, v.z, v.w);
}

// ---------------- block reductions (blockDim = 256) ----------------
__device__ __forceinline__ float blockMax256(float v, float* red)
{
#pragma unroll
    for (int o = 16; o; o >>= 1) v = fmaxf(v, __shfl_xor_sync(0xffffffffu, v, o));
    if ((threadIdx.x & 31) == 0) red[threadIdx.x >> 5] = v;
    __syncthreads();
    float m = red[0];
#pragma unroll
    for (int i = 1; i < 8; i++) m = fmaxf(m, red[i]);
    return m;
}
__device__ __forceinline__ float blockSum256(float v, float* red)
{
#pragma unroll
    for (int o = 16; o; o >>= 1) v += __shfl_xor_sync(0xffffffffu, v, o);
    if ((threadIdx.x & 31) == 0) red[threadIdx.x >> 5] = v;
    __syncthreads();
    float s = red[0];
#pragma unroll
    for (int i = 1; i < 8; i++) s += red[i];
    return s;
}

__device__ __forceinline__ void store_prob(__nv_bfloat16* Hp, __nv_bfloat16* Lp, float p)
{
    const __nv_bfloat16 h = __float2bfloat16(p);
    *Hp = h;
    *Lp = __float2bfloat16(p - __bfloat162float(h));
}

// self-attention softmax: rel bias, diag=-inf, padded key=-1e9 -> bf16 hi/lo
__global__ void softmax_self_k(const float* __restrict__ S, const int* __restrict__ mask,
                               const float* __restrict__ distW,
                               __nv_bfloat16* __restrict__ Ph, __nv_bfloat16* __restrict__ Pl)
{
    const int q = blockIdx.x, b = blockIdx.y, k = threadIdx.x;
    const long long idx = ((long long)(b * LL + q)) * LL + k;
    __shared__ float red[8];
    __shared__ float dw[23];
    if (k < 23) dw[k] = distW[k];
    const int valid = mask[b * LL + k];
    const float sc = S[idx];
    __syncthreads();

    float v;
    if (!valid)      v = -1e9f;
    else if (k == q) v = __int_as_float(0xff800000);
    else {
        int d = k - q; d = d < -11 ? -11 : (d > 11 ? 11 : d);
        v = sc + dw[d + 11];
    }
    const float m = blockMax256(v, red);
    __syncthreads();
    const float e = expf(v - m);
    const float s = blockSum256(e, red);
    store_prob(Ph + idx, Pl + idx, e / s);
}

// row softmax with key mask -> bf16 hi/lo
__global__ void softmax_rows_k(const float* __restrict__ Z, const int* __restrict__ mask,
                               __nv_bfloat16* __restrict__ Ph, __nv_bfloat16* __restrict__ Pl)
{
    const int q = blockIdx.x, b = blockIdx.y, k = threadIdx.x;
    const long long idx = ((long long)(b * LL + q)) * LL + k;
    __shared__ float red[8];
    const float v = mask[b * LL + k] ? Z[idx] : -1e9f;
    const float m = blockMax256(v, red);
    __syncthreads();
    const float e = expf(v - m);
    const float s = blockSum256(e, red);
    store_prob(Ph + idx, Pl + idx, e / s);
}

// column softmax -> transposed bf16 hi/lo: Out[b,h,p] = softmax_p(Z[b,p,h])
__global__ void softmax_cols_k(const float* __restrict__ Z, const int* __restrict__ maskP,
                               __nv_bfloat16* __restrict__ Ph, __nv_bfloat16* __restrict__ Pl)
{
    const int h = blockIdx.x, b = blockIdx.y, p = threadIdx.x;
    __shared__ float red[8];
    const float v = maskP[b * LL + p]
                  ? Z[((long long)(b * LL + p)) * LL + h] : -1e9f;
    const float m = blockMax256(v, red);
    __syncthreads();
    const float e = expf(v - m);
    const float s = blockSum256(e, red);
    const long long o = ((long long)(b * LL + h)) * LL + p;
    store_prob(Ph + o, Pl + o, e / s);
}

__global__ void masked_sum_k(const float* __restrict__ X, const int* __restrict__ mask,
                             float* __restrict__ out, int off)
{
    const int b = blockIdx.y;
    const int d = blockIdx.x * 128 + threadIdx.x;
    const float* xb = X + (long long)b * LL * DD;
    const int* mb = mask + b * LL;
    float acc = 0.f;
    for (int l = 0; l < LL; l++)
        if (mb[l]) acc += xb[l * DD + d];
    out[b * (2 * DD) + off + d] = acc;
}

__global__ void head_k(const float* __restrict__ aggin,
                       const float* __restrict__ Wg1, const float* __restrict__ bg1,
                       const float* __restrict__ Wg2, const float* __restrict__ bg2,
                       const float* __restrict__ Wo, float* __restrict__ out)
{
    __shared__ float sin[2 * DD];
    __shared__ float h1[DD];
    __shared__ float h2[DD];
    const int b = blockIdx.x, t = threadIdx.x;
    sin[t]       = aggin[b * 2 * DD + t];
    sin[t + DD]  = aggin[b * 2 * DD + DD + t];
    __syncthreads();
    float a = bg1[t];
    for (int k = 0; k < 2 * DD; k++) a = fmaf(sin[k], Wg1[k * DD + t], a);
    h1[t] = relu_(a);
    __syncthreads();
    a = bg2[t];
    for (int k = 0; k < DD; k++) a = fmaf(h1[k], Wg2[k * DD + t], a);
    h2[t] = relu_(a);
    __syncthreads();
    if (t < 3) {
        float s = 0.f;
        for (int k = 0; k < DD; k++) s = fmaf(h2[k], Wo[k * 3 + t], s);
        out[b * 3 + t] = s;
    }
}

// ---------------- host-side dispatch ----------------
static void tcmlp_f32(const __nv_bfloat16* Ah, const __nv_bfloat16* Al, int lda,
                      const __nv_bfloat16* Bh, const __nv_bfloat16* Bl,
                      const float* bias, int K, float* C)
{
    dim3 grid(DD >> 7, MROWS >> 7);
    tcmlp_k<0><<<grid, 256, TC_SMEM_BYTES>>>(Ah, Al, lda, Bh, Bl, bias, K, C,
                                             nullptr, nullptr, DD);
}
static void tcmlp_b16(const __nv_bfloat16* Ah, const __nv_bfloat16* Al, int lda,
                      const __nv_bfloat16* Bh, const __nv_bfloat16* Bl,
                      const float* bias, int K, __nv_bfloat16* Ch, __nv_bfloat16* Cl)
{
    dim3 grid(DD >> 7, MROWS >> 7);
    tcmlp_k<1><<<grid, 256, TC_SMEM_BYTES>>>(Ah, Al, lda, Bh, Bl, bias, K, nullptr,
                                             Ch, Cl, DD);
}
static void tcnt(const __nv_bfloat16* Ah, const __nv_bfloat16* Al,
                 const __nv_bfloat16* Bh, const __nv_bfloat16* Bl, float* C)
{
    tcnt_k<<<dim3(2, 2, BB), 256, TC_SMEM_BYTES>>>(Ah, Al, Bh, Bl, C);
}
static void tcnn(const __nv_bfloat16* Ph, const __nv_bfloat16* Pl,
                 const __nv_bfloat16* Xh, const __nv_bfloat16* Xl, int N,
                 __nv_bfloat16* Ch, __nv_bfloat16* Cl)
{
    tcnn_k<<<dim3(N >> 7, 2, BB), 256, NN_SMEM_BYTES>>>(Ph, Pl, Xh, Xl, CATW, Ch, Cl);
}
static void splitT(const float* W, __nv_bfloat16* Bh, __nv_bfloat16* Bl, int K, int N)
{
    splitT_k<<<dim3(N / 32, K / 32), dim3(32, 32)>>>(W, Bh, Bl, K, N);
}

extern "C" void kernel_launch(void* const* d_in, const int* in_sizes, int n_in,
                              void* d_out, int out_size)
{
    (void)in_sizes; (void)n_in; (void)out_size;
    const int*   prem  = (const int*)  d_in[0];
    const int*   hypo  = (const int*)  d_in[1];
    const float* embW  = (const float*)d_in[2];
    const float* distW = (const float*)d_in[3];
    const float* Ws1 = (const float*)d_in[4];  const float* bs1 = (const float*)d_in[5];
    const float* Ws2 = (const float*)d_in[6];  const float* bs2 = (const float*)d_in[7];
    const float* Wa1 = (const float*)d_in[8];  const float* ba1 = (const float*)d_in[9];
    const float* Wa2 = (const float*)d_in[10]; const float* ba2 = (const float*)d_in[11];
    const float* Wc1 = (const float*)d_in[12]; const float* bc1 = (const float*)d_in[13];
    const float* Wc2 = (const float*)d_in[14]; const float* bc2 = (const float*)d_in[15];
    const float* Wg1 = (const float*)d_in[16]; const float* bg1 = (const float*)d_in[17];
    const float* Wg2 = (const float*)d_in[18]; const float* bg2 = (const float*)d_in[19];
    const float* Wo  = (const float*)d_in[20];
    float* out = (float*)d_out;

    cudaFuncSetAttribute(tcmlp_k<0>, cudaFuncAttributeMaxDynamicSharedMemorySize, TC_SMEM_BYTES);
    cudaFuncSetAttribute(tcmlp_k<1>, cudaFuncAttributeMaxDynamicSharedMemorySize, TC_SMEM_BYTES);
    cudaFuncSetAttribute(tcnt_k, cudaFuncAttributeMaxDynamicSharedMemorySize, TC_SMEM_BYTES);
    cudaFuncSetAttribute(tcnn_k, cudaFuncAttributeMaxDynamicSharedMemorySize, NN_SMEM_BYTES);

    float *pq, *s1, *agg;
    int *mp, *mh;
    __nv_bfloat16 *chp, *clp, *chh, *clh, *hhi, *hlo, *qhi, *qlo, *khi, *klo;
    __nv_bfloat16 *p1h, *p1l, *p2h, *p2l, *w1h, *w1l, *w2h, *w2l;
    cudaGetSymbolAddress((void**)&pq,    g_pq);
    cudaGetSymbolAddress((void**)&s1,    g_s1);
    cudaGetSymbolAddress((void**)&agg,   g_agg);
    cudaGetSymbolAddress((void**)&mp,    g_mask_p);
    cudaGetSymbolAddress((void**)&mh,    g_mask_h);
    cudaGetSymbolAddress((void**)&chp,   g_chp);
    cudaGetSymbolAddress((void**)&clp,   g_clp);
    cudaGetSymbolAddress((void**)&chh,   g_chh);
    cudaGetSymbolAddress((void**)&clh,   g_clh);
    cudaGetSymbolAddress((void**)&hhi,   g_hhi);
    cudaGetSymbolAddress((void**)&hlo,   g_hlo);
    cudaGetSymbolAddress((void**)&qhi,   g_qhi);
    cudaGetSymbolAddress((void**)&qlo,   g_qlo);
    cudaGetSymbolAddress((void**)&khi,   g_khi);
    cudaGetSymbolAddress((void**)&klo,   g_klo);
    cudaGetSymbolAddress((void**)&p1h,   g_p1h);
    cudaGetSymbolAddress((void**)&p1l,   g_p1l);
    cudaGetSymbolAddress((void**)&p2h,   g_p2h);
    cudaGetSymbolAddress((void**)&p2l,   g_p2l);
    cudaGetSymbolAddress((void**)&w1h,   g_w1h);
    cudaGetSymbolAddress((void**)&w1l,   g_w1l);
    cudaGetSymbolAddress((void**)&w2h,   g_w2h);
    cudaGetSymbolAddress((void**)&w2l,   g_w2l);

    // embeddings -> concat cols 0..511 (bf16 hi/lo), masks
    embed_k<<<MROWS, 128>>>(prem, embW, chp, clp, mp);
    embed_k<<<MROWS, 128>>>(hypo, embW, chh, clh, mh);

    // ---- self branch (shared weights) ----
    splitT(Ws1, w1h, w1l, EE, DD);
    splitT(Ws2, w2h, w2l, DD, DD);
    // prem
    tcmlp_b16(chp, clp, CATW, w1h, w1l, bs1, EE, hhi, hlo);
    tcmlp_b16(hhi, hlo, DD,   w2h, w2l, bs2, DD, qhi, qlo);
    tcnt(qhi, qlo, qhi, qlo, s1);
    softmax_self_k<<<dim3(LL, BB), 256>>>(s1, mp, distW, p1h, p1l);
    tcnn(p1h, p1l, chp, clp, EE, chp + EE, clp + EE);          // ctx_prem
    // hypo
    tcmlp_b16(chh, clh, CATW, w1h, w1l, bs1, EE, hhi, hlo);
    tcmlp_b16(hhi, hlo, DD,   w2h, w2l, bs2, DD, qhi, qlo);
    tcnt(qhi, qlo, qhi, qlo, s1);
    softmax_self_k<<<dim3(LL, BB), 256>>>(s1, mh, distW, p1h, p1l);
    tcnn(p1h, p1l, chh, clh, EE, chh + EE, clh + EE);          // ctx_hypo

    // ---- inter attention ----
    splitT(Wa1, w1h, w1l, 2 * EE, DD);
    splitT(Wa2, w2h, w2l, DD, DD);
    tcmlp_b16(chp, clp, CATW, w1h, w1l, ba1, 2 * EE, hhi, hlo);
    tcmlp_b16(hhi, hlo, DD,   w2h, w2l, ba2, DD, qhi, qlo);
    tcmlp_b16(chh, clh, CATW, w1h, w1l, ba1, 2 * EE, hhi, hlo);
    tcmlp_b16(hhi, hlo, DD,   w2h, w2l, ba2, DD, khi, klo);
    tcnt(qhi, qlo, khi, klo, s1);                              // z
    softmax_cols_k<<<dim3(LL, BB), 256>>>(s1, mp, p2h, p2l);   // hypo2prem
    softmax_rows_k<<<dim3(LL, BB), 256>>>(s1, mh, p1h, p1l);   // prem2hypo
    tcnn(p1h, p1l, chh, clh, 2 * EE, chp + 2 * EE, clp + 2 * EE);  // attended_hypo
    tcnn(p2h, p2l, chp, clp, 2 * EE, chh + 2 * EE, clh + 2 * EE);  // attended_prem

    // ---- compare + masked sum ----
    splitT(Wc1, w1h, w1l, 4 * EE, DD);
    splitT(Wc2, w2h, w2l, DD, DD);
    tcmlp_b16(chp, clp, CATW, w1h, w1l, bc1, 4 * EE, hhi, hlo);
    tcmlp_f32(hhi, hlo, DD,   w2h, w2l, bc2, DD, pq);
    masked_sum_k<<<dim3(DD / 128, BB), 128>>>(pq, mp, agg, 0);
    tcmlp_b16(chh, clh, CATW, w1h, w1l, bc1, 4 * EE, hhi, hlo);
    tcmlp_f32(hhi, hlo, DD,   w2h, w2l, bc2, DD, pq);
    masked_sum_k<<<dim3(DD / 128, BB), 128>>>(pq, mh, agg, DD);

    // ---- aggregate MLP + output ----
    head_k<<<BB, DD>>>(agg, Wg1, bg1, Wg2, bg2, Wo, out);
}